// round 1
// baseline (speedup 1.0000x reference)
#include <cuda_runtime.h>
#include <math.h>

// Problem shape (fixed)
#define Bb 2
#define Hh 16
#define NN 2048
#define CC 1024
#define DD 64

// Scratch (device globals — no allocation allowed)
__device__ float g_qkv[(size_t)Bb * NN * 3 * CC];   // [B*N, 3C] = 50 MB
__device__ float g_q[(size_t)Bb * Hh * NN * DD];    // [B,H,N,d]
__device__ float g_k[(size_t)Bb * Hh * NN * DD];
__device__ float g_v[(size_t)Bb * Hh * NN * DD];
__device__ float g_att[(size_t)Bb * NN * CC];       // [B*N, C]

// ---------------------------------------------------------------------------
// SGEMM: C[M,N] = A[M,K] @ B[K,N] (+ bias[N])   row-major, all dims % tile == 0
// Block tile 128x128, K-tile 16, 256 threads, 8x8 per thread.
// ---------------------------------------------------------------------------
__global__ __launch_bounds__(256) void sgemm128(
    const float* __restrict__ A, const float* __restrict__ B,
    float* __restrict__ C, const float* __restrict__ bias,
    int M, int N, int K)
{
    __shared__ float As[16][128];   // transposed A tile: As[k][m]
    __shared__ float Bs[16][128];   // Bs[k][n]

    const int tid = threadIdx.x;
    const int bm = blockIdx.y * 128;
    const int bn = blockIdx.x * 128;

    const int arow = tid >> 2;            // 0..63
    const int acol = (tid & 3) * 4;       // 0,4,8,12
    const int brow = tid >> 5;            // 0..7
    const int bcol = (tid & 31) * 4;      // 0..124

    const int ty = tid >> 4;              // 0..15
    const int tx = tid & 15;              // 0..15

    float acc[8][8];
    #pragma unroll
    for (int i = 0; i < 8; i++)
        #pragma unroll
        for (int j = 0; j < 8; j++) acc[i][j] = 0.f;

    for (int k0 = 0; k0 < K; k0 += 16) {
        // Load A tile (128 x 16), store transposed
        #pragma unroll
        for (int it = 0; it < 2; it++) {
            int r = arow + it * 64;
            float4 va = *(const float4*)&A[(size_t)(bm + r) * K + k0 + acol];
            As[acol + 0][r] = va.x;
            As[acol + 1][r] = va.y;
            As[acol + 2][r] = va.z;
            As[acol + 3][r] = va.w;
        }
        // Load B tile (16 x 128)
        #pragma unroll
        for (int it = 0; it < 2; it++) {
            int r = brow + it * 8;
            float4 vb = *(const float4*)&B[(size_t)(k0 + r) * N + bn + bcol];
            *(float4*)&Bs[r][bcol] = vb;
        }
        __syncthreads();

        #pragma unroll
        for (int k = 0; k < 16; k++) {
            float ra[8], rb[8];
            *(float4*)&ra[0] = *(const float4*)&As[k][ty * 8];
            *(float4*)&ra[4] = *(const float4*)&As[k][ty * 8 + 4];
            *(float4*)&rb[0] = *(const float4*)&Bs[k][tx * 8];
            *(float4*)&rb[4] = *(const float4*)&Bs[k][tx * 8 + 4];
            #pragma unroll
            for (int i = 0; i < 8; i++)
                #pragma unroll
                for (int j = 0; j < 8; j++)
                    acc[i][j] += ra[i] * rb[j];
        }
        __syncthreads();
    }

    #pragma unroll
    for (int i = 0; i < 8; i++) {
        int row = bm + ty * 8 + i;
        #pragma unroll
        for (int j = 0; j < 8; j += 4) {
            int col = bn + tx * 8 + j;
            float4 v;
            v.x = acc[i][j + 0];
            v.y = acc[i][j + 1];
            v.z = acc[i][j + 2];
            v.w = acc[i][j + 3];
            if (bias) {
                v.x += bias[col + 0];
                v.y += bias[col + 1];
                v.z += bias[col + 2];
                v.w += bias[col + 3];
            }
            *(float4*)&C[(size_t)row * N + col] = v;
        }
    }
}

// ---------------------------------------------------------------------------
// RoPE + split into per-head [B,H,N,d] Q/K/V.
// qkv layout from GEMM: row = b*N+n, col = t*C + h*d + dd  (t in {q,k,v})
// ---------------------------------------------------------------------------
__global__ void rope_split(const float* __restrict__ qkv,
                           float* __restrict__ Q, float* __restrict__ Kt,
                           float* __restrict__ Vt)
{
    int idx = blockIdx.x * blockDim.x + threadIdx.x;   // over B*H*N*32
    int i = idx & 31;
    int n = (idx >> 5) & (NN - 1);
    int h = (idx >> 16) & (Hh - 1);   // 5 + 11 bits
    int b = idx >> 20;

    float inv_freq = powf(10000.f, -(float)i / 32.f);
    float fr = (float)n * inv_freq;
    float c = cosf(fr), s = sinf(fr);

    size_t base = ((size_t)b * NN + n) * (3 * CC) + h * DD;
    float q1 = qkv[base + i],          q2 = qkv[base + i + 32];
    float k1 = qkv[base + CC + i],     k2 = qkv[base + CC + i + 32];
    float v1 = qkv[base + 2 * CC + i], v2 = qkv[base + 2 * CC + i + 32];

    size_t ob = ((size_t)(b * Hh + h) * NN + n) * DD;
    Q[ob + i]       = q1 * c - q2 * s;
    Q[ob + i + 32]  = q1 * s + q2 * c;
    Kt[ob + i]      = k1 * c - k2 * s;
    Kt[ob + i + 32] = k1 * s + k2 * c;
    Vt[ob + i]      = v1;
    Vt[ob + i + 32] = v2;
}

// ---------------------------------------------------------------------------
// Flash attention, fp32. One thread = one query row (q[64], o[64] in regs).
// Block = 64 threads = one 64-row query tile of one (b,h). KV tiles of 64 in smem.
// Output written directly in [B, N, C] layout for the projection GEMM.
// ---------------------------------------------------------------------------
__global__ __launch_bounds__(64) void flash_attn(
    const float* __restrict__ Q, const float* __restrict__ K,
    const float* __restrict__ V, float* __restrict__ O)
{
    __shared__ float Ks[64][64];
    __shared__ float Vs[64][64];
    __shared__ float Ss[64][64];   // Ss[j][t] : transposed to keep LDS conflict-free

    const int bh = blockIdx.x;          // 0..B*H-1
    const int b = bh >> 4, h = bh & 15;
    const int t = threadIdx.x;
    const int qrow = blockIdx.y * 64 + t;
    const float scale = 0.125f;         // d^-0.5, d=64

    const float* qptr = Q + ((size_t)bh * NN + qrow) * DD;
    float q[64];
    #pragma unroll
    for (int i = 0; i < 16; i++)
        *(float4*)&q[i * 4] = *(const float4*)&qptr[i * 4];

    float o[64];
    #pragma unroll
    for (int i = 0; i < 64; i++) o[i] = 0.f;
    float m = -1e30f, l = 0.f;

    for (int kt = 0; kt < NN; kt += 64) {
        __syncthreads();
        const float* kbase = K + ((size_t)bh * NN + kt) * DD;
        const float* vbase = V + ((size_t)bh * NN + kt) * DD;
        for (int j = 0; j < 64; j++) {
            Ks[j][t] = kbase[j * DD + t];
            Vs[j][t] = vbase[j * DD + t];
        }
        __syncthreads();

        // S = q . K_j  (broadcast smem reads, float4)
        float tmax = -1e30f;
        for (int j = 0; j < 64; j++) {
            const float4* k4 = (const float4*)Ks[j];
            float s0 = 0.f, s1 = 0.f, s2 = 0.f, s3 = 0.f;
            #pragma unroll
            for (int i = 0; i < 16; i++) {
                float4 kv = k4[i];
                s0 += q[i * 4 + 0] * kv.x;
                s1 += q[i * 4 + 1] * kv.y;
                s2 += q[i * 4 + 2] * kv.z;
                s3 += q[i * 4 + 3] * kv.w;
            }
            float s = (s0 + s1 + s2 + s3) * scale;
            Ss[j][t] = s;
            tmax = fmaxf(tmax, s);
        }

        float mnew = fmaxf(m, tmax);
        float alpha = __expf(m - mnew);
        l *= alpha;
        #pragma unroll
        for (int i = 0; i < 64; i++) o[i] *= alpha;

        for (int j = 0; j < 64; j++) {
            float p = __expf(Ss[j][t] - mnew);
            l += p;
            const float4* v4 = (const float4*)Vs[j];
            #pragma unroll
            for (int i = 0; i < 16; i++) {
                float4 vv = v4[i];
                o[i * 4 + 0] += p * vv.x;
                o[i * 4 + 1] += p * vv.y;
                o[i * 4 + 2] += p * vv.z;
                o[i * 4 + 3] += p * vv.w;
            }
        }
        m = mnew;
    }

    float inv = 1.f / l;
    float* optr = O + ((size_t)b * NN + qrow) * CC + h * DD;
    #pragma unroll
    for (int i = 0; i < 16; i++) {
        float4 v;
        v.x = o[i * 4 + 0] * inv;
        v.y = o[i * 4 + 1] * inv;
        v.z = o[i * 4 + 2] * inv;
        v.w = o[i * 4 + 3] * inv;
        *(float4*)&optr[i * 4] = v;
    }
}

// ---------------------------------------------------------------------------
extern "C" void kernel_launch(void* const* d_in, const int* in_sizes, int n_in,
                              void* d_out, int out_size)
{
    const float* x      = (const float*)d_in[0];
    const float* w_qkv  = (const float*)d_in[1];
    const float* w_proj = (const float*)d_in[2];
    const float* b_proj = (const float*)d_in[3];
    float* out = (float*)d_out;

    float *qkv, *q, *k, *v, *att;
    cudaGetSymbolAddress((void**)&qkv, g_qkv);
    cudaGetSymbolAddress((void**)&q,   g_q);
    cudaGetSymbolAddress((void**)&k,   g_k);
    cudaGetSymbolAddress((void**)&v,   g_v);
    cudaGetSymbolAddress((void**)&att, g_att);

    // 1) QKV GEMM: [4096, 3072] = [4096, 1024] @ [1024, 3072]
    dim3 g1(3 * CC / 128, Bb * NN / 128);
    sgemm128<<<g1, 256>>>(x, w_qkv, qkv, nullptr, Bb * NN, 3 * CC, CC);

    // 2) RoPE + head split
    int nthr = Bb * Hh * NN * 32;
    rope_split<<<nthr / 256, 256>>>(qkv, q, k, v);

    // 3) Attention
    flash_attn<<<dim3(Bb * Hh, NN / 64), 64>>>(q, k, v, att);

    // 4) Projection GEMM + bias: [4096, 1024] = [4096, 1024] @ [1024, 1024]
    dim3 g2(CC / 128, Bb * NN / 128);
    sgemm128<<<g2, 256>>>(att, w_proj, out, b_proj, Bb * NN, CC, CC);
}

// round 2
// speedup vs baseline: 1.7671x; 1.7671x over previous
#include <cuda_runtime.h>
#include <math.h>
#include <stdint.h>

// Problem shape (fixed)
#define Bb 2
#define Hh 16
#define NN 2048
#define CC 1024
#define DD 64

// Scratch (device globals — no allocation allowed)
__device__ float g_qkv[(size_t)Bb * NN * 3 * CC];   // [B*N, 3C]
__device__ float g_q[(size_t)Bb * Hh * NN * DD];    // [B,H,N,d]
__device__ float g_k[(size_t)Bb * Hh * NN * DD];
__device__ float g_v[(size_t)Bb * Hh * NN * DD];
__device__ float g_att[(size_t)Bb * NN * CC];       // [B*N, C]

// ---------------------------------------------------------------------------
// SGEMM: C[M,N] = A[M,K] @ B[K,N] (+ bias[N])   row-major
// ---------------------------------------------------------------------------
__global__ __launch_bounds__(256) void sgemm128(
    const float* __restrict__ A, const float* __restrict__ B,
    float* __restrict__ C, const float* __restrict__ bias,
    int M, int N, int K)
{
    __shared__ float As[16][128];
    __shared__ float Bs[16][128];

    const int tid = threadIdx.x;
    const int bm = blockIdx.y * 128;
    const int bn = blockIdx.x * 128;

    const int arow = tid >> 2;
    const int acol = (tid & 3) * 4;
    const int brow = tid >> 5;
    const int bcol = (tid & 31) * 4;

    const int ty = tid >> 4;
    const int tx = tid & 15;

    float acc[8][8];
    #pragma unroll
    for (int i = 0; i < 8; i++)
        #pragma unroll
        for (int j = 0; j < 8; j++) acc[i][j] = 0.f;

    for (int k0 = 0; k0 < K; k0 += 16) {
        #pragma unroll
        for (int it = 0; it < 2; it++) {
            int r = arow + it * 64;
            float4 va = *(const float4*)&A[(size_t)(bm + r) * K + k0 + acol];
            As[acol + 0][r] = va.x;
            As[acol + 1][r] = va.y;
            As[acol + 2][r] = va.z;
            As[acol + 3][r] = va.w;
        }
        #pragma unroll
        for (int it = 0; it < 2; it++) {
            int r = brow + it * 8;
            float4 vb = *(const float4*)&B[(size_t)(k0 + r) * N + bn + bcol];
            *(float4*)&Bs[r][bcol] = vb;
        }
        __syncthreads();

        #pragma unroll
        for (int k = 0; k < 16; k++) {
            float ra[8], rb[8];
            *(float4*)&ra[0] = *(const float4*)&As[k][ty * 8];
            *(float4*)&ra[4] = *(const float4*)&As[k][ty * 8 + 4];
            *(float4*)&rb[0] = *(const float4*)&Bs[k][tx * 8];
            *(float4*)&rb[4] = *(const float4*)&Bs[k][tx * 8 + 4];
            #pragma unroll
            for (int i = 0; i < 8; i++)
                #pragma unroll
                for (int j = 0; j < 8; j++)
                    acc[i][j] += ra[i] * rb[j];
        }
        __syncthreads();
    }

    #pragma unroll
    for (int i = 0; i < 8; i++) {
        int row = bm + ty * 8 + i;
        #pragma unroll
        for (int j = 0; j < 8; j += 4) {
            int col = bn + tx * 8 + j;
            float4 v;
            v.x = acc[i][j + 0];
            v.y = acc[i][j + 1];
            v.z = acc[i][j + 2];
            v.w = acc[i][j + 3];
            if (bias) {
                v.x += bias[col + 0];
                v.y += bias[col + 1];
                v.z += bias[col + 2];
                v.w += bias[col + 3];
            }
            *(float4*)&C[(size_t)row * N + col] = v;
        }
    }
}

// ---------------------------------------------------------------------------
// RoPE + split into per-head [B,H,N,d] Q/K/V.
// ---------------------------------------------------------------------------
__global__ void rope_split(const float* __restrict__ qkv,
                           float* __restrict__ Q, float* __restrict__ Kt,
                           float* __restrict__ Vt)
{
    int idx = blockIdx.x * blockDim.x + threadIdx.x;
    int i = idx & 31;
    int n = (idx >> 5) & (NN - 1);
    int h = (idx >> 16) & (Hh - 1);
    int b = idx >> 20;

    float inv_freq = powf(10000.f, -(float)i / 32.f);
    float fr = (float)n * inv_freq;
    float c = cosf(fr), s = sinf(fr);

    size_t base = ((size_t)b * NN + n) * (3 * CC) + h * DD;
    float q1 = qkv[base + i],          q2 = qkv[base + i + 32];
    float k1 = qkv[base + CC + i],     k2 = qkv[base + CC + i + 32];
    float v1 = qkv[base + 2 * CC + i], v2 = qkv[base + 2 * CC + i + 32];

    size_t ob = ((size_t)(b * Hh + h) * NN + n) * DD;
    Q[ob + i]       = q1 * c - q2 * s;
    Q[ob + i + 32]  = q1 * s + q2 * c;
    Kt[ob + i]      = k1 * c - k2 * s;
    Kt[ob + i + 32] = k1 * s + k2 * c;
    Vt[ob + i]      = v1;
    Vt[ob + i + 32] = v2;
}

// ---------------------------------------------------------------------------
// tf32 mma helpers
// ---------------------------------------------------------------------------
__device__ __forceinline__ uint32_t f2tf(float f) {
    uint32_t u;
    asm("cvt.rna.tf32.f32 %0, %1;" : "=r"(u) : "f"(f));
    return u;
}

__device__ __forceinline__ void mma_tf32(float& d0, float& d1, float& d2, float& d3,
                                         uint32_t a0, uint32_t a1, uint32_t a2, uint32_t a3,
                                         uint32_t b0, uint32_t b1)
{
    asm volatile(
        "mma.sync.aligned.m16n8k8.row.col.f32.tf32.tf32.f32 "
        "{%0,%1,%2,%3}, {%4,%5,%6,%7}, {%8,%9}, {%0,%1,%2,%3};"
        : "+f"(d0), "+f"(d1), "+f"(d2), "+f"(d3)
        : "r"(a0), "r"(a1), "r"(a2), "r"(a3), "r"(b0), "r"(b1));
}

// ---------------------------------------------------------------------------
// Flash attention with tf32 tensor-core mma.
// Block = 128 threads = 4 warps; each warp owns 16 query rows of a 64-row tile.
// KV tiles of 64 staged in smem (K stride 68, V stride 72: conflict-free LDS).
// ---------------------------------------------------------------------------
#define KSTR 68
#define VSTR 72

__global__ __launch_bounds__(128) void flash_mma(
    const float* __restrict__ Q, const float* __restrict__ K,
    const float* __restrict__ V, float* __restrict__ O)
{
    __shared__ uint32_t Ks[64 * KSTR];
    __shared__ uint32_t Vs[64 * VSTR];

    const int bh = blockIdx.x;            // 0..B*H-1
    const int b = bh >> 4, h = bh & 15;
    const int tid = threadIdx.x;
    const int warp = tid >> 5, lane = tid & 31;
    const int gID = lane >> 2, tig = lane & 3;
    const int qbase = blockIdx.y * 64;
    const float scale = 0.125f;

    // ---- stage Q tile into Ks (tf32), pull A-fragments to regs ----
    {
        const float* qg = Q + ((size_t)bh * NN + qbase) * DD;
        #pragma unroll
        for (int it = 0; it < 8; it++) {
            int r = (tid >> 4) + it * 8;
            int c = (tid & 15) * 4;
            float4 v = *(const float4*)&qg[r * DD + c];
            uint32_t* dst = &Ks[r * KSTR + c];
            dst[0] = f2tf(v.x); dst[1] = f2tf(v.y);
            dst[2] = f2tf(v.z); dst[3] = f2tf(v.w);
        }
    }
    __syncthreads();

    uint32_t aQ[8][4];
    {
        int r0 = warp * 16 + gID;
        #pragma unroll
        for (int s = 0; s < 8; s++) {
            aQ[s][0] = Ks[r0 * KSTR + s * 8 + tig];
            aQ[s][1] = Ks[(r0 + 8) * KSTR + s * 8 + tig];
            aQ[s][2] = Ks[r0 * KSTR + s * 8 + tig + 4];
            aQ[s][3] = Ks[(r0 + 8) * KSTR + s * 8 + tig + 4];
        }
    }
    __syncthreads();

    float of[8][4];
    #pragma unroll
    for (int i = 0; i < 8; i++)
        #pragma unroll
        for (int c = 0; c < 4; c++) of[i][c] = 0.f;
    float m0 = -1e30f, m1 = -1e30f, l0 = 0.f, l1 = 0.f;

    for (int kt = 0; kt < NN; kt += 64) {
        // ---- stage K/V tiles (converted to tf32) ----
        const float* kg = K + ((size_t)bh * NN + kt) * DD;
        const float* vg = V + ((size_t)bh * NN + kt) * DD;
        #pragma unroll
        for (int it = 0; it < 8; it++) {
            int r = (tid >> 4) + it * 8;
            int c = (tid & 15) * 4;
            float4 kv = *(const float4*)&kg[r * DD + c];
            uint32_t* kd = &Ks[r * KSTR + c];
            kd[0] = f2tf(kv.x); kd[1] = f2tf(kv.y);
            kd[2] = f2tf(kv.z); kd[3] = f2tf(kv.w);
            float4 vv = *(const float4*)&vg[r * DD + c];
            uint32_t* vd = &Vs[r * VSTR + c];
            vd[0] = f2tf(vv.x); vd[1] = f2tf(vv.y);
            vd[2] = f2tf(vv.z); vd[3] = f2tf(vv.w);
        }
        __syncthreads();

        // ---- S = Q . K^T  (m16 x n64 per warp) ----
        float sf[8][4];
        #pragma unroll
        for (int nt = 0; nt < 8; nt++)
            #pragma unroll
            for (int c = 0; c < 4; c++) sf[nt][c] = 0.f;

        #pragma unroll
        for (int s = 0; s < 8; s++) {
            #pragma unroll
            for (int nt = 0; nt < 8; nt++) {
                uint32_t b0 = Ks[(nt * 8 + gID) * KSTR + s * 8 + tig];
                uint32_t b1 = Ks[(nt * 8 + gID) * KSTR + s * 8 + tig + 4];
                mma_tf32(sf[nt][0], sf[nt][1], sf[nt][2], sf[nt][3],
                         aQ[s][0], aQ[s][1], aQ[s][2], aQ[s][3], b0, b1);
            }
        }

        // ---- online softmax (rows r0 = warp*16+gID, r1 = r0+8) ----
        float tmax0 = -1e30f, tmax1 = -1e30f;
        #pragma unroll
        for (int nt = 0; nt < 8; nt++) {
            sf[nt][0] *= scale; sf[nt][1] *= scale;
            sf[nt][2] *= scale; sf[nt][3] *= scale;
            tmax0 = fmaxf(tmax0, fmaxf(sf[nt][0], sf[nt][1]));
            tmax1 = fmaxf(tmax1, fmaxf(sf[nt][2], sf[nt][3]));
        }
        tmax0 = fmaxf(tmax0, __shfl_xor_sync(0xffffffffu, tmax0, 1));
        tmax0 = fmaxf(tmax0, __shfl_xor_sync(0xffffffffu, tmax0, 2));
        tmax1 = fmaxf(tmax1, __shfl_xor_sync(0xffffffffu, tmax1, 1));
        tmax1 = fmaxf(tmax1, __shfl_xor_sync(0xffffffffu, tmax1, 2));

        float mn0 = fmaxf(m0, tmax0);
        float mn1 = fmaxf(m1, tmax1);
        float al0 = __expf(m0 - mn0);
        float al1 = __expf(m1 - mn1);
        m0 = mn0; m1 = mn1;
        l0 *= al0; l1 *= al1;
        #pragma unroll
        for (int i = 0; i < 8; i++) {
            of[i][0] *= al0; of[i][1] *= al0;
            of[i][2] *= al1; of[i][3] *= al1;
        }
        #pragma unroll
        for (int nt = 0; nt < 8; nt++) {
            sf[nt][0] = __expf(sf[nt][0] - mn0);
            sf[nt][1] = __expf(sf[nt][1] - mn0);
            sf[nt][2] = __expf(sf[nt][2] - mn1);
            sf[nt][3] = __expf(sf[nt][3] - mn1);
            l0 += sf[nt][0] + sf[nt][1];
            l1 += sf[nt][2] + sf[nt][3];
        }

        // ---- O += P . V  (k = keys, 8 k-steps; P frags built via shfl) ----
        #pragma unroll
        for (int j = 0; j < 8; j++) {
            int srcA = (lane & ~3) | (tig >> 1);
            float x0 = __shfl_sync(0xffffffffu, sf[j][0], srcA);
            float x1 = __shfl_sync(0xffffffffu, sf[j][1], srcA);
            float y0 = __shfl_sync(0xffffffffu, sf[j][2], srcA);
            float y1 = __shfl_sync(0xffffffffu, sf[j][3], srcA);
            float x2 = __shfl_sync(0xffffffffu, sf[j][0], srcA + 2);
            float x3 = __shfl_sync(0xffffffffu, sf[j][1], srcA + 2);
            float y2 = __shfl_sync(0xffffffffu, sf[j][2], srcA + 2);
            float y3 = __shfl_sync(0xffffffffu, sf[j][3], srcA + 2);
            uint32_t a0 = __float_as_uint((tig & 1) ? x1 : x0);
            uint32_t a1 = __float_as_uint((tig & 1) ? y1 : y0);
            uint32_t a2 = __float_as_uint((tig & 1) ? x3 : x2);
            uint32_t a3 = __float_as_uint((tig & 1) ? y3 : y2);
            #pragma unroll
            for (int i = 0; i < 8; i++) {
                uint32_t b0 = Vs[(j * 8 + tig) * VSTR + i * 8 + gID];
                uint32_t b1 = Vs[(j * 8 + tig + 4) * VSTR + i * 8 + gID];
                mma_tf32(of[i][0], of[i][1], of[i][2], of[i][3],
                         a0, a1, a2, a3, b0, b1);
            }
        }
        __syncthreads();
    }

    // ---- final normalize + write (O layout [B, N, C]) ----
    l0 += __shfl_xor_sync(0xffffffffu, l0, 1);
    l0 += __shfl_xor_sync(0xffffffffu, l0, 2);
    l1 += __shfl_xor_sync(0xffffffffu, l1, 1);
    l1 += __shfl_xor_sync(0xffffffffu, l1, 2);
    float inv0 = 1.f / l0;
    float inv1 = 1.f / l1;

    int r0 = qbase + warp * 16 + gID;
    int r1 = r0 + 8;
    float* o0 = O + ((size_t)b * NN + r0) * CC + h * DD;
    float* o1 = O + ((size_t)b * NN + r1) * CC + h * DD;
    #pragma unroll
    for (int i = 0; i < 8; i++) {
        int col = i * 8 + 2 * tig;
        float2 w0; w0.x = of[i][0] * inv0; w0.y = of[i][1] * inv0;
        float2 w1; w1.x = of[i][2] * inv1; w1.y = of[i][3] * inv1;
        *(float2*)&o0[col] = w0;
        *(float2*)&o1[col] = w1;
    }
}

// ---------------------------------------------------------------------------
extern "C" void kernel_launch(void* const* d_in, const int* in_sizes, int n_in,
                              void* d_out, int out_size)
{
    const float* x      = (const float*)d_in[0];
    const float* w_qkv  = (const float*)d_in[1];
    const float* w_proj = (const float*)d_in[2];
    const float* b_proj = (const float*)d_in[3];
    float* out = (float*)d_out;

    float *qkv, *q, *k, *v, *att;
    cudaGetSymbolAddress((void**)&qkv, g_qkv);
    cudaGetSymbolAddress((void**)&q,   g_q);
    cudaGetSymbolAddress((void**)&k,   g_k);
    cudaGetSymbolAddress((void**)&v,   g_v);
    cudaGetSymbolAddress((void**)&att, g_att);

    // 1) QKV GEMM
    dim3 g1(3 * CC / 128, Bb * NN / 128);
    sgemm128<<<g1, 256>>>(x, w_qkv, qkv, nullptr, Bb * NN, 3 * CC, CC);

    // 2) RoPE + head split
    int nthr = Bb * Hh * NN * 32;
    rope_split<<<nthr / 256, 256>>>(qkv, q, k, v);

    // 3) Attention (tf32 tensor cores)
    flash_mma<<<dim3(Bb * Hh, NN / 64), 128>>>(q, k, v, att);

    // 4) Projection GEMM + bias
    dim3 g2(CC / 128, Bb * NN / 128);
    sgemm128<<<g2, 256>>>(att, w_proj, out, b_proj, Bb * NN, CC, CC);
}

// round 3
// speedup vs baseline: 2.1710x; 1.2285x over previous
#include <cuda_runtime.h>
#include <cuda_bf16.h>
#include <math.h>
#include <stdint.h>

// Problem shape (fixed)
#define Bb 2
#define Hh 16
#define NN 2048
#define CC 1024
#define DD 64

// Scratch (device globals — no allocation allowed)
__device__ float g_qkv[(size_t)Bb * NN * 3 * CC];   // [B*N, 3C]
__device__ float g_q[(size_t)Bb * Hh * NN * DD];    // [B,H,N,d]
__device__ float g_k[(size_t)Bb * Hh * NN * DD];
__device__ float g_v[(size_t)Bb * Hh * NN * DD];
__device__ float g_att[(size_t)Bb * NN * CC];       // [B*N, C]

// ---------------------------------------------------------------------------
// bf16 helpers
// ---------------------------------------------------------------------------
__device__ __forceinline__ void split_pack(float x0, float x1,
                                           uint32_t& hi, uint32_t& lo)
{
    // hi/lo bf16x2 packed: low 16 bits = x0 (even index), high = x1
    __nv_bfloat16 h0 = __float2bfloat16_rn(x0);
    __nv_bfloat16 h1 = __float2bfloat16_rn(x1);
    float r0 = x0 - __bfloat162float(h0);
    float r1 = x1 - __bfloat162float(h1);
    __nv_bfloat16 l0 = __float2bfloat16_rn(r0);
    __nv_bfloat16 l1 = __float2bfloat16_rn(r1);
    hi = (uint32_t)__bfloat16_as_ushort(h0) | ((uint32_t)__bfloat16_as_ushort(h1) << 16);
    lo = (uint32_t)__bfloat16_as_ushort(l0) | ((uint32_t)__bfloat16_as_ushort(l1) << 16);
}

__device__ __forceinline__ void mma_bf16(float& d0, float& d1, float& d2, float& d3,
                                         uint32_t a0, uint32_t a1, uint32_t a2, uint32_t a3,
                                         uint32_t b0, uint32_t b1)
{
    asm volatile(
        "mma.sync.aligned.m16n8k16.row.col.f32.bf16.bf16.f32 "
        "{%0,%1,%2,%3}, {%4,%5,%6,%7}, {%8,%9}, {%0,%1,%2,%3};"
        : "+f"(d0), "+f"(d1), "+f"(d2), "+f"(d3)
        : "r"(a0), "r"(a1), "r"(a2), "r"(a3), "r"(b0), "r"(b1));
}

// ---------------------------------------------------------------------------
// bf16x3 error-compensated GEMM: C = A @ B (+ bias), fp32-level accuracy.
// Block tile 128x128, K-tile 32, 256 threads (8 warps, warp tile 32x64).
// smem planes hold packed bf16x2 (2 consecutive k) hi/lo, stride 17 words.
// ---------------------------------------------------------------------------
#define GP 17   // smem row stride in uint32 words (16 kpairs + 1 pad)

__global__ __launch_bounds__(256) void gemm_bf16x3(
    const float* __restrict__ A, const float* __restrict__ B,
    float* __restrict__ C, const float* __restrict__ bias,
    int M, int N, int K)
{
    __shared__ uint32_t Ah[128 * GP];
    __shared__ uint32_t Al[128 * GP];
    __shared__ uint32_t Bh[128 * GP];
    __shared__ uint32_t Bl[128 * GP];

    const int tid  = threadIdx.x;
    const int warp = tid >> 5, lane = tid & 31;
    const int gID  = lane >> 2, tig = lane & 3;
    const int bm = blockIdx.y * 128;
    const int bn = blockIdx.x * 128;
    const int m0 = (warp >> 1) * 32;    // warp tile row
    const int n0 = (warp & 1) * 64;     // warp tile col

    // loader indices
    const int ar  = tid >> 1;           // A row 0..127
    const int ach = (tid & 1);          // A col half (16 floats each)
    const int nb  = (lane) * 4;         // hmm careful: use tid&31
    const int nb4 = (tid & 31) * 4;     // B col group 0..124
    const int kp0 = tid >> 5;           // 0..7

    float acc[2][8][4];
    #pragma unroll
    for (int mi = 0; mi < 2; mi++)
        #pragma unroll
        for (int nt = 0; nt < 8; nt++)
            #pragma unroll
            for (int c = 0; c < 4; c++) acc[mi][nt][c] = 0.f;

    for (int k0 = 0; k0 < K; k0 += 32) {
        // ---- stage A tile 128x32 ----
        {
            const float* ap = A + (size_t)(bm + ar) * K + k0 + ach * 16;
            #pragma unroll
            for (int j = 0; j < 4; j++) {
                float4 v = *(const float4*)&ap[j * 4];
                int kp = ach * 8 + j * 2;
                uint32_t h0, l0, h1, l1;
                split_pack(v.x, v.y, h0, l0);
                split_pack(v.z, v.w, h1, l1);
                Ah[ar * GP + kp]     = h0;  Al[ar * GP + kp]     = l0;
                Ah[ar * GP + kp + 1] = h1;  Al[ar * GP + kp + 1] = l1;
            }
        }
        // ---- stage B tile 32x128, transposed into [n][kpair] ----
        #pragma unroll
        for (int half = 0; half < 2; half++) {
            int kp = kp0 + half * 8;
            const float* b0p = B + (size_t)(k0 + 2 * kp) * N + bn + nb4;
            const float* b1p = B + (size_t)(k0 + 2 * kp + 1) * N + bn + nb4;
            float4 r0 = *(const float4*)b0p;
            float4 r1 = *(const float4*)b1p;
            const float* x0 = &r0.x;
            const float* x1 = &r1.x;
            #pragma unroll
            for (int q = 0; q < 4; q++) {
                uint32_t h, l;
                split_pack(x0[q], x1[q], h, l);   // low = even k (row 2kp)
                Bh[(nb4 + q) * GP + kp] = h;
                Bl[(nb4 + q) * GP + kp] = l;
            }
        }
        __syncthreads();

        // ---- compute: 2 mma k-steps of 16 ----
        #pragma unroll
        for (int s = 0; s < 2; s++) {
            uint32_t af[2][2][4];   // [mi][plane][reg]
            #pragma unroll
            for (int mi = 0; mi < 2; mi++) {
                int base = (m0 + mi * 16 + gID) * GP + s * 8;
                af[mi][0][0] = Ah[base + tig];
                af[mi][0][1] = Ah[base + 8 * GP + tig];
                af[mi][0][2] = Ah[base + tig + 4];
                af[mi][0][3] = Ah[base + 8 * GP + tig + 4];
                af[mi][1][0] = Al[base + tig];
                af[mi][1][1] = Al[base + 8 * GP + tig];
                af[mi][1][2] = Al[base + tig + 4];
                af[mi][1][3] = Al[base + 8 * GP + tig + 4];
            }
            uint32_t bf[8][2][2];   // [nt][plane][reg]
            #pragma unroll
            for (int nt = 0; nt < 8; nt++) {
                int base = (n0 + nt * 8 + gID) * GP + s * 8;
                bf[nt][0][0] = Bh[base + tig];
                bf[nt][0][1] = Bh[base + tig + 4];
                bf[nt][1][0] = Bl[base + tig];
                bf[nt][1][1] = Bl[base + tig + 4];
            }
            #pragma unroll
            for (int mi = 0; mi < 2; mi++)
                #pragma unroll
                for (int nt = 0; nt < 8; nt++) {
                    // hi*hi + hi*lo + lo*hi
                    mma_bf16(acc[mi][nt][0], acc[mi][nt][1], acc[mi][nt][2], acc[mi][nt][3],
                             af[mi][0][0], af[mi][0][1], af[mi][0][2], af[mi][0][3],
                             bf[nt][0][0], bf[nt][0][1]);
                    mma_bf16(acc[mi][nt][0], acc[mi][nt][1], acc[mi][nt][2], acc[mi][nt][3],
                             af[mi][0][0], af[mi][0][1], af[mi][0][2], af[mi][0][3],
                             bf[nt][1][0], bf[nt][1][1]);
                    mma_bf16(acc[mi][nt][0], acc[mi][nt][1], acc[mi][nt][2], acc[mi][nt][3],
                             af[mi][1][0], af[mi][1][1], af[mi][1][2], af[mi][1][3],
                             bf[nt][0][0], bf[nt][0][1]);
                }
        }
        __syncthreads();
    }

    // ---- epilogue ----
    #pragma unroll
    for (int mi = 0; mi < 2; mi++) {
        int row = bm + m0 + mi * 16 + gID;
        #pragma unroll
        for (int nt = 0; nt < 8; nt++) {
            int col = bn + n0 + nt * 8 + 2 * tig;
            float b0 = bias ? bias[col] : 0.f;
            float b1 = bias ? bias[col + 1] : 0.f;
            float2 w0; w0.x = acc[mi][nt][0] + b0; w0.y = acc[mi][nt][1] + b1;
            float2 w1; w1.x = acc[mi][nt][2] + b0; w1.y = acc[mi][nt][3] + b1;
            *(float2*)&C[(size_t)row * N + col] = w0;
            *(float2*)&C[(size_t)(row + 8) * N + col] = w1;
        }
    }
}

// ---------------------------------------------------------------------------
// RoPE + split into per-head [B,H,N,d] Q/K/V.
// ---------------------------------------------------------------------------
__global__ void rope_split(const float* __restrict__ qkv,
                           float* __restrict__ Q, float* __restrict__ Kt,
                           float* __restrict__ Vt)
{
    int idx = blockIdx.x * blockDim.x + threadIdx.x;
    int i = idx & 31;
    int n = (idx >> 5) & (NN - 1);
    int h = (idx >> 16) & (Hh - 1);
    int b = idx >> 20;

    float inv_freq = powf(10000.f, -(float)i / 32.f);
    float fr = (float)n * inv_freq;
    float c = cosf(fr), s = sinf(fr);

    size_t base = ((size_t)b * NN + n) * (3 * CC) + h * DD;
    float q1 = qkv[base + i],          q2 = qkv[base + i + 32];
    float k1 = qkv[base + CC + i],     k2 = qkv[base + CC + i + 32];
    float v1 = qkv[base + 2 * CC + i], v2 = qkv[base + 2 * CC + i + 32];

    size_t ob = ((size_t)(b * Hh + h) * NN + n) * DD;
    Q[ob + i]       = q1 * c - q2 * s;
    Q[ob + i + 32]  = q1 * s + q2 * c;
    Kt[ob + i]      = k1 * c - k2 * s;
    Kt[ob + i + 32] = k1 * s + k2 * c;
    Vt[ob + i]      = v1;
    Vt[ob + i + 32] = v2;
}

// ---------------------------------------------------------------------------
// tf32 mma helpers
// ---------------------------------------------------------------------------
__device__ __forceinline__ uint32_t f2tf(float f) {
    uint32_t u;
    asm("cvt.rna.tf32.f32 %0, %1;" : "=r"(u) : "f"(f));
    return u;
}

__device__ __forceinline__ void mma_tf32(float& d0, float& d1, float& d2, float& d3,
                                         uint32_t a0, uint32_t a1, uint32_t a2, uint32_t a3,
                                         uint32_t b0, uint32_t b1)
{
    asm volatile(
        "mma.sync.aligned.m16n8k8.row.col.f32.tf32.tf32.f32 "
        "{%0,%1,%2,%3}, {%4,%5,%6,%7}, {%8,%9}, {%0,%1,%2,%3};"
        : "+f"(d0), "+f"(d1), "+f"(d2), "+f"(d3)
        : "r"(a0), "r"(a1), "r"(a2), "r"(a3), "r"(b0), "r"(b1));
}

// ---------------------------------------------------------------------------
// Flash attention with tf32 tensor-core mma.
// ---------------------------------------------------------------------------
#define KSTR 68
#define VSTR 72

__global__ __launch_bounds__(128) void flash_mma(
    const float* __restrict__ Q, const float* __restrict__ K,
    const float* __restrict__ V, float* __restrict__ O)
{
    __shared__ uint32_t Ks[64 * KSTR];
    __shared__ uint32_t Vs[64 * VSTR];

    const int bh = blockIdx.x;
    const int b = bh >> 4, h = bh & 15;
    const int tid = threadIdx.x;
    const int warp = tid >> 5, lane = tid & 31;
    const int gID = lane >> 2, tig = lane & 3;
    const int qbase = blockIdx.y * 64;
    const float scale = 0.125f;

    {
        const float* qg = Q + ((size_t)bh * NN + qbase) * DD;
        #pragma unroll
        for (int it = 0; it < 8; it++) {
            int r = (tid >> 4) + it * 8;
            int c = (tid & 15) * 4;
            float4 v = *(const float4*)&qg[r * DD + c];
            uint32_t* dst = &Ks[r * KSTR + c];
            dst[0] = f2tf(v.x); dst[1] = f2tf(v.y);
            dst[2] = f2tf(v.z); dst[3] = f2tf(v.w);
        }
    }
    __syncthreads();

    uint32_t aQ[8][4];
    {
        int r0 = warp * 16 + gID;
        #pragma unroll
        for (int s = 0; s < 8; s++) {
            aQ[s][0] = Ks[r0 * KSTR + s * 8 + tig];
            aQ[s][1] = Ks[(r0 + 8) * KSTR + s * 8 + tig];
            aQ[s][2] = Ks[r0 * KSTR + s * 8 + tig + 4];
            aQ[s][3] = Ks[(r0 + 8) * KSTR + s * 8 + tig + 4];
        }
    }
    __syncthreads();

    float of[8][4];
    #pragma unroll
    for (int i = 0; i < 8; i++)
        #pragma unroll
        for (int c = 0; c < 4; c++) of[i][c] = 0.f;
    float m0 = -1e30f, m1 = -1e30f, l0 = 0.f, l1 = 0.f;

    for (int kt = 0; kt < NN; kt += 64) {
        const float* kg = K + ((size_t)bh * NN + kt) * DD;
        const float* vg = V + ((size_t)bh * NN + kt) * DD;
        #pragma unroll
        for (int it = 0; it < 8; it++) {
            int r = (tid >> 4) + it * 8;
            int c = (tid & 15) * 4;
            float4 kv = *(const float4*)&kg[r * DD + c];
            uint32_t* kd = &Ks[r * KSTR + c];
            kd[0] = f2tf(kv.x); kd[1] = f2tf(kv.y);
            kd[2] = f2tf(kv.z); kd[3] = f2tf(kv.w);
            float4 vv = *(const float4*)&vg[r * DD + c];
            uint32_t* vd = &Vs[r * VSTR + c];
            vd[0] = f2tf(vv.x); vd[1] = f2tf(vv.y);
            vd[2] = f2tf(vv.z); vd[3] = f2tf(vv.w);
        }
        __syncthreads();

        float sf[8][4];
        #pragma unroll
        for (int nt = 0; nt < 8; nt++)
            #pragma unroll
            for (int c = 0; c < 4; c++) sf[nt][c] = 0.f;

        #pragma unroll
        for (int s = 0; s < 8; s++) {
            #pragma unroll
            for (int nt = 0; nt < 8; nt++) {
                uint32_t b0 = Ks[(nt * 8 + gID) * KSTR + s * 8 + tig];
                uint32_t b1 = Ks[(nt * 8 + gID) * KSTR + s * 8 + tig + 4];
                mma_tf32(sf[nt][0], sf[nt][1], sf[nt][2], sf[nt][3],
                         aQ[s][0], aQ[s][1], aQ[s][2], aQ[s][3], b0, b1);
            }
        }

        float tmax0 = -1e30f, tmax1 = -1e30f;
        #pragma unroll
        for (int nt = 0; nt < 8; nt++) {
            sf[nt][0] *= scale; sf[nt][1] *= scale;
            sf[nt][2] *= scale; sf[nt][3] *= scale;
            tmax0 = fmaxf(tmax0, fmaxf(sf[nt][0], sf[nt][1]));
            tmax1 = fmaxf(tmax1, fmaxf(sf[nt][2], sf[nt][3]));
        }
        tmax0 = fmaxf(tmax0, __shfl_xor_sync(0xffffffffu, tmax0, 1));
        tmax0 = fmaxf(tmax0, __shfl_xor_sync(0xffffffffu, tmax0, 2));
        tmax1 = fmaxf(tmax1, __shfl_xor_sync(0xffffffffu, tmax1, 1));
        tmax1 = fmaxf(tmax1, __shfl_xor_sync(0xffffffffu, tmax1, 2));

        float mn0 = fmaxf(m0, tmax0);
        float mn1 = fmaxf(m1, tmax1);
        float al0 = __expf(m0 - mn0);
        float al1 = __expf(m1 - mn1);
        m0 = mn0; m1 = mn1;
        l0 *= al0; l1 *= al1;
        #pragma unroll
        for (int i = 0; i < 8; i++) {
            of[i][0] *= al0; of[i][1] *= al0;
            of[i][2] *= al1; of[i][3] *= al1;
        }
        #pragma unroll
        for (int nt = 0; nt < 8; nt++) {
            sf[nt][0] = __expf(sf[nt][0] - mn0);
            sf[nt][1] = __expf(sf[nt][1] - mn0);
            sf[nt][2] = __expf(sf[nt][2] - mn1);
            sf[nt][3] = __expf(sf[nt][3] - mn1);
            l0 += sf[nt][0] + sf[nt][1];
            l1 += sf[nt][2] + sf[nt][3];
        }

        #pragma unroll
        for (int j = 0; j < 8; j++) {
            int srcA = (lane & ~3) | (tig >> 1);
            float x0 = __shfl_sync(0xffffffffu, sf[j][0], srcA);
            float x1 = __shfl_sync(0xffffffffu, sf[j][1], srcA);
            float y0 = __shfl_sync(0xffffffffu, sf[j][2], srcA);
            float y1 = __shfl_sync(0xffffffffu, sf[j][3], srcA);
            float x2 = __shfl_sync(0xffffffffu, sf[j][0], srcA + 2);
            float x3 = __shfl_sync(0xffffffffu, sf[j][1], srcA + 2);
            float y2 = __shfl_sync(0xffffffffu, sf[j][2], srcA + 2);
            float y3 = __shfl_sync(0xffffffffu, sf[j][3], srcA + 2);
            uint32_t a0 = __float_as_uint((tig & 1) ? x1 : x0);
            uint32_t a1 = __float_as_uint((tig & 1) ? y1 : y0);
            uint32_t a2 = __float_as_uint((tig & 1) ? x3 : x2);
            uint32_t a3 = __float_as_uint((tig & 1) ? y3 : y2);
            #pragma unroll
            for (int i = 0; i < 8; i++) {
                uint32_t b0 = Vs[(j * 8 + tig) * VSTR + i * 8 + gID];
                uint32_t b1 = Vs[(j * 8 + tig + 4) * VSTR + i * 8 + gID];
                mma_tf32(of[i][0], of[i][1], of[i][2], of[i][3],
                         a0, a1, a2, a3, b0, b1);
            }
        }
        __syncthreads();
    }

    l0 += __shfl_xor_sync(0xffffffffu, l0, 1);
    l0 += __shfl_xor_sync(0xffffffffu, l0, 2);
    l1 += __shfl_xor_sync(0xffffffffu, l1, 1);
    l1 += __shfl_xor_sync(0xffffffffu, l1, 2);
    float inv0 = 1.f / l0;
    float inv1 = 1.f / l1;

    int r0 = qbase + warp * 16 + gID;
    int r1 = r0 + 8;
    float* o0 = O + ((size_t)b * NN + r0) * CC + h * DD;
    float* o1 = O + ((size_t)b * NN + r1) * CC + h * DD;
    #pragma unroll
    for (int i = 0; i < 8; i++) {
        int col = i * 8 + 2 * tig;
        float2 w0; w0.x = of[i][0] * inv0; w0.y = of[i][1] * inv0;
        float2 w1; w1.x = of[i][2] * inv1; w1.y = of[i][3] * inv1;
        *(float2*)&o0[col] = w0;
        *(float2*)&o1[col] = w1;
    }
}

// ---------------------------------------------------------------------------
extern "C" void kernel_launch(void* const* d_in, const int* in_sizes, int n_in,
                              void* d_out, int out_size)
{
    const float* x      = (const float*)d_in[0];
    const float* w_qkv  = (const float*)d_in[1];
    const float* w_proj = (const float*)d_in[2];
    const float* b_proj = (const float*)d_in[3];
    float* out = (float*)d_out;

    float *qkv, *q, *k, *v, *att;
    cudaGetSymbolAddress((void**)&qkv, g_qkv);
    cudaGetSymbolAddress((void**)&q,   g_q);
    cudaGetSymbolAddress((void**)&k,   g_k);
    cudaGetSymbolAddress((void**)&v,   g_v);
    cudaGetSymbolAddress((void**)&att, g_att);

    // 1) QKV GEMM: [4096, 3072] = [4096, 1024] @ [1024, 3072]  (bf16x3)
    dim3 g1(3 * CC / 128, Bb * NN / 128);
    gemm_bf16x3<<<g1, 256>>>(x, w_qkv, qkv, nullptr, Bb * NN, 3 * CC, CC);

    // 2) RoPE + head split
    int nthr = Bb * Hh * NN * 32;
    rope_split<<<nthr / 256, 256>>>(qkv, q, k, v);

    // 3) Attention (tf32 tensor cores)
    flash_mma<<<dim3(Bb * Hh, NN / 64), 128>>>(q, k, v, att);

    // 4) Projection GEMM + bias (bf16x3)
    dim3 g2(CC / 128, Bb * NN / 128);
    gemm_bf16x3<<<g2, 256>>>(att, w_proj, out, b_proj, Bb * NN, CC, CC);
}

// round 4
// speedup vs baseline: 2.8927x; 1.3324x over previous
#include <cuda_runtime.h>
#include <cuda_bf16.h>
#include <math.h>
#include <stdint.h>

// Problem shape (fixed)
#define Bb 2
#define Hh 16
#define NN 2048
#define CC 1024
#define DD 64

#define MM_ (Bb * NN)        // 4096 rows

// Scratch (device globals — no allocation allowed)
__device__ float g_qkv[(size_t)Bb * NN * 3 * CC];   // [B*N, 3C]
__device__ float g_q[(size_t)Bb * Hh * NN * DD];    // [B,H,N,d]
__device__ float g_k[(size_t)Bb * Hh * NN * DD];
__device__ float g_v[(size_t)Bb * Hh * NN * DD];

// bf16 hi/lo planes
__device__ __align__(16) __nv_bfloat16 g_xh[(size_t)MM_ * CC];
__device__ __align__(16) __nv_bfloat16 g_xl[(size_t)MM_ * CC];
__device__ __align__(16) __nv_bfloat16 g_wqh[(size_t)3 * CC * CC];  // [3072][1024] (transposed)
__device__ __align__(16) __nv_bfloat16 g_wql[(size_t)3 * CC * CC];
__device__ __align__(16) __nv_bfloat16 g_wph[(size_t)CC * CC];      // [1024][1024] (transposed)
__device__ __align__(16) __nv_bfloat16 g_wpl[(size_t)CC * CC];
__device__ __align__(16) __nv_bfloat16 g_atth[(size_t)MM_ * CC];
__device__ __align__(16) __nv_bfloat16 g_attl[(size_t)MM_ * CC];

// ---------------------------------------------------------------------------
// helpers
// ---------------------------------------------------------------------------
__device__ __forceinline__ void split1(float v, __nv_bfloat16& h, __nv_bfloat16& l) {
    h = __float2bfloat16_rn(v);
    l = __float2bfloat16_rn(v - __bfloat162float(h));
}

__device__ __forceinline__ void mma_bf16(float* d,
                                         const uint32_t* a, uint32_t b0, uint32_t b1)
{
    asm volatile(
        "mma.sync.aligned.m16n8k16.row.col.f32.bf16.bf16.f32 "
        "{%0,%1,%2,%3}, {%4,%5,%6,%7}, {%8,%9}, {%0,%1,%2,%3};"
        : "+f"(d[0]), "+f"(d[1]), "+f"(d[2]), "+f"(d[3])
        : "r"(a[0]), "r"(a[1]), "r"(a[2]), "r"(a[3]), "r"(b0), "r"(b1));
}

#define LDM4(r, addr)                                                        \
    asm volatile("ldmatrix.sync.aligned.m8n8.x4.shared.b16 {%0,%1,%2,%3}, [%4];" \
                 : "=r"((r)[0]), "=r"((r)[1]), "=r"((r)[2]), "=r"((r)[3])    \
                 : "r"(addr))

#define CP16(saddr, gptr)                                                    \
    asm volatile("cp.async.cg.shared.global [%0], [%1], 16;" :: "r"(saddr), "l"(gptr))

// ---------------------------------------------------------------------------
// split kernels (one-time prep)
// ---------------------------------------------------------------------------
__global__ void split_plain(const float* __restrict__ src,
                            __nv_bfloat16* __restrict__ hi,
                            __nv_bfloat16* __restrict__ lo)
{
    int i = blockIdx.x * blockDim.x + threadIdx.x;   // over n/4
    float4 v = ((const float4*)src)[i];
    __nv_bfloat16 h0, h1, h2, h3, l0, l1, l2, l3;
    split1(v.x, h0, l0); split1(v.y, h1, l1);
    split1(v.z, h2, l2); split1(v.w, h3, l3);
    ((__nv_bfloat162*)hi)[2 * i]     = __halves2bfloat162(h0, h1);
    ((__nv_bfloat162*)hi)[2 * i + 1] = __halves2bfloat162(h2, h3);
    ((__nv_bfloat162*)lo)[2 * i]     = __halves2bfloat162(l0, l1);
    ((__nv_bfloat162*)lo)[2 * i + 1] = __halves2bfloat162(l2, l3);
}

// W [K,N] f32  ->  hiT/loT [N,K] bf16
__global__ __launch_bounds__(256) void split_T(
    const float* __restrict__ W,
    __nv_bfloat16* __restrict__ hiT, __nv_bfloat16* __restrict__ loT,
    int K, int N)
{
    __shared__ float t[32][33];
    int n0 = blockIdx.x * 32, k0 = blockIdx.y * 32;
    int c = threadIdx.x & 31, r0 = threadIdx.x >> 5;
    #pragma unroll
    for (int j = 0; j < 4; j++) {
        int r = r0 + j * 8;
        t[r][c] = W[(size_t)(k0 + r) * N + n0 + c];
    }
    __syncthreads();
    #pragma unroll
    for (int j = 0; j < 4; j++) {
        int r = r0 + j * 8;
        float v = t[c][r];                  // = W[k0+c][n0+r]
        __nv_bfloat16 h, l;
        split1(v, h, l);
        hiT[(size_t)(n0 + r) * K + k0 + c] = h;
        loT[(size_t)(n0 + r) * K + k0 + c] = l;
    }
}

// ---------------------------------------------------------------------------
// bf16x3 pipelined GEMM: C[M,N] = A @ B^T (+bias)
// A planes: [M][K] bf16 hi/lo; B planes: [N][K] bf16 hi/lo (pre-transposed).
// Block tile 128x128, k-tile 16, 2-stage cp.async, 8 warps (warp tile 32x64).
// ---------------------------------------------------------------------------
#define KT 16
#define SST 24                 // smem row stride (elems): 16 + 8 pad, 48B
#define ARR_E (128 * SST)      // 3072 elems per plane per stage

__global__ __launch_bounds__(256, 2) void gemm_bf3(
    const __nv_bfloat16* __restrict__ Ah, const __nv_bfloat16* __restrict__ Al,
    const __nv_bfloat16* __restrict__ Bh, const __nv_bfloat16* __restrict__ Bl,
    float* __restrict__ C, const float* __restrict__ bias,
    int M, int N, int K)
{
    __shared__ __align__(16) __nv_bfloat16 sm[2 * 4 * ARR_E];   // 48 KB exactly
    const uint32_t sbase = (uint32_t)__cvta_generic_to_shared(sm);

    const int tid  = threadIdx.x;
    const int warp = tid >> 5, lane = tid & 31;
    const int gID  = lane >> 2, tig = lane & 3;
    const int bm = blockIdx.y * 128;
    const int bn = blockIdx.x * 128;
    const int m0 = (warp >> 1) * 32;
    const int n0 = (warp & 1) * 64;

    // loader: one 16B granule per plane per thread
    const int lrow = tid >> 1;
    const int lkg  = (tid & 1) * 8;
    const __nv_bfloat16* gA_h = Ah + (size_t)(bm + lrow) * K + lkg;
    const __nv_bfloat16* gA_l = Al + (size_t)(bm + lrow) * K + lkg;
    const __nv_bfloat16* gB_h = Bh + (size_t)(bn + lrow) * K + lkg;
    const __nv_bfloat16* gB_l = Bl + (size_t)(bn + lrow) * K + lkg;
    const uint32_t sdst = sbase + (uint32_t)(lrow * SST + lkg) * 2;

    // ldmatrix per-lane offsets (bytes)
    const uint32_t offA = (uint32_t)((lane & 15) * SST + (lane >> 4) * 8) * 2;
    const uint32_t offB = (uint32_t)((((lane >> 4) << 3) + (lane & 7)) * SST
                                     + ((lane >> 3) & 1) * 8) * 2;

    float acc[2][8][4];
    #pragma unroll
    for (int mi = 0; mi < 2; mi++)
        #pragma unroll
        for (int nt = 0; nt < 8; nt++)
            #pragma unroll
            for (int c = 0; c < 4; c++) acc[mi][nt][c] = 0.f;

    const int NITER = K / KT;

    // prologue: stage 0
    {
        uint32_t d = sdst;
        CP16(d + 0 * ARR_E * 2, gA_h);
        CP16(d + 1 * ARR_E * 2, gA_l);
        CP16(d + 2 * ARR_E * 2, gB_h);
        CP16(d + 3 * ARR_E * 2, gB_l);
        asm volatile("cp.async.commit_group;");
    }

    #pragma unroll 1
    for (int it = 0; it < NITER; it++) {
        const int cur = it & 1;
        if (it + 1 < NITER) {
            int k0 = (it + 1) * KT;
            uint32_t d = sdst + (uint32_t)((cur ^ 1) * 4 * ARR_E) * 2;
            CP16(d + 0 * ARR_E * 2, gA_h + k0);
            CP16(d + 1 * ARR_E * 2, gA_l + k0);
            CP16(d + 2 * ARR_E * 2, gB_h + k0);
            CP16(d + 3 * ARR_E * 2, gB_l + k0);
        }
        asm volatile("cp.async.commit_group;");
        asm volatile("cp.async.wait_group 1;");
        __syncthreads();

        const uint32_t ab = sbase + (uint32_t)(cur * 4 * ARR_E) * 2;

        uint32_t af[2][2][4];
        #pragma unroll
        for (int mi = 0; mi < 2; mi++) {
            uint32_t a0 = ab + (uint32_t)((m0 + mi * 16) * SST) * 2 + offA;
            LDM4(af[mi][0], a0);
            LDM4(af[mi][1], a0 + ARR_E * 2);
        }
        #pragma unroll
        for (int ntp = 0; ntp < 4; ntp++) {
            uint32_t b0a = ab + (uint32_t)(2 * ARR_E + (n0 + ntp * 16) * SST) * 2 + offB;
            uint32_t bh[4], bl[4];
            LDM4(bh, b0a);
            LDM4(bl, b0a + ARR_E * 2);
            #pragma unroll
            for (int mi = 0; mi < 2; mi++) {
                mma_bf16(acc[mi][2 * ntp],     af[mi][0], bh[0], bh[1]);
                mma_bf16(acc[mi][2 * ntp],     af[mi][0], bl[0], bl[1]);
                mma_bf16(acc[mi][2 * ntp],     af[mi][1], bh[0], bh[1]);
                mma_bf16(acc[mi][2 * ntp + 1], af[mi][0], bh[2], bh[3]);
                mma_bf16(acc[mi][2 * ntp + 1], af[mi][0], bl[2], bl[3]);
                mma_bf16(acc[mi][2 * ntp + 1], af[mi][1], bh[2], bh[3]);
            }
        }
        __syncthreads();
    }

    #pragma unroll
    for (int mi = 0; mi < 2; mi++) {
        int row = bm + m0 + mi * 16 + gID;
        #pragma unroll
        for (int nt = 0; nt < 8; nt++) {
            int col = bn + n0 + nt * 8 + 2 * tig;
            float b0 = bias ? bias[col] : 0.f;
            float b1 = bias ? bias[col + 1] : 0.f;
            float2 w0; w0.x = acc[mi][nt][0] + b0; w0.y = acc[mi][nt][1] + b1;
            float2 w1; w1.x = acc[mi][nt][2] + b0; w1.y = acc[mi][nt][3] + b1;
            *(float2*)&C[(size_t)row * N + col] = w0;
            *(float2*)&C[(size_t)(row + 8) * N + col] = w1;
        }
    }
}

// ---------------------------------------------------------------------------
// RoPE + split into per-head [B,H,N,d] Q/K/V.
// ---------------------------------------------------------------------------
__global__ void rope_split(const float* __restrict__ qkv,
                           float* __restrict__ Q, float* __restrict__ Kt,
                           float* __restrict__ Vt)
{
    int idx = blockIdx.x * blockDim.x + threadIdx.x;
    int i = idx & 31;
    int n = (idx >> 5) & (NN - 1);
    int h = (idx >> 16) & (Hh - 1);
    int b = idx >> 20;

    float inv_freq = powf(10000.f, -(float)i / 32.f);
    float fr = (float)n * inv_freq;
    float c = cosf(fr), s = sinf(fr);

    size_t base = ((size_t)b * NN + n) * (3 * CC) + h * DD;
    float q1 = qkv[base + i],          q2 = qkv[base + i + 32];
    float k1 = qkv[base + CC + i],     k2 = qkv[base + CC + i + 32];
    float v1 = qkv[base + 2 * CC + i], v2 = qkv[base + 2 * CC + i + 32];

    size_t ob = ((size_t)(b * Hh + h) * NN + n) * DD;
    Q[ob + i]       = q1 * c - q2 * s;
    Q[ob + i + 32]  = q1 * s + q2 * c;
    Kt[ob + i]      = k1 * c - k2 * s;
    Kt[ob + i + 32] = k1 * s + k2 * c;
    Vt[ob + i]      = v1;
    Vt[ob + i + 32] = v2;
}

// ---------------------------------------------------------------------------
// tf32 mma helpers
// ---------------------------------------------------------------------------
__device__ __forceinline__ uint32_t f2tf(float f) {
    uint32_t u;
    asm("cvt.rna.tf32.f32 %0, %1;" : "=r"(u) : "f"(f));
    return u;
}

__device__ __forceinline__ void mma_tf32(float& d0, float& d1, float& d2, float& d3,
                                         uint32_t a0, uint32_t a1, uint32_t a2, uint32_t a3,
                                         uint32_t b0, uint32_t b1)
{
    asm volatile(
        "mma.sync.aligned.m16n8k8.row.col.f32.tf32.tf32.f32 "
        "{%0,%1,%2,%3}, {%4,%5,%6,%7}, {%8,%9}, {%0,%1,%2,%3};"
        : "+f"(d0), "+f"(d1), "+f"(d2), "+f"(d3)
        : "r"(a0), "r"(a1), "r"(a2), "r"(a3), "r"(b0), "r"(b1));
}

// ---------------------------------------------------------------------------
// Flash attention with tf32 tensor-core mma. Epilogue writes bf16 hi/lo planes.
// ---------------------------------------------------------------------------
#define KSTR 68
#define VSTR 72

__global__ __launch_bounds__(128) void flash_mma(
    const float* __restrict__ Q, const float* __restrict__ K,
    const float* __restrict__ V,
    __nv_bfloat16* __restrict__ Oh, __nv_bfloat16* __restrict__ Ol)
{
    __shared__ uint32_t Ks[64 * KSTR];
    __shared__ uint32_t Vs[64 * VSTR];

    const int bh = blockIdx.x;
    const int b = bh >> 4, h = bh & 15;
    const int tid = threadIdx.x;
    const int warp = tid >> 5, lane = tid & 31;
    const int gID = lane >> 2, tig = lane & 3;
    const int qbase = blockIdx.y * 64;
    const float scale = 0.125f;

    {
        const float* qg = Q + ((size_t)bh * NN + qbase) * DD;
        #pragma unroll
        for (int it = 0; it < 8; it++) {
            int r = (tid >> 4) + it * 8;
            int c = (tid & 15) * 4;
            float4 v = *(const float4*)&qg[r * DD + c];
            uint32_t* dst = &Ks[r * KSTR + c];
            dst[0] = f2tf(v.x); dst[1] = f2tf(v.y);
            dst[2] = f2tf(v.z); dst[3] = f2tf(v.w);
        }
    }
    __syncthreads();

    uint32_t aQ[8][4];
    {
        int r0 = warp * 16 + gID;
        #pragma unroll
        for (int s = 0; s < 8; s++) {
            aQ[s][0] = Ks[r0 * KSTR + s * 8 + tig];
            aQ[s][1] = Ks[(r0 + 8) * KSTR + s * 8 + tig];
            aQ[s][2] = Ks[r0 * KSTR + s * 8 + tig + 4];
            aQ[s][3] = Ks[(r0 + 8) * KSTR + s * 8 + tig + 4];
        }
    }
    __syncthreads();

    float of[8][4];
    #pragma unroll
    for (int i = 0; i < 8; i++)
        #pragma unroll
        for (int c = 0; c < 4; c++) of[i][c] = 0.f;
    float m0 = -1e30f, m1 = -1e30f, l0 = 0.f, l1 = 0.f;

    for (int kt = 0; kt < NN; kt += 64) {
        const float* kg = K + ((size_t)bh * NN + kt) * DD;
        const float* vg = V + ((size_t)bh * NN + kt) * DD;
        #pragma unroll
        for (int it = 0; it < 8; it++) {
            int r = (tid >> 4) + it * 8;
            int c = (tid & 15) * 4;
            float4 kv = *(const float4*)&kg[r * DD + c];
            uint32_t* kd = &Ks[r * KSTR + c];
            kd[0] = f2tf(kv.x); kd[1] = f2tf(kv.y);
            kd[2] = f2tf(kv.z); kd[3] = f2tf(kv.w);
            float4 vv = *(const float4*)&vg[r * DD + c];
            uint32_t* vd = &Vs[r * VSTR + c];
            vd[0] = f2tf(vv.x); vd[1] = f2tf(vv.y);
            vd[2] = f2tf(vv.z); vd[3] = f2tf(vv.w);
        }
        __syncthreads();

        float sf[8][4];
        #pragma unroll
        for (int nt = 0; nt < 8; nt++)
            #pragma unroll
            for (int c = 0; c < 4; c++) sf[nt][c] = 0.f;

        #pragma unroll
        for (int s = 0; s < 8; s++) {
            #pragma unroll
            for (int nt = 0; nt < 8; nt++) {
                uint32_t b0 = Ks[(nt * 8 + gID) * KSTR + s * 8 + tig];
                uint32_t b1 = Ks[(nt * 8 + gID) * KSTR + s * 8 + tig + 4];
                mma_tf32(sf[nt][0], sf[nt][1], sf[nt][2], sf[nt][3],
                         aQ[s][0], aQ[s][1], aQ[s][2], aQ[s][3], b0, b1);
            }
        }

        float tmax0 = -1e30f, tmax1 = -1e30f;
        #pragma unroll
        for (int nt = 0; nt < 8; nt++) {
            sf[nt][0] *= scale; sf[nt][1] *= scale;
            sf[nt][2] *= scale; sf[nt][3] *= scale;
            tmax0 = fmaxf(tmax0, fmaxf(sf[nt][0], sf[nt][1]));
            tmax1 = fmaxf(tmax1, fmaxf(sf[nt][2], sf[nt][3]));
        }
        tmax0 = fmaxf(tmax0, __shfl_xor_sync(0xffffffffu, tmax0, 1));
        tmax0 = fmaxf(tmax0, __shfl_xor_sync(0xffffffffu, tmax0, 2));
        tmax1 = fmaxf(tmax1, __shfl_xor_sync(0xffffffffu, tmax1, 1));
        tmax1 = fmaxf(tmax1, __shfl_xor_sync(0xffffffffu, tmax1, 2));

        float mn0 = fmaxf(m0, tmax0);
        float mn1 = fmaxf(m1, tmax1);
        float al0 = __expf(m0 - mn0);
        float al1 = __expf(m1 - mn1);
        m0 = mn0; m1 = mn1;
        l0 *= al0; l1 *= al1;
        #pragma unroll
        for (int i = 0; i < 8; i++) {
            of[i][0] *= al0; of[i][1] *= al0;
            of[i][2] *= al1; of[i][3] *= al1;
        }
        #pragma unroll
        for (int nt = 0; nt < 8; nt++) {
            sf[nt][0] = __expf(sf[nt][0] - mn0);
            sf[nt][1] = __expf(sf[nt][1] - mn0);
            sf[nt][2] = __expf(sf[nt][2] - mn1);
            sf[nt][3] = __expf(sf[nt][3] - mn1);
            l0 += sf[nt][0] + sf[nt][1];
            l1 += sf[nt][2] + sf[nt][3];
        }

        #pragma unroll
        for (int j = 0; j < 8; j++) {
            int srcA = (lane & ~3) | (tig >> 1);
            float x0 = __shfl_sync(0xffffffffu, sf[j][0], srcA);
            float x1 = __shfl_sync(0xffffffffu, sf[j][1], srcA);
            float y0 = __shfl_sync(0xffffffffu, sf[j][2], srcA);
            float y1 = __shfl_sync(0xffffffffu, sf[j][3], srcA);
            float x2 = __shfl_sync(0xffffffffu, sf[j][0], srcA + 2);
            float x3 = __shfl_sync(0xffffffffu, sf[j][1], srcA + 2);
            float y2 = __shfl_sync(0xffffffffu, sf[j][2], srcA + 2);
            float y3 = __shfl_sync(0xffffffffu, sf[j][3], srcA + 2);
            uint32_t a0 = __float_as_uint((tig & 1) ? x1 : x0);
            uint32_t a1 = __float_as_uint((tig & 1) ? y1 : y0);
            uint32_t a2 = __float_as_uint((tig & 1) ? x3 : x2);
            uint32_t a3 = __float_as_uint((tig & 1) ? y3 : y2);
            #pragma unroll
            for (int i = 0; i < 8; i++) {
                uint32_t b0 = Vs[(j * 8 + tig) * VSTR + i * 8 + gID];
                uint32_t b1 = Vs[(j * 8 + tig + 4) * VSTR + i * 8 + gID];
                mma_tf32(of[i][0], of[i][1], of[i][2], of[i][3],
                         a0, a1, a2, a3, b0, b1);
            }
        }
        __syncthreads();
    }

    l0 += __shfl_xor_sync(0xffffffffu, l0, 1);
    l0 += __shfl_xor_sync(0xffffffffu, l0, 2);
    l1 += __shfl_xor_sync(0xffffffffu, l1, 1);
    l1 += __shfl_xor_sync(0xffffffffu, l1, 2);
    float inv0 = 1.f / l0;
    float inv1 = 1.f / l1;

    int r0 = qbase + warp * 16 + gID;
    int r1 = r0 + 8;
    size_t base0 = ((size_t)b * NN + r0) * CC + h * DD;
    size_t base1 = ((size_t)b * NN + r1) * CC + h * DD;
    #pragma unroll
    for (int i = 0; i < 8; i++) {
        int col = i * 8 + 2 * tig;
        float v00 = of[i][0] * inv0, v01 = of[i][1] * inv0;
        float v10 = of[i][2] * inv1, v11 = of[i][3] * inv1;
        __nv_bfloat16 h00, h01, h10, h11, l00, l01, l10, l11;
        split1(v00, h00, l00); split1(v01, h01, l01);
        split1(v10, h10, l10); split1(v11, h11, l11);
        *(__nv_bfloat162*)&Oh[base0 + col] = __halves2bfloat162(h00, h01);
        *(__nv_bfloat162*)&Ol[base0 + col] = __halves2bfloat162(l00, l01);
        *(__nv_bfloat162*)&Oh[base1 + col] = __halves2bfloat162(h10, h11);
        *(__nv_bfloat162*)&Ol[base1 + col] = __halves2bfloat162(l10, l11);
    }
}

// ---------------------------------------------------------------------------
extern "C" void kernel_launch(void* const* d_in, const int* in_sizes, int n_in,
                              void* d_out, int out_size)
{
    const float* x      = (const float*)d_in[0];
    const float* w_qkv  = (const float*)d_in[1];
    const float* w_proj = (const float*)d_in[2];
    const float* b_proj = (const float*)d_in[3];
    float* out = (float*)d_out;

    float *qkv, *q, *k, *v;
    cudaGetSymbolAddress((void**)&qkv, g_qkv);
    cudaGetSymbolAddress((void**)&q,   g_q);
    cudaGetSymbolAddress((void**)&k,   g_k);
    cudaGetSymbolAddress((void**)&v,   g_v);
    __nv_bfloat16 *xh, *xl, *wqh, *wql, *wph, *wpl, *ath, *atl;
    cudaGetSymbolAddress((void**)&xh,  g_xh);
    cudaGetSymbolAddress((void**)&xl,  g_xl);
    cudaGetSymbolAddress((void**)&wqh, g_wqh);
    cudaGetSymbolAddress((void**)&wql, g_wql);
    cudaGetSymbolAddress((void**)&wph, g_wph);
    cudaGetSymbolAddress((void**)&wpl, g_wpl);
    cudaGetSymbolAddress((void**)&ath, g_atth);
    cudaGetSymbolAddress((void**)&atl, g_attl);

    // 0) one-time splits
    split_plain<<<(MM_ * CC / 4) / 256, 256>>>(x, xh, xl);
    split_T<<<dim3(3 * CC / 32, CC / 32), 256>>>(w_qkv, wqh, wql, CC, 3 * CC);
    split_T<<<dim3(CC / 32, CC / 32), 256>>>(w_proj, wph, wpl, CC, CC);

    // 1) QKV GEMM: [4096, 3072] (bf16x3 pipelined)
    gemm_bf3<<<dim3(3 * CC / 128, MM_ / 128), 256>>>(
        xh, xl, wqh, wql, qkv, nullptr, MM_, 3 * CC, CC);

    // 2) RoPE + head split
    rope_split<<<(Bb * Hh * NN * 32) / 256, 256>>>(qkv, q, k, v);

    // 3) Attention (tf32 tensor cores) -> bf16 hi/lo planes
    flash_mma<<<dim3(Bb * Hh, NN / 64), 128>>>(q, k, v, ath, atl);

    // 4) Projection GEMM + bias
    gemm_bf3<<<dim3(CC / 128, MM_ / 128), 256>>>(
        ath, atl, wph, wpl, out, b_proj, MM_, CC, CC);
}

// round 5
// speedup vs baseline: 3.4123x; 1.1796x over previous
#include <cuda_runtime.h>
#include <cuda_bf16.h>
#include <math.h>
#include <stdint.h>

// Problem shape (fixed)
#define Bb 2
#define Hh 16
#define NN 2048
#define CC 1024
#define DD 64
#define MM_ (Bb * NN)        // 4096 rows

// Scratch (device globals — no allocation allowed)
__device__ float g_qkv[(size_t)Bb * NN * 3 * CC];   // [B*N, 3C]
__device__ float g_q[(size_t)Bb * Hh * NN * DD];    // [B,H,N,d] (tf32-rounded)
__device__ float g_k[(size_t)Bb * Hh * NN * DD];
__device__ float g_v[(size_t)Bb * Hh * NN * DD];

// bf16 hi/lo planes
__device__ __align__(16) __nv_bfloat16 g_xh[(size_t)MM_ * CC];
__device__ __align__(16) __nv_bfloat16 g_xl[(size_t)MM_ * CC];
__device__ __align__(16) __nv_bfloat16 g_wqh[(size_t)3 * CC * CC];  // [3072][1024] (transposed)
__device__ __align__(16) __nv_bfloat16 g_wql[(size_t)3 * CC * CC];
__device__ __align__(16) __nv_bfloat16 g_wph[(size_t)CC * CC];      // [1024][1024] (transposed)
__device__ __align__(16) __nv_bfloat16 g_wpl[(size_t)CC * CC];
__device__ __align__(16) __nv_bfloat16 g_atth[(size_t)MM_ * CC];
__device__ __align__(16) __nv_bfloat16 g_attl[(size_t)MM_ * CC];

// ---------------------------------------------------------------------------
// helpers
// ---------------------------------------------------------------------------
__device__ __forceinline__ void split1(float v, __nv_bfloat16& h, __nv_bfloat16& l) {
    h = __float2bfloat16_rn(v);
    l = __float2bfloat16_rn(v - __bfloat162float(h));
}

__device__ __forceinline__ uint32_t f2tf(float f) {
    uint32_t u;
    asm("cvt.rna.tf32.f32 %0, %1;" : "=r"(u) : "f"(f));
    return u;
}

__device__ __forceinline__ void mma_bf16(float* d,
                                         const uint32_t* a, uint32_t b0, uint32_t b1)
{
    asm volatile(
        "mma.sync.aligned.m16n8k16.row.col.f32.bf16.bf16.f32 "
        "{%0,%1,%2,%3}, {%4,%5,%6,%7}, {%8,%9}, {%0,%1,%2,%3};"
        : "+f"(d[0]), "+f"(d[1]), "+f"(d[2]), "+f"(d[3])
        : "r"(a[0]), "r"(a[1]), "r"(a[2]), "r"(a[3]), "r"(b0), "r"(b1));
}

__device__ __forceinline__ void mma_tf32(float& d0, float& d1, float& d2, float& d3,
                                         uint32_t a0, uint32_t a1, uint32_t a2, uint32_t a3,
                                         uint32_t b0, uint32_t b1)
{
    asm volatile(
        "mma.sync.aligned.m16n8k8.row.col.f32.tf32.tf32.f32 "
        "{%0,%1,%2,%3}, {%4,%5,%6,%7}, {%8,%9}, {%0,%1,%2,%3};"
        : "+f"(d0), "+f"(d1), "+f"(d2), "+f"(d3)
        : "r"(a0), "r"(a1), "r"(a2), "r"(a3), "r"(b0), "r"(b1));
}

#define LDM4(r, addr)                                                        \
    asm volatile("ldmatrix.sync.aligned.m8n8.x4.shared.b16 {%0,%1,%2,%3}, [%4];" \
                 : "=r"((r)[0]), "=r"((r)[1]), "=r"((r)[2]), "=r"((r)[3])    \
                 : "r"(addr))

#define CP16(saddr, gptr)                                                    \
    asm volatile("cp.async.cg.shared.global [%0], [%1], 16;" :: "r"(saddr), "l"(gptr))

// ---------------------------------------------------------------------------
// split kernels (one-time prep)
// ---------------------------------------------------------------------------
__global__ void split_plain(const float* __restrict__ src,
                            __nv_bfloat16* __restrict__ hi,
                            __nv_bfloat16* __restrict__ lo)
{
    int i = blockIdx.x * blockDim.x + threadIdx.x;   // over n/4
    float4 v = ((const float4*)src)[i];
    __nv_bfloat16 h0, h1, h2, h3, l0, l1, l2, l3;
    split1(v.x, h0, l0); split1(v.y, h1, l1);
    split1(v.z, h2, l2); split1(v.w, h3, l3);
    ((__nv_bfloat162*)hi)[2 * i]     = __halves2bfloat162(h0, h1);
    ((__nv_bfloat162*)hi)[2 * i + 1] = __halves2bfloat162(h2, h3);
    ((__nv_bfloat162*)lo)[2 * i]     = __halves2bfloat162(l0, l1);
    ((__nv_bfloat162*)lo)[2 * i + 1] = __halves2bfloat162(l2, l3);
}

// W [K,N] f32  ->  hiT/loT [N,K] bf16
__global__ __launch_bounds__(256) void split_T(
    const float* __restrict__ W,
    __nv_bfloat16* __restrict__ hiT, __nv_bfloat16* __restrict__ loT,
    int K, int N)
{
    __shared__ float t[32][33];
    int n0 = blockIdx.x * 32, k0 = blockIdx.y * 32;
    int c = threadIdx.x & 31, r0 = threadIdx.x >> 5;
    #pragma unroll
    for (int j = 0; j < 4; j++) {
        int r = r0 + j * 8;
        t[r][c] = W[(size_t)(k0 + r) * N + n0 + c];
    }
    __syncthreads();
    #pragma unroll
    for (int j = 0; j < 4; j++) {
        int r = r0 + j * 8;
        float v = t[c][r];                  // = W[k0+c][n0+r]
        __nv_bfloat16 h, l;
        split1(v, h, l);
        hiT[(size_t)(n0 + r) * K + k0 + c] = h;
        loT[(size_t)(n0 + r) * K + k0 + c] = l;
    }
}

// ---------------------------------------------------------------------------
// bf16x3 3-stage pipelined GEMM: C[M,N] = A @ B^T (+bias)
// A planes [M][K], B planes [N][K] bf16. Block 128x128, k-tile 32, 3 stages.
// Rows are 64B, XOR-swizzled granules: g' = g ^ ((row>>1)&3) -> conflict-free
// ldmatrix AND conflict-free cp.async stores, zero padding.
// ---------------------------------------------------------------------------
#define GPLANE 8192            // 128 rows * 64 B
#define GSTG   32768           // 4 planes

__global__ void __launch_bounds__(256, 2) gemm_bf3(
    const __nv_bfloat16* __restrict__ Ah, const __nv_bfloat16* __restrict__ Al,
    const __nv_bfloat16* __restrict__ Bh, const __nv_bfloat16* __restrict__ Bl,
    float* __restrict__ C, const float* __restrict__ bias,
    int M, int N, int K)
{
    extern __shared__ __align__(16) char smg[];
    const uint32_t sbase = (uint32_t)__cvta_generic_to_shared(smg);

    const int tid  = threadIdx.x;
    const int warp = tid >> 5, lane = tid & 31;
    const int gID  = lane >> 2, tig = lane & 3;
    const int bm = blockIdx.y * 128;
    const int bn = blockIdx.x * 128;
    const int m0 = (warp >> 1) * 32;
    const int n0 = (warp & 1) * 64;

    // ---- loader: plane = tid>>6, 8 granules (16B) each ----
    const int lp   = tid >> 6;
    const int lid0 = tid & 63;
    const __nv_bfloat16* gplane =
        lp == 0 ? Ah + (size_t)bm * K :
        lp == 1 ? Al + (size_t)bm * K :
        lp == 2 ? Bh + (size_t)bn * K :
                  Bl + (size_t)bn * K;
    int      lsrc[8];
    uint32_t ldst[8];
    #pragma unroll
    for (int j = 0; j < 8; j++) {
        int id = lid0 + j * 64;
        int r = id >> 2, g = id & 3;
        lsrc[j] = r * K + g * 8;
        ldst[j] = (uint32_t)(lp * GPLANE + r * 64 + ((g ^ ((r >> 1) & 3)) << 4));
    }
#define GLOAD(st, k0)                                                          \
    do { for (int j_ = 0; j_ < 8; j_++)                                        \
             CP16(sbase + (uint32_t)(st) * GSTG + ldst[j_], gplane + lsrc[j_] + (k0)); \
    } while (0)

    // ---- fragment address precompute ----
    uint32_t aoff[2]; int aswz[2];
    #pragma unroll
    for (int mi = 0; mi < 2; mi++) {
        int r = m0 + mi * 16 + (lane & 15);
        aoff[mi] = (uint32_t)(r * 64);
        aswz[mi] = (r >> 1) & 3;
    }
    const int ghA = lane >> 4;
    uint32_t boff[4]; int bswz[4];
    const int permB = ((lane >> 4) << 3) + (lane & 7);
    const int gbB = (lane >> 3) & 1;
    #pragma unroll
    for (int ntp = 0; ntp < 4; ntp++) {
        int r = n0 + ntp * 16 + permB;
        boff[ntp] = (uint32_t)(r * 64);
        bswz[ntp] = (r >> 1) & 3;
    }

    float acc[2][8][4];
    #pragma unroll
    for (int mi = 0; mi < 2; mi++)
        #pragma unroll
        for (int nt = 0; nt < 8; nt++)
            #pragma unroll
            for (int c = 0; c < 4; c++) acc[mi][nt][c] = 0.f;

    const int NIT = K >> 5;

    GLOAD(0, 0);
    asm volatile("cp.async.commit_group;");
    GLOAD(1, 32);
    asm volatile("cp.async.commit_group;");

    int cur = 0;
    #pragma unroll 1
    for (int it = 0; it < NIT; it++) {
        asm volatile("cp.async.wait_group 1;");
        __syncthreads();
        int nxt = cur + 2; if (nxt >= 3) nxt -= 3;
        if (it + 2 < NIT) GLOAD(nxt, (it + 2) * 32);
        asm volatile("cp.async.commit_group;");

        const uint32_t stb = sbase + (uint32_t)cur * GSTG;
        #pragma unroll
        for (int s = 0; s < 2; s++) {
            uint32_t af[2][2][4];
            #pragma unroll
            for (int mi = 0; mi < 2; mi++) {
                uint32_t ra = stb + aoff[mi] + (uint32_t)((((s << 1) + ghA) ^ aswz[mi]) << 4);
                LDM4(af[mi][0], ra);
                LDM4(af[mi][1], ra + GPLANE);
            }
            #pragma unroll
            for (int ntp = 0; ntp < 4; ntp++) {
                uint32_t rb = stb + 2 * GPLANE + boff[ntp]
                              + (uint32_t)((((s << 1) + gbB) ^ bswz[ntp]) << 4);
                uint32_t bh4[4], bl4[4];
                LDM4(bh4, rb);
                LDM4(bl4, rb + GPLANE);
                #pragma unroll
                for (int mi = 0; mi < 2; mi++) {
                    mma_bf16(acc[mi][2 * ntp],     af[mi][0], bh4[0], bh4[1]);
                    mma_bf16(acc[mi][2 * ntp],     af[mi][0], bl4[0], bl4[1]);
                    mma_bf16(acc[mi][2 * ntp],     af[mi][1], bh4[0], bh4[1]);
                    mma_bf16(acc[mi][2 * ntp + 1], af[mi][0], bh4[2], bh4[3]);
                    mma_bf16(acc[mi][2 * ntp + 1], af[mi][0], bl4[2], bl4[3]);
                    mma_bf16(acc[mi][2 * ntp + 1], af[mi][1], bh4[2], bh4[3]);
                }
            }
        }
        cur = cur + 1; if (cur == 3) cur = 0;
    }

    #pragma unroll
    for (int mi = 0; mi < 2; mi++) {
        int row = bm + m0 + mi * 16 + gID;
        #pragma unroll
        for (int nt = 0; nt < 8; nt++) {
            int col = bn + n0 + nt * 8 + 2 * tig;
            float b0 = bias ? bias[col] : 0.f;
            float b1 = bias ? bias[col + 1] : 0.f;
            float2 w0; w0.x = acc[mi][nt][0] + b0; w0.y = acc[mi][nt][1] + b1;
            float2 w1; w1.x = acc[mi][nt][2] + b0; w1.y = acc[mi][nt][3] + b1;
            *(float2*)&C[(size_t)row * N + col] = w0;
            *(float2*)&C[(size_t)(row + 8) * N + col] = w1;
        }
    }
#undef GLOAD
}

// ---------------------------------------------------------------------------
// RoPE + split into per-head [B,H,N,d] Q/K/V — outputs tf32-rounded fp32.
// ---------------------------------------------------------------------------
__global__ void rope_split(const float* __restrict__ qkv,
                           float* __restrict__ Q, float* __restrict__ Kt,
                           float* __restrict__ Vt)
{
    int idx = blockIdx.x * blockDim.x + threadIdx.x;
    int i = idx & 31;
    int n = (idx >> 5) & (NN - 1);
    int h = (idx >> 16) & (Hh - 1);
    int b = idx >> 20;

    float inv_freq = powf(10000.f, -(float)i / 32.f);
    float fr = (float)n * inv_freq;
    float c = cosf(fr), s = sinf(fr);

    size_t base = ((size_t)b * NN + n) * (3 * CC) + h * DD;
    float q1 = qkv[base + i],          q2 = qkv[base + i + 32];
    float k1 = qkv[base + CC + i],     k2 = qkv[base + CC + i + 32];
    float v1 = qkv[base + 2 * CC + i], v2 = qkv[base + 2 * CC + i + 32];

    size_t ob = ((size_t)(b * Hh + h) * NN + n) * DD;
    Q[ob + i]       = __uint_as_float(f2tf(q1 * c - q2 * s));
    Q[ob + i + 32]  = __uint_as_float(f2tf(q1 * s + q2 * c));
    Kt[ob + i]      = __uint_as_float(f2tf(k1 * c - k2 * s));
    Kt[ob + i + 32] = __uint_as_float(f2tf(k1 * s + k2 * c));
    Vt[ob + i]      = __uint_as_float(f2tf(v1));
    Vt[ob + i + 32] = __uint_as_float(f2tf(v2));
}

// ---------------------------------------------------------------------------
// Flash attention, tf32 mma, 2-stage cp.async KV pipeline.
// Inputs are pre-rounded tf32 (stored fp32) -> zero conversion in hot loop.
// ---------------------------------------------------------------------------
#define KSTR 68
#define VSTR 72
#define KSB  17408             // 64 * 68 * 4
#define VSB  18432             // 64 * 72 * 4

__global__ void __launch_bounds__(128) flash_mma(
    const float* __restrict__ Q, const float* __restrict__ K,
    const float* __restrict__ V,
    __nv_bfloat16* __restrict__ Oh, __nv_bfloat16* __restrict__ Ol)
{
    extern __shared__ __align__(16) char sma[];
    const uint32_t sb = (uint32_t)__cvta_generic_to_shared(sma);

    const int bh = blockIdx.x;
    const int b = bh >> 4, h = bh & 15;
    const int tid = threadIdx.x;
    const int warp = tid >> 5, lane = tid & 31;
    const int gID = lane >> 2, tig = lane & 3;
    const int qbase = blockIdx.y * 64;
    const float scale = 0.125f;

    // ---- stage Q tile into stage-0 Ks region, extract A-frags ----
    {
        const float* qg = Q + ((size_t)bh * NN + qbase) * DD;
        uint32_t* Qs = (uint32_t*)sma;
        #pragma unroll
        for (int it = 0; it < 8; it++) {
            int r = (tid >> 4) + it * 8;
            int c = (tid & 15) * 4;
            float4 v = *(const float4*)&qg[r * DD + c];
            uint32_t* dst = &Qs[r * KSTR + c];
            dst[0] = __float_as_uint(v.x); dst[1] = __float_as_uint(v.y);
            dst[2] = __float_as_uint(v.z); dst[3] = __float_as_uint(v.w);
        }
    }
    __syncthreads();

    uint32_t aQ[8][4];
    {
        const uint32_t* Qs = (const uint32_t*)sma;
        int r0 = warp * 16 + gID;
        #pragma unroll
        for (int s = 0; s < 8; s++) {
            aQ[s][0] = Qs[r0 * KSTR + s * 8 + tig];
            aQ[s][1] = Qs[(r0 + 8) * KSTR + s * 8 + tig];
            aQ[s][2] = Qs[r0 * KSTR + s * 8 + tig + 4];
            aQ[s][3] = Qs[(r0 + 8) * KSTR + s * 8 + tig + 4];
        }
    }
    __syncthreads();

    // ---- KV cp.async loader setup ----
    const float* kbase = K + (size_t)bh * NN * DD;
    const float* vbase = V + (size_t)bh * NN * DD;
    int      asrc[8];
    uint32_t kdst[8], vdst[8];
    #pragma unroll
    for (int j = 0; j < 8; j++) {
        int id = tid + j * 128;
        int r = id >> 4, g = id & 15;
        asrc[j] = r * DD + g * 4;
        kdst[j] = (uint32_t)(r * 272 + g * 16);
        vdst[j] = (uint32_t)(2 * KSB + r * 288 + g * 16);
    }
#define KVLOAD(st, row0)                                                       \
    do { for (int j_ = 0; j_ < 8; j_++) {                                      \
             CP16(sb + (uint32_t)(st) * KSB + kdst[j_],                        \
                  kbase + (size_t)(row0) * DD + asrc[j_]);                     \
             CP16(sb + (uint32_t)(st) * VSB + vdst[j_],                        \
                  vbase + (size_t)(row0) * DD + asrc[j_]);                     \
         } } while (0)

    float of[8][4];
    #pragma unroll
    for (int i = 0; i < 8; i++)
        #pragma unroll
        for (int c = 0; c < 4; c++) of[i][c] = 0.f;
    float m0 = -1e30f, m1 = -1e30f, l0 = 0.f, l1 = 0.f;

    KVLOAD(0, 0);
    asm volatile("cp.async.commit_group;");

    #pragma unroll 1
    for (int t = 0; t < 32; t++) {
        asm volatile("cp.async.wait_group 0;");
        __syncthreads();
        if (t + 1 < 32) KVLOAD((t + 1) & 1, (t + 1) * 64);
        asm volatile("cp.async.commit_group;");

        const uint32_t* Ks = (const uint32_t*)(sma + (t & 1) * KSB);
        const uint32_t* Vs = (const uint32_t*)(sma + 2 * KSB + (t & 1) * VSB);

        // ---- S = Q . K^T ----
        float sf[8][4];
        #pragma unroll
        for (int nt = 0; nt < 8; nt++)
            #pragma unroll
            for (int c = 0; c < 4; c++) sf[nt][c] = 0.f;

        #pragma unroll
        for (int s = 0; s < 8; s++) {
            #pragma unroll
            for (int nt = 0; nt < 8; nt++) {
                uint32_t b0 = Ks[(nt * 8 + gID) * KSTR + s * 8 + tig];
                uint32_t b1 = Ks[(nt * 8 + gID) * KSTR + s * 8 + tig + 4];
                mma_tf32(sf[nt][0], sf[nt][1], sf[nt][2], sf[nt][3],
                         aQ[s][0], aQ[s][1], aQ[s][2], aQ[s][3], b0, b1);
            }
        }

        // ---- online softmax ----
        float tmax0 = -1e30f, tmax1 = -1e30f;
        #pragma unroll
        for (int nt = 0; nt < 8; nt++) {
            sf[nt][0] *= scale; sf[nt][1] *= scale;
            sf[nt][2] *= scale; sf[nt][3] *= scale;
            tmax0 = fmaxf(tmax0, fmaxf(sf[nt][0], sf[nt][1]));
            tmax1 = fmaxf(tmax1, fmaxf(sf[nt][2], sf[nt][3]));
        }
        tmax0 = fmaxf(tmax0, __shfl_xor_sync(0xffffffffu, tmax0, 1));
        tmax0 = fmaxf(tmax0, __shfl_xor_sync(0xffffffffu, tmax0, 2));
        tmax1 = fmaxf(tmax1, __shfl_xor_sync(0xffffffffu, tmax1, 1));
        tmax1 = fmaxf(tmax1, __shfl_xor_sync(0xffffffffu, tmax1, 2));

        float mn0 = fmaxf(m0, tmax0);
        float mn1 = fmaxf(m1, tmax1);
        float al0 = __expf(m0 - mn0);
        float al1 = __expf(m1 - mn1);
        m0 = mn0; m1 = mn1;
        l0 *= al0; l1 *= al1;
        #pragma unroll
        for (int i = 0; i < 8; i++) {
            of[i][0] *= al0; of[i][1] *= al0;
            of[i][2] *= al1; of[i][3] *= al1;
        }
        #pragma unroll
        for (int nt = 0; nt < 8; nt++) {
            sf[nt][0] = __expf(sf[nt][0] - mn0);
            sf[nt][1] = __expf(sf[nt][1] - mn0);
            sf[nt][2] = __expf(sf[nt][2] - mn1);
            sf[nt][3] = __expf(sf[nt][3] - mn1);
            l0 += sf[nt][0] + sf[nt][1];
            l1 += sf[nt][2] + sf[nt][3];
        }

        // ---- O += P . V ----
        #pragma unroll
        for (int j = 0; j < 8; j++) {
            int srcA = (lane & ~3) | (tig >> 1);
            float x0 = __shfl_sync(0xffffffffu, sf[j][0], srcA);
            float x1 = __shfl_sync(0xffffffffu, sf[j][1], srcA);
            float y0 = __shfl_sync(0xffffffffu, sf[j][2], srcA);
            float y1 = __shfl_sync(0xffffffffu, sf[j][3], srcA);
            float x2 = __shfl_sync(0xffffffffu, sf[j][0], srcA + 2);
            float x3 = __shfl_sync(0xffffffffu, sf[j][1], srcA + 2);
            float y2 = __shfl_sync(0xffffffffu, sf[j][2], srcA + 2);
            float y3 = __shfl_sync(0xffffffffu, sf[j][3], srcA + 2);
            uint32_t a0 = __float_as_uint((tig & 1) ? x1 : x0);
            uint32_t a1 = __float_as_uint((tig & 1) ? y1 : y0);
            uint32_t a2 = __float_as_uint((tig & 1) ? x3 : x2);
            uint32_t a3 = __float_as_uint((tig & 1) ? y3 : y2);
            #pragma unroll
            for (int i = 0; i < 8; i++) {
                uint32_t b0 = Vs[(j * 8 + tig) * VSTR + i * 8 + gID];
                uint32_t b1 = Vs[(j * 8 + tig + 4) * VSTR + i * 8 + gID];
                mma_tf32(of[i][0], of[i][1], of[i][2], of[i][3],
                         a0, a1, a2, a3, b0, b1);
            }
        }
    }

    l0 += __shfl_xor_sync(0xffffffffu, l0, 1);
    l0 += __shfl_xor_sync(0xffffffffu, l0, 2);
    l1 += __shfl_xor_sync(0xffffffffu, l1, 1);
    l1 += __shfl_xor_sync(0xffffffffu, l1, 2);
    float inv0 = 1.f / l0;
    float inv1 = 1.f / l1;

    int r0 = qbase + warp * 16 + gID;
    int r1 = r0 + 8;
    size_t base0 = ((size_t)b * NN + r0) * CC + h * DD;
    size_t base1 = ((size_t)b * NN + r1) * CC + h * DD;
    #pragma unroll
    for (int i = 0; i < 8; i++) {
        int col = i * 8 + 2 * tig;
        float v00 = of[i][0] * inv0, v01 = of[i][1] * inv0;
        float v10 = of[i][2] * inv1, v11 = of[i][3] * inv1;
        __nv_bfloat16 h00, h01, h10, h11, l00x, l01x, l10x, l11x;
        split1(v00, h00, l00x); split1(v01, h01, l01x);
        split1(v10, h10, l10x); split1(v11, h11, l11x);
        *(__nv_bfloat162*)&Oh[base0 + col] = __halves2bfloat162(h00, h01);
        *(__nv_bfloat162*)&Ol[base0 + col] = __halves2bfloat162(l00x, l01x);
        *(__nv_bfloat162*)&Oh[base1 + col] = __halves2bfloat162(h10, h11);
        *(__nv_bfloat162*)&Ol[base1 + col] = __halves2bfloat162(l10x, l11x);
    }
#undef KVLOAD
}

// ---------------------------------------------------------------------------
extern "C" void kernel_launch(void* const* d_in, const int* in_sizes, int n_in,
                              void* d_out, int out_size)
{
    const float* x      = (const float*)d_in[0];
    const float* w_qkv  = (const float*)d_in[1];
    const float* w_proj = (const float*)d_in[2];
    const float* b_proj = (const float*)d_in[3];
    float* out = (float*)d_out;

    float *qkv, *q, *k, *v;
    cudaGetSymbolAddress((void**)&qkv, g_qkv);
    cudaGetSymbolAddress((void**)&q,   g_q);
    cudaGetSymbolAddress((void**)&k,   g_k);
    cudaGetSymbolAddress((void**)&v,   g_v);
    __nv_bfloat16 *xh, *xl, *wqh, *wql, *wph, *wpl, *ath, *atl;
    cudaGetSymbolAddress((void**)&xh,  g_xh);
    cudaGetSymbolAddress((void**)&xl,  g_xl);
    cudaGetSymbolAddress((void**)&wqh, g_wqh);
    cudaGetSymbolAddress((void**)&wql, g_wql);
    cudaGetSymbolAddress((void**)&wph, g_wph);
    cudaGetSymbolAddress((void**)&wpl, g_wpl);
    cudaGetSymbolAddress((void**)&ath, g_atth);
    cudaGetSymbolAddress((void**)&atl, g_attl);

    static int attr_done = 0;
    if (!attr_done) {
        cudaFuncSetAttribute(gemm_bf3, cudaFuncAttributeMaxDynamicSharedMemorySize,
                             3 * GSTG);
        cudaFuncSetAttribute(flash_mma, cudaFuncAttributeMaxDynamicSharedMemorySize,
                             2 * KSB + 2 * VSB);
        attr_done = 1;
    }

    // 0) one-time splits
    split_plain<<<(MM_ * CC / 4) / 256, 256>>>(x, xh, xl);
    split_T<<<dim3(3 * CC / 32, CC / 32), 256>>>(w_qkv, wqh, wql, CC, 3 * CC);
    split_T<<<dim3(CC / 32, CC / 32), 256>>>(w_proj, wph, wpl, CC, CC);

    // 1) QKV GEMM: [4096, 3072] (bf16x3, 3-stage pipeline)
    gemm_bf3<<<dim3(3 * CC / 128, MM_ / 128), 256, 3 * GSTG>>>(
        xh, xl, wqh, wql, qkv, nullptr, MM_, 3 * CC, CC);

    // 2) RoPE + head split (tf32-rounded outputs)
    rope_split<<<(Bb * Hh * NN * 32) / 256, 256>>>(qkv, q, k, v);

    // 3) Attention (tf32 tensor cores, pipelined KV)
    flash_mma<<<dim3(Bb * Hh, NN / 64), 128, 2 * KSB + 2 * VSB>>>(q, k, v, ath, atl);

    // 4) Projection GEMM + bias
    gemm_bf3<<<dim3(CC / 128, MM_ / 128), 256, 3 * GSTG>>>(
        ath, atl, wph, wpl, out, b_proj, MM_, CC, CC);
}

// round 7
// speedup vs baseline: 3.6989x; 1.0840x over previous
#include <cuda_runtime.h>
#include <cuda_bf16.h>
#include <math.h>
#include <stdint.h>

// Problem shape (fixed)
#define Bb 2
#define Hh 16
#define NN 2048
#define CC 1024
#define DD 64
#define MM_ (Bb * NN)        // 4096 rows

// Scratch (device globals — no allocation allowed)
__device__ float g_qkv[(size_t)Bb * NN * 3 * CC];   // [B*N, 3C]
__device__ float g_q[(size_t)Bb * Hh * NN * DD];    // [B,H,N,d] (tf32-rounded)
__device__ float g_k[(size_t)Bb * Hh * NN * DD];
__device__ float g_v[(size_t)Bb * Hh * NN * DD];

// bf16 hi/lo planes
__device__ __align__(16) __nv_bfloat16 g_xh[(size_t)MM_ * CC];
__device__ __align__(16) __nv_bfloat16 g_xl[(size_t)MM_ * CC];
__device__ __align__(16) __nv_bfloat16 g_wqh[(size_t)3 * CC * CC];  // [3072][1024] (transposed)
__device__ __align__(16) __nv_bfloat16 g_wql[(size_t)3 * CC * CC];
__device__ __align__(16) __nv_bfloat16 g_wph[(size_t)CC * CC];      // [1024][1024] (transposed)
__device__ __align__(16) __nv_bfloat16 g_wpl[(size_t)CC * CC];
__device__ __align__(16) __nv_bfloat16 g_atth[(size_t)MM_ * CC];
__device__ __align__(16) __nv_bfloat16 g_attl[(size_t)MM_ * CC];

// ---------------------------------------------------------------------------
// helpers
// ---------------------------------------------------------------------------
__device__ __forceinline__ void split1(float v, __nv_bfloat16& h, __nv_bfloat16& l) {
    h = __float2bfloat16_rn(v);
    l = __float2bfloat16_rn(v - __bfloat162float(h));
}

__device__ __forceinline__ uint32_t f2tf(float f) {
    uint32_t u;
    asm("cvt.rna.tf32.f32 %0, %1;" : "=r"(u) : "f"(f));
    return u;
}

__device__ __forceinline__ void mma_bf16(float* d,
                                         const uint32_t* a, uint32_t b0, uint32_t b1)
{
    asm volatile(
        "mma.sync.aligned.m16n8k16.row.col.f32.bf16.bf16.f32 "
        "{%0,%1,%2,%3}, {%4,%5,%6,%7}, {%8,%9}, {%0,%1,%2,%3};"
        : "+f"(d[0]), "+f"(d[1]), "+f"(d[2]), "+f"(d[3])
        : "r"(a[0]), "r"(a[1]), "r"(a[2]), "r"(a[3]), "r"(b0), "r"(b1));
}

__device__ __forceinline__ void mma_tf32(float& d0, float& d1, float& d2, float& d3,
                                         uint32_t a0, uint32_t a1, uint32_t a2, uint32_t a3,
                                         uint32_t b0, uint32_t b1)
{
    asm volatile(
        "mma.sync.aligned.m16n8k8.row.col.f32.tf32.tf32.f32 "
        "{%0,%1,%2,%3}, {%4,%5,%6,%7}, {%8,%9}, {%0,%1,%2,%3};"
        : "+f"(d0), "+f"(d1), "+f"(d2), "+f"(d3)
        : "r"(a0), "r"(a1), "r"(a2), "r"(a3), "r"(b0), "r"(b1));
}

#define LDM4(r, addr)                                                        \
    asm volatile("ldmatrix.sync.aligned.m8n8.x4.shared.b16 {%0,%1,%2,%3}, [%4];" \
                 : "=r"((r)[0]), "=r"((r)[1]), "=r"((r)[2]), "=r"((r)[3])    \
                 : "r"(addr))

#define CP16(saddr, gptr)                                                    \
    asm volatile("cp.async.cg.shared.global [%0], [%1], 16;" :: "r"(saddr), "l"(gptr))

// ---------------------------------------------------------------------------
// split kernels (one-time prep)
// ---------------------------------------------------------------------------
__global__ void split_plain(const float* __restrict__ src,
                            __nv_bfloat16* __restrict__ hi,
                            __nv_bfloat16* __restrict__ lo)
{
    int i = blockIdx.x * blockDim.x + threadIdx.x;   // over n/4
    float4 v = ((const float4*)src)[i];
    __nv_bfloat16 h0, h1, h2, h3, l0, l1, l2, l3;
    split1(v.x, h0, l0); split1(v.y, h1, l1);
    split1(v.z, h2, l2); split1(v.w, h3, l3);
    ((__nv_bfloat162*)hi)[2 * i]     = __halves2bfloat162(h0, h1);
    ((__nv_bfloat162*)hi)[2 * i + 1] = __halves2bfloat162(h2, h3);
    ((__nv_bfloat162*)lo)[2 * i]     = __halves2bfloat162(l0, l1);
    ((__nv_bfloat162*)lo)[2 * i + 1] = __halves2bfloat162(l2, l3);
}

// W [K,N] f32  ->  hiT/loT [N,K] bf16
__global__ __launch_bounds__(256) void split_T(
    const float* __restrict__ W,
    __nv_bfloat16* __restrict__ hiT, __nv_bfloat16* __restrict__ loT,
    int K, int N)
{
    __shared__ float t[32][33];
    int n0 = blockIdx.x * 32, k0 = blockIdx.y * 32;
    int c = threadIdx.x & 31, r0 = threadIdx.x >> 5;
    #pragma unroll
    for (int j = 0; j < 4; j++) {
        int r = r0 + j * 8;
        t[r][c] = W[(size_t)(k0 + r) * N + n0 + c];
    }
    __syncthreads();
    #pragma unroll
    for (int j = 0; j < 4; j++) {
        int r = r0 + j * 8;
        float v = t[c][r];                  // = W[k0+c][n0+r]
        __nv_bfloat16 h, l;
        split1(v, h, l);
        hiT[(size_t)(n0 + r) * K + k0 + c] = h;
        loT[(size_t)(n0 + r) * K + k0 + c] = l;
    }
}

// ---------------------------------------------------------------------------
// bf16x3 3-stage pipelined GEMM: C[M,N] = A @ B^T (+bias)
// A planes [M][K], B planes [N][K] bf16. Block 128x128, k-tile 32, 3 stages.
// XOR-swizzled 64B rows: conflict-free ldmatrix + cp.async, zero padding.
// ---------------------------------------------------------------------------
#define GPLANE 8192            // 128 rows * 64 B
#define GSTG   32768           // 4 planes

__global__ void __launch_bounds__(256, 2) gemm_bf3(
    const __nv_bfloat16* __restrict__ Ah, const __nv_bfloat16* __restrict__ Al,
    const __nv_bfloat16* __restrict__ Bh, const __nv_bfloat16* __restrict__ Bl,
    float* __restrict__ C, const float* __restrict__ bias,
    int M, int N, int K)
{
    extern __shared__ __align__(16) char smg[];
    const uint32_t sbase = (uint32_t)__cvta_generic_to_shared(smg);

    const int tid  = threadIdx.x;
    const int warp = tid >> 5, lane = tid & 31;
    const int gID  = lane >> 2, tig = lane & 3;
    const int bm = blockIdx.y * 128;
    const int bn = blockIdx.x * 128;
    const int m0 = (warp >> 1) * 32;
    const int n0 = (warp & 1) * 64;

    const int lp   = tid >> 6;
    const int lid0 = tid & 63;
    const __nv_bfloat16* gplane =
        lp == 0 ? Ah + (size_t)bm * K :
        lp == 1 ? Al + (size_t)bm * K :
        lp == 2 ? Bh + (size_t)bn * K :
                  Bl + (size_t)bn * K;
    int      lsrc[8];
    uint32_t ldst[8];
    #pragma unroll
    for (int j = 0; j < 8; j++) {
        int id = lid0 + j * 64;
        int r = id >> 2, g = id & 3;
        lsrc[j] = r * K + g * 8;
        ldst[j] = (uint32_t)(lp * GPLANE + r * 64 + ((g ^ ((r >> 1) & 3)) << 4));
    }
#define GLOAD(st, k0)                                                          \
    do { for (int j_ = 0; j_ < 8; j_++)                                        \
             CP16(sbase + (uint32_t)(st) * GSTG + ldst[j_], gplane + lsrc[j_] + (k0)); \
    } while (0)

    uint32_t aoff[2]; int aswz[2];
    #pragma unroll
    for (int mi = 0; mi < 2; mi++) {
        int r = m0 + mi * 16 + (lane & 15);
        aoff[mi] = (uint32_t)(r * 64);
        aswz[mi] = (r >> 1) & 3;
    }
    const int ghA = lane >> 4;
    uint32_t boff[4]; int bswz[4];
    const int permB = ((lane >> 4) << 3) + (lane & 7);
    const int gbB = (lane >> 3) & 1;
    #pragma unroll
    for (int ntp = 0; ntp < 4; ntp++) {
        int r = n0 + ntp * 16 + permB;
        boff[ntp] = (uint32_t)(r * 64);
        bswz[ntp] = (r >> 1) & 3;
    }

    float acc[2][8][4];
    #pragma unroll
    for (int mi = 0; mi < 2; mi++)
        #pragma unroll
        for (int nt = 0; nt < 8; nt++)
            #pragma unroll
            for (int c = 0; c < 4; c++) acc[mi][nt][c] = 0.f;

    const int NIT = K >> 5;

    GLOAD(0, 0);
    asm volatile("cp.async.commit_group;");
    GLOAD(1, 32);
    asm volatile("cp.async.commit_group;");

    int cur = 0;
    #pragma unroll 1
    for (int it = 0; it < NIT; it++) {
        asm volatile("cp.async.wait_group 1;");
        __syncthreads();
        int nxt = cur + 2; if (nxt >= 3) nxt -= 3;
        if (it + 2 < NIT) GLOAD(nxt, (it + 2) * 32);
        asm volatile("cp.async.commit_group;");

        const uint32_t stb = sbase + (uint32_t)cur * GSTG;
        #pragma unroll
        for (int s = 0; s < 2; s++) {
            uint32_t af[2][2][4];
            #pragma unroll
            for (int mi = 0; mi < 2; mi++) {
                uint32_t ra = stb + aoff[mi] + (uint32_t)((((s << 1) + ghA) ^ aswz[mi]) << 4);
                LDM4(af[mi][0], ra);
                LDM4(af[mi][1], ra + GPLANE);
            }
            #pragma unroll
            for (int ntp = 0; ntp < 4; ntp++) {
                uint32_t rb = stb + 2 * GPLANE + boff[ntp]
                              + (uint32_t)((((s << 1) + gbB) ^ bswz[ntp]) << 4);
                uint32_t bh4[4], bl4[4];
                LDM4(bh4, rb);
                LDM4(bl4, rb + GPLANE);
                #pragma unroll
                for (int mi = 0; mi < 2; mi++) {
                    mma_bf16(acc[mi][2 * ntp],     af[mi][0], bh4[0], bh4[1]);
                    mma_bf16(acc[mi][2 * ntp],     af[mi][0], bl4[0], bl4[1]);
                    mma_bf16(acc[mi][2 * ntp],     af[mi][1], bh4[0], bh4[1]);
                    mma_bf16(acc[mi][2 * ntp + 1], af[mi][0], bh4[2], bh4[3]);
                    mma_bf16(acc[mi][2 * ntp + 1], af[mi][0], bl4[2], bl4[3]);
                    mma_bf16(acc[mi][2 * ntp + 1], af[mi][1], bh4[2], bh4[3]);
                }
            }
        }
        cur = cur + 1; if (cur == 3) cur = 0;
    }

    #pragma unroll
    for (int mi = 0; mi < 2; mi++) {
        int row = bm + m0 + mi * 16 + gID;
        #pragma unroll
        for (int nt = 0; nt < 8; nt++) {
            int col = bn + n0 + nt * 8 + 2 * tig;
            float b0 = bias ? bias[col] : 0.f;
            float b1 = bias ? bias[col + 1] : 0.f;
            float2 w0; w0.x = acc[mi][nt][0] + b0; w0.y = acc[mi][nt][1] + b1;
            float2 w1; w1.x = acc[mi][nt][2] + b0; w1.y = acc[mi][nt][3] + b1;
            *(float2*)&C[(size_t)row * N + col] = w0;
            *(float2*)&C[(size_t)(row + 8) * N + col] = w1;
        }
    }
#undef GLOAD
}

// ---------------------------------------------------------------------------
// RoPE + split into per-head [B,H,N,d] Q/K/V — outputs tf32-rounded fp32.
// ---------------------------------------------------------------------------
__global__ void rope_split(const float* __restrict__ qkv,
                           float* __restrict__ Q, float* __restrict__ Kt,
                           float* __restrict__ Vt)
{
    int idx = blockIdx.x * blockDim.x + threadIdx.x;
    int i = idx & 31;
    int n = (idx >> 5) & (NN - 1);
    int h = (idx >> 16) & (Hh - 1);
    int b = idx >> 20;

    float inv_freq = powf(10000.f, -(float)i / 32.f);
    float fr = (float)n * inv_freq;
    float c = cosf(fr), s = sinf(fr);

    size_t base = ((size_t)b * NN + n) * (3 * CC) + h * DD;
    float q1 = qkv[base + i],          q2 = qkv[base + i + 32];
    float k1 = qkv[base + CC + i],     k2 = qkv[base + CC + i + 32];
    float v1 = qkv[base + 2 * CC + i], v2 = qkv[base + 2 * CC + i + 32];

    size_t ob = ((size_t)(b * Hh + h) * NN + n) * DD;
    Q[ob + i]       = __uint_as_float(f2tf(q1 * c - q2 * s));
    Q[ob + i + 32]  = __uint_as_float(f2tf(q1 * s + q2 * c));
    Kt[ob + i]      = __uint_as_float(f2tf(k1 * c - k2 * s));
    Kt[ob + i + 32] = __uint_as_float(f2tf(k1 * s + k2 * c));
    Vt[ob + i]      = __uint_as_float(f2tf(v1));
    Vt[ob + i + 32] = __uint_as_float(f2tf(v2));
}

// ---------------------------------------------------------------------------
// Flash attention, tf32 mma, 2-stage cp.async KV pipeline.
// 256 threads = 8 warps; Q tile 128 rows/CTA (16 per warp), KV tiles 64.
// Inputs pre-rounded tf32 -> zero conversion in hot loop.
// ---------------------------------------------------------------------------
#define KSTR 68
#define VSTR 72
#define KSB  17408             // 64 * 68 * 4
#define VSB  18432             // 64 * 72 * 4

__global__ void __launch_bounds__(256, 2) flash_mma(
    const float* __restrict__ Q, const float* __restrict__ K,
    const float* __restrict__ V,
    __nv_bfloat16* __restrict__ Oh, __nv_bfloat16* __restrict__ Ol)
{
    extern __shared__ __align__(16) char sma[];
    const uint32_t sb = (uint32_t)__cvta_generic_to_shared(sma);

    const int bh = blockIdx.x;
    const int b = bh >> 4, h = bh & 15;
    const int tid = threadIdx.x;
    const int warp = tid >> 5, lane = tid & 31;
    const int gID = lane >> 2, tig = lane & 3;
    const int qbase = blockIdx.y * 128;
    const float scale = 0.125f;

    // ---- stage full 128-row Q tile across the two K stage regions (32KB) ----
    {
        const float* qg = Q + ((size_t)bh * NN + qbase) * DD;
        uint32_t* Qs = (uint32_t*)sma;
        #pragma unroll
        for (int it = 0; it < 8; it++) {
            int r = (tid >> 4) + it * 16;
            int c = (tid & 15) * 4;
            float4 v = *(const float4*)&qg[r * DD + c];
            uint32_t* dst = &Qs[r * KSTR + c];
            dst[0] = __float_as_uint(v.x); dst[1] = __float_as_uint(v.y);
            dst[2] = __float_as_uint(v.z); dst[3] = __float_as_uint(v.w);
        }
    }
    __syncthreads();

    uint32_t aQ[8][4];
    {
        const uint32_t* Qs = (const uint32_t*)sma;
        int r0 = warp * 16 + gID;
        #pragma unroll
        for (int s = 0; s < 8; s++) {
            aQ[s][0] = Qs[r0 * KSTR + s * 8 + tig];
            aQ[s][1] = Qs[(r0 + 8) * KSTR + s * 8 + tig];
            aQ[s][2] = Qs[r0 * KSTR + s * 8 + tig + 4];
            aQ[s][3] = Qs[(r0 + 8) * KSTR + s * 8 + tig + 4];
        }
    }
    __syncthreads();

    // ---- KV cp.async loader (256 threads -> 4 granules each per tile) ----
    const float* kbase = K + (size_t)bh * NN * DD;
    const float* vbase = V + (size_t)bh * NN * DD;
    int      asrc[4];
    uint32_t kdst[4], vdst[4];
    #pragma unroll
    for (int j = 0; j < 4; j++) {
        int id = tid + j * 256;
        int r = id >> 4, g = id & 15;
        asrc[j] = r * DD + g * 4;
        kdst[j] = (uint32_t)(r * 272 + g * 16);
        vdst[j] = (uint32_t)(2 * KSB + r * 288 + g * 16);
    }
#define KVLOAD(st, row0)                                                       \
    do { for (int j_ = 0; j_ < 4; j_++) {                                      \
             CP16(sb + (uint32_t)(st) * KSB + kdst[j_],                        \
                  kbase + (size_t)(row0) * DD + asrc[j_]);                     \
             CP16(sb + (uint32_t)(st) * VSB + vdst[j_],                        \
                  vbase + (size_t)(row0) * DD + asrc[j_]);                     \
         } } while (0)

    float of[8][4];
    #pragma unroll
    for (int i = 0; i < 8; i++)
        #pragma unroll
        for (int c = 0; c < 4; c++) of[i][c] = 0.f;
    float m0 = -1e30f, m1 = -1e30f, l0 = 0.f, l1 = 0.f;

    KVLOAD(0, 0);
    asm volatile("cp.async.commit_group;");

    #pragma unroll 1
    for (int t = 0; t < 32; t++) {
        asm volatile("cp.async.wait_group 0;");
        __syncthreads();
        if (t + 1 < 32) KVLOAD((t + 1) & 1, (t + 1) * 64);
        asm volatile("cp.async.commit_group;");

        const uint32_t* Ks = (const uint32_t*)(sma + (t & 1) * KSB);
        const uint32_t* Vs = (const uint32_t*)(sma + 2 * KSB + (t & 1) * VSB);

        // ---- S = Q . K^T ----
        float sf[8][4];
        #pragma unroll
        for (int nt = 0; nt < 8; nt++)
            #pragma unroll
            for (int c = 0; c < 4; c++) sf[nt][c] = 0.f;

        #pragma unroll
        for (int s = 0; s < 8; s++) {
            #pragma unroll
            for (int nt = 0; nt < 8; nt++) {
                uint32_t b0 = Ks[(nt * 8 + gID) * KSTR + s * 8 + tig];
                uint32_t b1 = Ks[(nt * 8 + gID) * KSTR + s * 8 + tig + 4];
                mma_tf32(sf[nt][0], sf[nt][1], sf[nt][2], sf[nt][3],
                         aQ[s][0], aQ[s][1], aQ[s][2], aQ[s][3], b0, b1);
            }
        }

        // ---- online softmax ----
        float tmax0 = -1e30f, tmax1 = -1e30f;
        #pragma unroll
        for (int nt = 0; nt < 8; nt++) {
            sf[nt][0] *= scale; sf[nt][1] *= scale;
            sf[nt][2] *= scale; sf[nt][3] *= scale;
            tmax0 = fmaxf(tmax0, fmaxf(sf[nt][0], sf[nt][1]));
            tmax1 = fmaxf(tmax1, fmaxf(sf[nt][2], sf[nt][3]));
        }
        tmax0 = fmaxf(tmax0, __shfl_xor_sync(0xffffffffu, tmax0, 1));
        tmax0 = fmaxf(tmax0, __shfl_xor_sync(0xffffffffu, tmax0, 2));
        tmax1 = fmaxf(tmax1, __shfl_xor_sync(0xffffffffu, tmax1, 1));
        tmax1 = fmaxf(tmax1, __shfl_xor_sync(0xffffffffu, tmax1, 2));

        float mn0 = fmaxf(m0, tmax0);
        float mn1 = fmaxf(m1, tmax1);
        float al0 = __expf(m0 - mn0);
        float al1 = __expf(m1 - mn1);
        m0 = mn0; m1 = mn1;
        l0 *= al0; l1 *= al1;
        #pragma unroll
        for (int i = 0; i < 8; i++) {
            of[i][0] *= al0; of[i][1] *= al0;
            of[i][2] *= al1; of[i][3] *= al1;
        }
        #pragma unroll
        for (int nt = 0; nt < 8; nt++) {
            sf[nt][0] = __expf(sf[nt][0] - mn0);
            sf[nt][1] = __expf(sf[nt][1] - mn0);
            sf[nt][2] = __expf(sf[nt][2] - mn1);
            sf[nt][3] = __expf(sf[nt][3] - mn1);
            l0 += sf[nt][0] + sf[nt][1];
            l1 += sf[nt][2] + sf[nt][3];
        }

        // ---- O += P . V ----
        #pragma unroll
        for (int j = 0; j < 8; j++) {
            int srcA = (lane & ~3) | (tig >> 1);
            float x0 = __shfl_sync(0xffffffffu, sf[j][0], srcA);
            float x1 = __shfl_sync(0xffffffffu, sf[j][1], srcA);
            float y0 = __shfl_sync(0xffffffffu, sf[j][2], srcA);
            float y1 = __shfl_sync(0xffffffffu, sf[j][3], srcA);
            float x2 = __shfl_sync(0xffffffffu, sf[j][0], srcA + 2);
            float x3 = __shfl_sync(0xffffffffu, sf[j][1], srcA + 2);
            float y2 = __shfl_sync(0xffffffffu, sf[j][2], srcA + 2);
            float y3 = __shfl_sync(0xffffffffu, sf[j][3], srcA + 2);
            uint32_t a0 = __float_as_uint((tig & 1) ? x1 : x0);
            uint32_t a1 = __float_as_uint((tig & 1) ? y1 : y0);
            uint32_t a2 = __float_as_uint((tig & 1) ? x3 : x2);
            uint32_t a3 = __float_as_uint((tig & 1) ? y3 : y2);
            #pragma unroll
            for (int i = 0; i < 8; i++) {
                uint32_t b0 = Vs[(j * 8 + tig) * VSTR + i * 8 + gID];
                uint32_t b1 = Vs[(j * 8 + tig + 4) * VSTR + i * 8 + gID];
                mma_tf32(of[i][0], of[i][1], of[i][2], of[i][3],
                         a0, a1, a2, a3, b0, b1);
            }
        }
    }

    l0 += __shfl_xor_sync(0xffffffffu, l0, 1);
    l0 += __shfl_xor_sync(0xffffffffu, l0, 2);
    l1 += __shfl_xor_sync(0xffffffffu, l1, 1);
    l1 += __shfl_xor_sync(0xffffffffu, l1, 2);
    float inv0 = 1.f / l0;
    float inv1 = 1.f / l1;

    int r0 = qbase + warp * 16 + gID;
    int r1 = r0 + 8;
    size_t base0 = ((size_t)b * NN + r0) * CC + h * DD;
    size_t base1 = ((size_t)b * NN + r1) * CC + h * DD;
    #pragma unroll
    for (int i = 0; i < 8; i++) {
        int col = i * 8 + 2 * tig;
        float v00 = of[i][0] * inv0, v01 = of[i][1] * inv0;
        float v10 = of[i][2] * inv1, v11 = of[i][3] * inv1;
        __nv_bfloat16 h00, h01, h10, h11, l00x, l01x, l10x, l11x;
        split1(v00, h00, l00x); split1(v01, h01, l01x);
        split1(v10, h10, l10x); split1(v11, h11, l11x);
        *(__nv_bfloat162*)&Oh[base0 + col] = __halves2bfloat162(h00, h01);
        *(__nv_bfloat162*)&Ol[base0 + col] = __halves2bfloat162(l00x, l01x);
        *(__nv_bfloat162*)&Oh[base1 + col] = __halves2bfloat162(h10, h11);
        *(__nv_bfloat162*)&Ol[base1 + col] = __halves2bfloat162(l10x, l11x);
    }
#undef KVLOAD
}

// ---------------------------------------------------------------------------
extern "C" void kernel_launch(void* const* d_in, const int* in_sizes, int n_in,
                              void* d_out, int out_size)
{
    const float* x      = (const float*)d_in[0];
    const float* w_qkv  = (const float*)d_in[1];
    const float* w_proj = (const float*)d_in[2];
    const float* b_proj = (const float*)d_in[3];
    float* out = (float*)d_out;

    float *qkv, *q, *k, *v;
    cudaGetSymbolAddress((void**)&qkv, g_qkv);
    cudaGetSymbolAddress((void**)&q,   g_q);
    cudaGetSymbolAddress((void**)&k,   g_k);
    cudaGetSymbolAddress((void**)&v,   g_v);
    __nv_bfloat16 *xh, *xl, *wqh, *wql, *wph, *wpl, *ath, *atl;
    cudaGetSymbolAddress((void**)&xh,  g_xh);
    cudaGetSymbolAddress((void**)&xl,  g_xl);
    cudaGetSymbolAddress((void**)&wqh, g_wqh);
    cudaGetSymbolAddress((void**)&wql, g_wql);
    cudaGetSymbolAddress((void**)&wph, g_wph);
    cudaGetSymbolAddress((void**)&wpl, g_wpl);
    cudaGetSymbolAddress((void**)&ath, g_atth);
    cudaGetSymbolAddress((void**)&atl, g_attl);

    static int attr_done = 0;
    if (!attr_done) {
        cudaFuncSetAttribute(gemm_bf3, cudaFuncAttributeMaxDynamicSharedMemorySize,
                             3 * GSTG);
        cudaFuncSetAttribute(flash_mma, cudaFuncAttributeMaxDynamicSharedMemorySize,
                             2 * KSB + 2 * VSB);
        attr_done = 1;
    }

    // 0) one-time splits
    split_plain<<<(MM_ * CC / 4) / 256, 256>>>(x, xh, xl);
    split_T<<<dim3(3 * CC / 32, CC / 32), 256>>>(w_qkv, wqh, wql, CC, 3 * CC);
    split_T<<<dim3(CC / 32, CC / 32), 256>>>(w_proj, wph, wpl, CC, CC);

    // 1) QKV GEMM: [4096, 3072] (bf16x3, 3-stage pipeline)
    gemm_bf3<<<dim3(3 * CC / 128, MM_ / 128), 256, 3 * GSTG>>>(
        xh, xl, wqh, wql, qkv, nullptr, MM_, 3 * CC, CC);

    // 2) RoPE + head split (tf32-rounded outputs)
    rope_split<<<(Bb * Hh * NN * 32) / 256, 256>>>(qkv, q, k, v);

    // 3) Attention (tf32 tensor cores, pipelined KV, 128-row Q tiles)
    flash_mma<<<dim3(Bb * Hh, NN / 128), 256, 2 * KSB + 2 * VSB>>>(q, k, v, ath, atl);

    // 4) Projection GEMM + bias
    gemm_bf3<<<dim3(CC / 128, MM_ / 128), 256, 3 * GSTG>>>(
        ath, atl, wph, wpl, out, b_proj, MM_, CC, CC);
}

// round 8
// speedup vs baseline: 5.0556x; 1.3668x over previous
#include <cuda_runtime.h>
#include <cuda_bf16.h>
#include <cuda_fp16.h>
#include <math.h>
#include <stdint.h>

// Problem shape (fixed)
#define Bb 2
#define Hh 16
#define NN 2048
#define CC 1024
#define DD 64
#define MM_ (Bb * NN)        // 4096 rows

// Scratch (device globals — no allocation allowed)
__device__ float g_qkv[(size_t)Bb * NN * 3 * CC];   // [B*N, 3C]
__device__ __align__(16) __half g_qh[(size_t)Bb * Hh * NN * DD];  // fp16, scale-folded
__device__ __align__(16) __half g_kh[(size_t)Bb * Hh * NN * DD];
__device__ __align__(16) __half g_vh[(size_t)Bb * Hh * NN * DD];

// bf16 hi/lo planes
__device__ __align__(16) __nv_bfloat16 g_xh[(size_t)MM_ * CC];
__device__ __align__(16) __nv_bfloat16 g_xl[(size_t)MM_ * CC];
__device__ __align__(16) __nv_bfloat16 g_wqh[(size_t)3 * CC * CC];  // [3072][1024] (transposed)
__device__ __align__(16) __nv_bfloat16 g_wql[(size_t)3 * CC * CC];
__device__ __align__(16) __nv_bfloat16 g_wph[(size_t)CC * CC];      // [1024][1024] (transposed)
__device__ __align__(16) __nv_bfloat16 g_wpl[(size_t)CC * CC];
__device__ __align__(16) __nv_bfloat16 g_atth[(size_t)MM_ * CC];
__device__ __align__(16) __nv_bfloat16 g_attl[(size_t)MM_ * CC];

// ---------------------------------------------------------------------------
// helpers
// ---------------------------------------------------------------------------
__device__ __forceinline__ void split1(float v, __nv_bfloat16& h, __nv_bfloat16& l) {
    h = __float2bfloat16_rn(v);
    l = __float2bfloat16_rn(v - __bfloat162float(h));
}

__device__ __forceinline__ void mma_bf16(float* d,
                                         const uint32_t* a, uint32_t b0, uint32_t b1)
{
    asm volatile(
        "mma.sync.aligned.m16n8k16.row.col.f32.bf16.bf16.f32 "
        "{%0,%1,%2,%3}, {%4,%5,%6,%7}, {%8,%9}, {%0,%1,%2,%3};"
        : "+f"(d[0]), "+f"(d[1]), "+f"(d[2]), "+f"(d[3])
        : "r"(a[0]), "r"(a[1]), "r"(a[2]), "r"(a[3]), "r"(b0), "r"(b1));
}

__device__ __forceinline__ void mma_f16(float* d,
                                        uint32_t a0, uint32_t a1, uint32_t a2, uint32_t a3,
                                        uint32_t b0, uint32_t b1)
{
    asm volatile(
        "mma.sync.aligned.m16n8k16.row.col.f32.f16.f16.f32 "
        "{%0,%1,%2,%3}, {%4,%5,%6,%7}, {%8,%9}, {%0,%1,%2,%3};"
        : "+f"(d[0]), "+f"(d[1]), "+f"(d[2]), "+f"(d[3])
        : "r"(a0), "r"(a1), "r"(a2), "r"(a3), "r"(b0), "r"(b1));
}

#define LDM4(r, addr)                                                        \
    asm volatile("ldmatrix.sync.aligned.m8n8.x4.shared.b16 {%0,%1,%2,%3}, [%4];" \
                 : "=r"((r)[0]), "=r"((r)[1]), "=r"((r)[2]), "=r"((r)[3])    \
                 : "r"(addr))

#define LDM4T(r, addr)                                                       \
    asm volatile("ldmatrix.sync.aligned.m8n8.x4.trans.shared.b16 {%0,%1,%2,%3}, [%4];" \
                 : "=r"((r)[0]), "=r"((r)[1]), "=r"((r)[2]), "=r"((r)[3])    \
                 : "r"(addr))

#define CP16(saddr, gptr)                                                    \
    asm volatile("cp.async.cg.shared.global [%0], [%1], 16;" :: "r"(saddr), "l"(gptr))

__device__ __forceinline__ uint32_t packh2(float lo, float hi) {
    __half2 h = __floats2half2_rn(lo, hi);
    return *(uint32_t*)&h;
}

// ---------------------------------------------------------------------------
// split kernels (one-time prep)
// ---------------------------------------------------------------------------
__global__ void split_plain(const float* __restrict__ src,
                            __nv_bfloat16* __restrict__ hi,
                            __nv_bfloat16* __restrict__ lo)
{
    int i = blockIdx.x * blockDim.x + threadIdx.x;   // over n/4
    float4 v = ((const float4*)src)[i];
    __nv_bfloat16 h0, h1, h2, h3, l0, l1, l2, l3;
    split1(v.x, h0, l0); split1(v.y, h1, l1);
    split1(v.z, h2, l2); split1(v.w, h3, l3);
    ((__nv_bfloat162*)hi)[2 * i]     = __halves2bfloat162(h0, h1);
    ((__nv_bfloat162*)hi)[2 * i + 1] = __halves2bfloat162(h2, h3);
    ((__nv_bfloat162*)lo)[2 * i]     = __halves2bfloat162(l0, l1);
    ((__nv_bfloat162*)lo)[2 * i + 1] = __halves2bfloat162(l2, l3);
}

// W [K,N] f32  ->  hiT/loT [N,K] bf16
__global__ __launch_bounds__(256) void split_T(
    const float* __restrict__ W,
    __nv_bfloat16* __restrict__ hiT, __nv_bfloat16* __restrict__ loT,
    int K, int N)
{
    __shared__ float t[32][33];
    int n0 = blockIdx.x * 32, k0 = blockIdx.y * 32;
    int c = threadIdx.x & 31, r0 = threadIdx.x >> 5;
    #pragma unroll
    for (int j = 0; j < 4; j++) {
        int r = r0 + j * 8;
        t[r][c] = W[(size_t)(k0 + r) * N + n0 + c];
    }
    __syncthreads();
    #pragma unroll
    for (int j = 0; j < 4; j++) {
        int r = r0 + j * 8;
        float v = t[c][r];                  // = W[k0+c][n0+r]
        __nv_bfloat16 h, l;
        split1(v, h, l);
        hiT[(size_t)(n0 + r) * K + k0 + c] = h;
        loT[(size_t)(n0 + r) * K + k0 + c] = l;
    }
}

// ---------------------------------------------------------------------------
// bf16x3 3-stage pipelined GEMM: C[M,N] = A @ B^T (+bias)  (unchanged)
// ---------------------------------------------------------------------------
#define GPLANE 8192            // 128 rows * 64 B
#define GSTG   32768           // 4 planes

__global__ void __launch_bounds__(256, 2) gemm_bf3(
    const __nv_bfloat16* __restrict__ Ah, const __nv_bfloat16* __restrict__ Al,
    const __nv_bfloat16* __restrict__ Bh, const __nv_bfloat16* __restrict__ Bl,
    float* __restrict__ C, const float* __restrict__ bias,
    int M, int N, int K)
{
    extern __shared__ __align__(16) char smg[];
    const uint32_t sbase = (uint32_t)__cvta_generic_to_shared(smg);

    const int tid  = threadIdx.x;
    const int warp = tid >> 5, lane = tid & 31;
    const int gID  = lane >> 2, tig = lane & 3;
    const int bm = blockIdx.y * 128;
    const int bn = blockIdx.x * 128;
    const int m0 = (warp >> 1) * 32;
    const int n0 = (warp & 1) * 64;

    const int lp   = tid >> 6;
    const int lid0 = tid & 63;
    const __nv_bfloat16* gplane =
        lp == 0 ? Ah + (size_t)bm * K :
        lp == 1 ? Al + (size_t)bm * K :
        lp == 2 ? Bh + (size_t)bn * K :
                  Bl + (size_t)bn * K;
    int      lsrc[8];
    uint32_t ldst[8];
    #pragma unroll
    for (int j = 0; j < 8; j++) {
        int id = lid0 + j * 64;
        int r = id >> 2, g = id & 3;
        lsrc[j] = r * K + g * 8;
        ldst[j] = (uint32_t)(lp * GPLANE + r * 64 + ((g ^ ((r >> 1) & 3)) << 4));
    }
#define GLOAD(st, k0)                                                          \
    do { for (int j_ = 0; j_ < 8; j_++)                                        \
             CP16(sbase + (uint32_t)(st) * GSTG + ldst[j_], gplane + lsrc[j_] + (k0)); \
    } while (0)

    uint32_t aoff[2]; int aswz[2];
    #pragma unroll
    for (int mi = 0; mi < 2; mi++) {
        int r = m0 + mi * 16 + (lane & 15);
        aoff[mi] = (uint32_t)(r * 64);
        aswz[mi] = (r >> 1) & 3;
    }
    const int ghA = lane >> 4;
    uint32_t boff[4]; int bswz[4];
    const int permB = ((lane >> 4) << 3) + (lane & 7);
    const int gbB = (lane >> 3) & 1;
    #pragma unroll
    for (int ntp = 0; ntp < 4; ntp++) {
        int r = n0 + ntp * 16 + permB;
        boff[ntp] = (uint32_t)(r * 64);
        bswz[ntp] = (r >> 1) & 3;
    }

    float acc[2][8][4];
    #pragma unroll
    for (int mi = 0; mi < 2; mi++)
        #pragma unroll
        for (int nt = 0; nt < 8; nt++)
            #pragma unroll
            for (int c = 0; c < 4; c++) acc[mi][nt][c] = 0.f;

    const int NIT = K >> 5;

    GLOAD(0, 0);
    asm volatile("cp.async.commit_group;");
    GLOAD(1, 32);
    asm volatile("cp.async.commit_group;");

    int cur = 0;
    #pragma unroll 1
    for (int it = 0; it < NIT; it++) {
        asm volatile("cp.async.wait_group 1;");
        __syncthreads();
        int nxt = cur + 2; if (nxt >= 3) nxt -= 3;
        if (it + 2 < NIT) GLOAD(nxt, (it + 2) * 32);
        asm volatile("cp.async.commit_group;");

        const uint32_t stb = sbase + (uint32_t)cur * GSTG;
        #pragma unroll
        for (int s = 0; s < 2; s++) {
            uint32_t af[2][2][4];
            #pragma unroll
            for (int mi = 0; mi < 2; mi++) {
                uint32_t ra = stb + aoff[mi] + (uint32_t)((((s << 1) + ghA) ^ aswz[mi]) << 4);
                LDM4(af[mi][0], ra);
                LDM4(af[mi][1], ra + GPLANE);
            }
            #pragma unroll
            for (int ntp = 0; ntp < 4; ntp++) {
                uint32_t rb = stb + 2 * GPLANE + boff[ntp]
                              + (uint32_t)((((s << 1) + gbB) ^ bswz[ntp]) << 4);
                uint32_t bh4[4], bl4[4];
                LDM4(bh4, rb);
                LDM4(bl4, rb + GPLANE);
                #pragma unroll
                for (int mi = 0; mi < 2; mi++) {
                    mma_bf16(acc[mi][2 * ntp],     af[mi][0], bh4[0], bh4[1]);
                    mma_bf16(acc[mi][2 * ntp],     af[mi][0], bl4[0], bl4[1]);
                    mma_bf16(acc[mi][2 * ntp],     af[mi][1], bh4[0], bh4[1]);
                    mma_bf16(acc[mi][2 * ntp + 1], af[mi][0], bh4[2], bh4[3]);
                    mma_bf16(acc[mi][2 * ntp + 1], af[mi][0], bl4[2], bl4[3]);
                    mma_bf16(acc[mi][2 * ntp + 1], af[mi][1], bh4[2], bh4[3]);
                }
            }
        }
        cur = cur + 1; if (cur == 3) cur = 0;
    }

    #pragma unroll
    for (int mi = 0; mi < 2; mi++) {
        int row = bm + m0 + mi * 16 + gID;
        #pragma unroll
        for (int nt = 0; nt < 8; nt++) {
            int col = bn + n0 + nt * 8 + 2 * tig;
            float b0 = bias ? bias[col] : 0.f;
            float b1 = bias ? bias[col + 1] : 0.f;
            float2 w0; w0.x = acc[mi][nt][0] + b0; w0.y = acc[mi][nt][1] + b1;
            float2 w1; w1.x = acc[mi][nt][2] + b0; w1.y = acc[mi][nt][3] + b1;
            *(float2*)&C[(size_t)row * N + col] = w0;
            *(float2*)&C[(size_t)(row + 8) * N + col] = w1;
        }
    }
#undef GLOAD
}

// ---------------------------------------------------------------------------
// RoPE + split into per-head [B,H,N,d] fp16 Q/K/V. Scale folded into Q.
// ---------------------------------------------------------------------------
__global__ void rope_split(const float* __restrict__ qkv,
                           __half* __restrict__ Q, __half* __restrict__ Kt,
                           __half* __restrict__ Vt)
{
    int idx = blockIdx.x * blockDim.x + threadIdx.x;
    int i = idx & 31;
    int n = (idx >> 5) & (NN - 1);
    int h = (idx >> 16) & (Hh - 1);
    int b = idx >> 20;

    float inv_freq = powf(10000.f, -(float)i / 32.f);
    float fr = (float)n * inv_freq;
    float c = cosf(fr), s = sinf(fr);

    size_t base = ((size_t)b * NN + n) * (3 * CC) + h * DD;
    float q1 = qkv[base + i],          q2 = qkv[base + i + 32];
    float k1 = qkv[base + CC + i],     k2 = qkv[base + CC + i + 32];
    float v1 = qkv[base + 2 * CC + i], v2 = qkv[base + 2 * CC + i + 32];

    size_t ob = ((size_t)(b * Hh + h) * NN + n) * DD;
    Q[ob + i]       = __float2half_rn(0.125f * (q1 * c - q2 * s));
    Q[ob + i + 32]  = __float2half_rn(0.125f * (q1 * s + q2 * c));
    Kt[ob + i]      = __float2half_rn(k1 * c - k2 * s);
    Kt[ob + i + 32] = __float2half_rn(k1 * s + k2 * c);
    Vt[ob + i]      = __float2half_rn(v1);
    Vt[ob + i + 32] = __float2half_rn(v2);
}

// ---------------------------------------------------------------------------
// Flash attention, fp16 mma (m16n8k16), ldmatrix fragments, 2-stage KV pipe.
// 256 threads = 8 warps; Q tile 128 rows/CTA, KV tiles 64. Rows 128B, XOR swz.
// smem: K st0 [0,8K) K st1 [8K,16K) V st0 [16K,24K) V st1 [24K,32K)
// ---------------------------------------------------------------------------
#define FA_SMEM 32768

__global__ void __launch_bounds__(256, 2) flash_mma(
    const __half* __restrict__ Q, const __half* __restrict__ K,
    const __half* __restrict__ V,
    __nv_bfloat16* __restrict__ Oh, __nv_bfloat16* __restrict__ Ol)
{
    extern __shared__ __align__(16) char sma[];
    const uint32_t sb = (uint32_t)__cvta_generic_to_shared(sma);

    const int bh = blockIdx.x;
    const int b = bh >> 4, h = bh & 15;
    const int tid = threadIdx.x;
    const int warp = tid >> 5, lane = tid & 31;
    const int gID = lane >> 2, tig = lane & 3;
    const int qbase = blockIdx.y * 128;

    // ---- stage Q tile (128 rows x 128B = 16KB) into [0,16K), extract frags ----
    {
        const __half* qg = Q + ((size_t)bh * NN + qbase) * DD;
        #pragma unroll
        for (int j = 0; j < 4; j++) {
            int id = tid + j * 256;          // 0..1023
            int r = id >> 3, g = id & 7;
            CP16(sb + (uint32_t)(r * 128 + ((g ^ (r & 7)) << 4)), qg + r * DD + g * 8);
        }
        asm volatile("cp.async.commit_group;");
        asm volatile("cp.async.wait_group 0;");
        __syncthreads();
    }

    uint32_t aQ[4][4];
    {
        int qr = warp * 16 + (lane & 15);
        #pragma unroll
        for (int s = 0; s < 4; s++) {
            int gran = 2 * s + (lane >> 4);
            LDM4(aQ[s], sb + (uint32_t)(qr * 128 + ((gran ^ (qr & 7)) << 4)));
        }
    }
    __syncthreads();

    // ---- KV loader ----
    const __half* kbase = K + (size_t)bh * NN * DD;
    const __half* vbase = V + (size_t)bh * NN * DD;
#define KVLOAD(st, row0)                                                       \
    do { _Pragma("unroll")                                                     \
         for (int j_ = 0; j_ < 2; j_++) {                                      \
             int id_ = tid + j_ * 256;          /* 0..511 */                   \
             int r_ = id_ >> 3, g_ = id_ & 7;                                  \
             uint32_t sw_ = (uint32_t)(r_ * 128 + (((g_ ^ (r_ & 7))) << 4));   \
             CP16(sb + (uint32_t)(st) * 8192 + sw_,                            \
                  kbase + (size_t)(row0 + r_) * DD + g_ * 8);                  \
             CP16(sb + 16384u + (uint32_t)(st) * 8192 + sw_,                   \
                  vbase + (size_t)(row0 + r_) * DD + g_ * 8);                  \
         } } while (0)

    // fragment address components
    const int kr0  = lane & 7;
    const int gsel = (lane >> 3) & 1;
    const int sel  = lane >> 4;

    float of[8][4];
    #pragma unroll
    for (int i = 0; i < 8; i++)
        #pragma unroll
        for (int c = 0; c < 4; c++) of[i][c] = 0.f;
    float m0 = -1e30f, m1 = -1e30f, l0 = 0.f, l1 = 0.f;

    KVLOAD(0, 0);
    asm volatile("cp.async.commit_group;");

    #pragma unroll 1
    for (int t = 0; t < 32; t++) {
        asm volatile("cp.async.wait_group 0;");
        __syncthreads();
        if (t + 1 < 32) KVLOAD((t + 1) & 1, (t + 1) * 64);
        asm volatile("cp.async.commit_group;");

        const uint32_t Kst = sb + (uint32_t)((t & 1) * 8192);
        const uint32_t Vst = sb + 16384u + (uint32_t)((t & 1) * 8192);

        // ---- S = Q . K^T  (m16 x n64, 4 k16 steps) ----
        float sf[8][4];
        #pragma unroll
        for (int nt = 0; nt < 8; nt++)
            #pragma unroll
            for (int c = 0; c < 4; c++) sf[nt][c] = 0.f;

        #pragma unroll
        for (int s = 0; s < 4; s++) {
            int physg = (2 * s + gsel) ^ kr0;
            #pragma unroll
            for (int ip = 0; ip < 4; ip++) {
                int row = (2 * ip + sel) * 8 + kr0;
                uint32_t bb[4];
                LDM4(bb, Kst + (uint32_t)(row * 128 + (physg << 4)));
                mma_f16(sf[2 * ip],     aQ[s][0], aQ[s][1], aQ[s][2], aQ[s][3], bb[0], bb[1]);
                mma_f16(sf[2 * ip + 1], aQ[s][0], aQ[s][1], aQ[s][2], aQ[s][3], bb[2], bb[3]);
            }
        }

        // ---- online softmax (scale pre-folded into Q) ----
        float tmax0 = -1e30f, tmax1 = -1e30f;
        #pragma unroll
        for (int nt = 0; nt < 8; nt++) {
            tmax0 = fmaxf(tmax0, fmaxf(sf[nt][0], sf[nt][1]));
            tmax1 = fmaxf(tmax1, fmaxf(sf[nt][2], sf[nt][3]));
        }
        tmax0 = fmaxf(tmax0, __shfl_xor_sync(0xffffffffu, tmax0, 1));
        tmax0 = fmaxf(tmax0, __shfl_xor_sync(0xffffffffu, tmax0, 2));
        tmax1 = fmaxf(tmax1, __shfl_xor_sync(0xffffffffu, tmax1, 1));
        tmax1 = fmaxf(tmax1, __shfl_xor_sync(0xffffffffu, tmax1, 2));

        float mn0 = fmaxf(m0, tmax0);
        float mn1 = fmaxf(m1, tmax1);
        float al0 = __expf(m0 - mn0);
        float al1 = __expf(m1 - mn1);
        m0 = mn0; m1 = mn1;
        l0 *= al0; l1 *= al1;
        #pragma unroll
        for (int i = 0; i < 8; i++) {
            of[i][0] *= al0; of[i][1] *= al0;
            of[i][2] *= al1; of[i][3] *= al1;
        }
        #pragma unroll
        for (int nt = 0; nt < 8; nt++) {
            sf[nt][0] = __expf(sf[nt][0] - mn0);
            sf[nt][1] = __expf(sf[nt][1] - mn0);
            sf[nt][2] = __expf(sf[nt][2] - mn1);
            sf[nt][3] = __expf(sf[nt][3] - mn1);
            l0 += sf[nt][0] + sf[nt][1];
            l1 += sf[nt][2] + sf[nt][3];
        }

        // ---- O += P . V  (4 k16 steps over keys; A-frags by register pack) ----
        #pragma unroll
        for (int kk = 0; kk < 4; kk++) {
            uint32_t a0 = packh2(sf[2 * kk][0],     sf[2 * kk][1]);
            uint32_t a1 = packh2(sf[2 * kk][2],     sf[2 * kk][3]);
            uint32_t a2 = packh2(sf[2 * kk + 1][0], sf[2 * kk + 1][1]);
            uint32_t a3 = packh2(sf[2 * kk + 1][2], sf[2 * kk + 1][3]);
            int row = 16 * kk + kr0 + 8 * gsel;
            #pragma unroll
            for (int jp = 0; jp < 4; jp++) {
                int physg = (2 * jp + sel) ^ kr0;
                uint32_t bb[4];
                LDM4T(bb, Vst + (uint32_t)(row * 128 + (physg << 4)));
                mma_f16(of[2 * jp],     a0, a1, a2, a3, bb[0], bb[1]);
                mma_f16(of[2 * jp + 1], a0, a1, a2, a3, bb[2], bb[3]);
            }
        }
    }

    l0 += __shfl_xor_sync(0xffffffffu, l0, 1);
    l0 += __shfl_xor_sync(0xffffffffu, l0, 2);
    l1 += __shfl_xor_sync(0xffffffffu, l1, 1);
    l1 += __shfl_xor_sync(0xffffffffu, l1, 2);
    float inv0 = 1.f / l0;
    float inv1 = 1.f / l1;

    int r0 = qbase + warp * 16 + gID;
    int r1 = r0 + 8;
    size_t base0 = ((size_t)b * NN + r0) * CC + h * DD;
    size_t base1 = ((size_t)b * NN + r1) * CC + h * DD;
    #pragma unroll
    for (int i = 0; i < 8; i++) {
        int col = i * 8 + 2 * tig;
        float v00 = of[i][0] * inv0, v01 = of[i][1] * inv0;
        float v10 = of[i][2] * inv1, v11 = of[i][3] * inv1;
        __nv_bfloat16 h00, h01, h10, h11, l00x, l01x, l10x, l11x;
        split1(v00, h00, l00x); split1(v01, h01, l01x);
        split1(v10, h10, l10x); split1(v11, h11, l11x);
        *(__nv_bfloat162*)&Oh[base0 + col] = __halves2bfloat162(h00, h01);
        *(__nv_bfloat162*)&Ol[base0 + col] = __halves2bfloat162(l00x, l01x);
        *(__nv_bfloat162*)&Oh[base1 + col] = __halves2bfloat162(h10, h11);
        *(__nv_bfloat162*)&Ol[base1 + col] = __halves2bfloat162(l10x, l11x);
    }
#undef KVLOAD
}

// ---------------------------------------------------------------------------
extern "C" void kernel_launch(void* const* d_in, const int* in_sizes, int n_in,
                              void* d_out, int out_size)
{
    const float* x      = (const float*)d_in[0];
    const float* w_qkv  = (const float*)d_in[1];
    const float* w_proj = (const float*)d_in[2];
    const float* b_proj = (const float*)d_in[3];
    float* out = (float*)d_out;

    float* qkv;
    __half *qh, *kh, *vh;
    cudaGetSymbolAddress((void**)&qkv, g_qkv);
    cudaGetSymbolAddress((void**)&qh,  g_qh);
    cudaGetSymbolAddress((void**)&kh,  g_kh);
    cudaGetSymbolAddress((void**)&vh,  g_vh);
    __nv_bfloat16 *xh, *xl, *wqh, *wql, *wph, *wpl, *ath, *atl;
    cudaGetSymbolAddress((void**)&xh,  g_xh);
    cudaGetSymbolAddress((void**)&xl,  g_xl);
    cudaGetSymbolAddress((void**)&wqh, g_wqh);
    cudaGetSymbolAddress((void**)&wql, g_wql);
    cudaGetSymbolAddress((void**)&wph, g_wph);
    cudaGetSymbolAddress((void**)&wpl, g_wpl);
    cudaGetSymbolAddress((void**)&ath, g_atth);
    cudaGetSymbolAddress((void**)&atl, g_attl);

    static int attr_done = 0;
    if (!attr_done) {
        cudaFuncSetAttribute(gemm_bf3, cudaFuncAttributeMaxDynamicSharedMemorySize,
                             3 * GSTG);
        cudaFuncSetAttribute(flash_mma, cudaFuncAttributeMaxDynamicSharedMemorySize,
                             FA_SMEM);
        attr_done = 1;
    }

    // 0) one-time splits
    split_plain<<<(MM_ * CC / 4) / 256, 256>>>(x, xh, xl);
    split_T<<<dim3(3 * CC / 32, CC / 32), 256>>>(w_qkv, wqh, wql, CC, 3 * CC);
    split_T<<<dim3(CC / 32, CC / 32), 256>>>(w_proj, wph, wpl, CC, CC);

    // 1) QKV GEMM: [4096, 3072] (bf16x3, 3-stage pipeline)
    gemm_bf3<<<dim3(3 * CC / 128, MM_ / 128), 256, 3 * GSTG>>>(
        xh, xl, wqh, wql, qkv, nullptr, MM_, 3 * CC, CC);

    // 2) RoPE + head split (fp16 outputs, scale folded into Q)
    rope_split<<<(Bb * Hh * NN * 32) / 256, 256>>>(qkv, qh, kh, vh);

    // 3) Attention (fp16 tensor cores, pipelined KV, 128-row Q tiles)
    flash_mma<<<dim3(Bb * Hh, NN / 128), 256, FA_SMEM>>>(qh, kh, vh, ath, atl);

    // 4) Projection GEMM + bias
    gemm_bf3<<<dim3(CC / 128, MM_ / 128), 256, 3 * GSTG>>>(
        ath, atl, wph, wpl, out, b_proj, MM_, CC, CC);
}

// round 9
// speedup vs baseline: 6.4599x; 1.2778x over previous
#include <cuda_runtime.h>
#include <cuda_bf16.h>
#include <cuda_fp16.h>
#include <math.h>
#include <stdint.h>

// Problem shape (fixed)
#define Bb 2
#define Hh 16
#define NN 2048
#define CC 1024
#define DD 64
#define MM_ (Bb * NN)        // 4096 rows

// Scratch (device globals — no allocation allowed)
__device__ float g_qkv[(size_t)Bb * NN * 3 * CC];   // [B*N, 3C]
__device__ __align__(16) __half g_qh[(size_t)Bb * Hh * NN * DD];  // fp16, scale-folded
__device__ __align__(16) __half g_kh[(size_t)Bb * Hh * NN * DD];
__device__ __align__(16) __half g_vh[(size_t)Bb * Hh * NN * DD];

// fp16 activation planes + weight hi/lo planes
__device__ __align__(16) __half g_xa[(size_t)MM_ * CC];            // fp16(x)
__device__ __align__(16) __half g_wqh[(size_t)3 * CC * CC];        // [3072][1024] T, hi
__device__ __align__(16) __half g_wql[(size_t)3 * CC * CC];        // lo
__device__ __align__(16) __half g_wph[(size_t)CC * CC];            // [1024][1024] T, hi
__device__ __align__(16) __half g_wpl[(size_t)CC * CC];            // lo
__device__ __align__(16) __half g_att[(size_t)MM_ * CC];           // fp16(attention out)

// ---------------------------------------------------------------------------
// helpers
// ---------------------------------------------------------------------------
__device__ __forceinline__ void mma_f16(float* d,
                                        uint32_t a0, uint32_t a1, uint32_t a2, uint32_t a3,
                                        uint32_t b0, uint32_t b1)
{
    asm volatile(
        "mma.sync.aligned.m16n8k16.row.col.f32.f16.f16.f32 "
        "{%0,%1,%2,%3}, {%4,%5,%6,%7}, {%8,%9}, {%0,%1,%2,%3};"
        : "+f"(d[0]), "+f"(d[1]), "+f"(d[2]), "+f"(d[3])
        : "r"(a0), "r"(a1), "r"(a2), "r"(a3), "r"(b0), "r"(b1));
}

#define LDM4(r, addr)                                                        \
    asm volatile("ldmatrix.sync.aligned.m8n8.x4.shared.b16 {%0,%1,%2,%3}, [%4];" \
                 : "=r"((r)[0]), "=r"((r)[1]), "=r"((r)[2]), "=r"((r)[3])    \
                 : "r"(addr))

#define LDM4T(r, addr)                                                       \
    asm volatile("ldmatrix.sync.aligned.m8n8.x4.trans.shared.b16 {%0,%1,%2,%3}, [%4];" \
                 : "=r"((r)[0]), "=r"((r)[1]), "=r"((r)[2]), "=r"((r)[3])    \
                 : "r"(addr))

#define CP16(saddr, gptr)                                                    \
    asm volatile("cp.async.cg.shared.global [%0], [%1], 16;" :: "r"(saddr), "l"(gptr))

__device__ __forceinline__ uint32_t packh2(float lo, float hi) {
    __half2 h = __floats2half2_rn(lo, hi);
    return *(uint32_t*)&h;
}

// ---------------------------------------------------------------------------
// prep kernels
// ---------------------------------------------------------------------------
// x f32 -> fp16 (plain downconvert)
__global__ void conv_h(const float* __restrict__ src, __half* __restrict__ dst)
{
    int i = blockIdx.x * blockDim.x + threadIdx.x;   // over n/4
    float4 v = ((const float4*)src)[i];
    __half2 a = __floats2half2_rn(v.x, v.y);
    __half2 b = __floats2half2_rn(v.z, v.w);
    ((__half2*)dst)[2 * i]     = a;
    ((__half2*)dst)[2 * i + 1] = b;
}

// W [K,N] f32 -> hiT/loT [N,K] fp16 (hi = rn(w), lo = rn(w - hi))
__global__ __launch_bounds__(256) void split_T_h(
    const float* __restrict__ W,
    __half* __restrict__ hiT, __half* __restrict__ loT,
    int K, int N)
{
    __shared__ float t[32][33];
    int n0 = blockIdx.x * 32, k0 = blockIdx.y * 32;
    int c = threadIdx.x & 31, r0 = threadIdx.x >> 5;
    #pragma unroll
    for (int j = 0; j < 4; j++) {
        int r = r0 + j * 8;
        t[r][c] = W[(size_t)(k0 + r) * N + n0 + c];
    }
    __syncthreads();
    #pragma unroll
    for (int j = 0; j < 4; j++) {
        int r = r0 + j * 8;
        float v = t[c][r];                  // = W[k0+c][n0+r]
        __half h = __float2half_rn(v);
        __half l = __float2half_rn(v - __half2float(h));
        hiT[(size_t)(n0 + r) * K + k0 + c] = h;
        loT[(size_t)(n0 + r) * K + k0 + c] = l;
    }
}

// ---------------------------------------------------------------------------
// fp16x2 3-stage pipelined GEMM: C[M,N] = A @ (Bh+Bl)^T (+bias)
// A plane [M][K] fp16; B planes [N][K] fp16 hi/lo (pre-transposed).
// Block 128x128, k-tile 32, 3 stages; 64B rows, XOR swizzle, zero padding.
// ---------------------------------------------------------------------------
#define GPLANE 8192            // 128 rows * 64 B
#define GSTG   24576           // 3 planes
#define OFF_A  0
#define OFF_BH 8192
#define OFF_BL 16384

__global__ void __launch_bounds__(256, 2) gemm_f16x2(
    const __half* __restrict__ A,
    const __half* __restrict__ Bh, const __half* __restrict__ Bl,
    float* __restrict__ C, const float* __restrict__ bias,
    int M, int N, int K)
{
    extern __shared__ __align__(16) char smg[];
    const uint32_t sbase = (uint32_t)__cvta_generic_to_shared(smg);

    const int tid  = threadIdx.x;
    const int warp = tid >> 5, lane = tid & 31;
    const int gID  = lane >> 2, tig = lane & 3;
    const int bm = blockIdx.y * 128;
    const int bn = blockIdx.x * 128;
    const int m0 = (warp >> 1) * 32;
    const int n0 = (warp & 1) * 64;

    // loader: 6 granules (16B) per thread: 1536 granules = 3 planes x 512
    const __half* gsrc[6];
    uint32_t      gdst[6];
    #pragma unroll
    for (int j = 0; j < 6; j++) {
        int id = tid + j * 256;
        int pl = id >> 9;                  // 0=A, 1=Bh, 2=Bl
        int idx = id & 511;
        int r = idx >> 2, g = idx & 3;
        const __half* base =
            pl == 0 ? A  + (size_t)(bm + r) * K :
            pl == 1 ? Bh + (size_t)(bn + r) * K :
                      Bl + (size_t)(bn + r) * K;
        gsrc[j] = base + g * 8;
        gdst[j] = (uint32_t)(pl * GPLANE + r * 64 + ((g ^ ((r >> 1) & 3)) << 4));
    }
#define GLOAD(st, k0)                                                          \
    do { for (int j_ = 0; j_ < 6; j_++)                                        \
             CP16(sbase + (uint32_t)(st) * GSTG + gdst[j_], gsrc[j_] + (k0));  \
    } while (0)

    uint32_t aoff[2]; int aswz[2];
    #pragma unroll
    for (int mi = 0; mi < 2; mi++) {
        int r = m0 + mi * 16 + (lane & 15);
        aoff[mi] = (uint32_t)(r * 64);
        aswz[mi] = (r >> 1) & 3;
    }
    const int ghA = lane >> 4;
    uint32_t boff[4]; int bswz[4];
    const int permB = ((lane >> 4) << 3) + (lane & 7);
    const int gbB = (lane >> 3) & 1;
    #pragma unroll
    for (int ntp = 0; ntp < 4; ntp++) {
        int r = n0 + ntp * 16 + permB;
        boff[ntp] = (uint32_t)(r * 64);
        bswz[ntp] = (r >> 1) & 3;
    }

    float acc[2][8][4];
    #pragma unroll
    for (int mi = 0; mi < 2; mi++)
        #pragma unroll
        for (int nt = 0; nt < 8; nt++)
            #pragma unroll
            for (int c = 0; c < 4; c++) acc[mi][nt][c] = 0.f;

    const int NIT = K >> 5;

    GLOAD(0, 0);
    asm volatile("cp.async.commit_group;");
    GLOAD(1, 32);
    asm volatile("cp.async.commit_group;");

    int cur = 0;
    #pragma unroll 1
    for (int it = 0; it < NIT; it++) {
        asm volatile("cp.async.wait_group 1;");
        __syncthreads();
        int nxt = cur + 2; if (nxt >= 3) nxt -= 3;
        if (it + 2 < NIT) GLOAD(nxt, (it + 2) * 32);
        asm volatile("cp.async.commit_group;");

        const uint32_t stb = sbase + (uint32_t)cur * GSTG;
        #pragma unroll
        for (int s = 0; s < 2; s++) {
            uint32_t af[2][4];
            #pragma unroll
            for (int mi = 0; mi < 2; mi++) {
                uint32_t ra = stb + OFF_A + aoff[mi]
                              + (uint32_t)((((s << 1) + ghA) ^ aswz[mi]) << 4);
                LDM4(af[mi], ra);
            }
            #pragma unroll
            for (int ntp = 0; ntp < 4; ntp++) {
                uint32_t rb = stb + OFF_BH + boff[ntp]
                              + (uint32_t)((((s << 1) + gbB) ^ bswz[ntp]) << 4);
                uint32_t bh4[4], bl4[4];
                LDM4(bh4, rb);
                LDM4(bl4, rb + GPLANE);
                #pragma unroll
                for (int mi = 0; mi < 2; mi++) {
                    mma_f16(acc[mi][2 * ntp],
                            af[mi][0], af[mi][1], af[mi][2], af[mi][3], bh4[0], bh4[1]);
                    mma_f16(acc[mi][2 * ntp],
                            af[mi][0], af[mi][1], af[mi][2], af[mi][3], bl4[0], bl4[1]);
                    mma_f16(acc[mi][2 * ntp + 1],
                            af[mi][0], af[mi][1], af[mi][2], af[mi][3], bh4[2], bh4[3]);
                    mma_f16(acc[mi][2 * ntp + 1],
                            af[mi][0], af[mi][1], af[mi][2], af[mi][3], bl4[2], bl4[3]);
                }
            }
        }
        cur = cur + 1; if (cur == 3) cur = 0;
    }

    #pragma unroll
    for (int mi = 0; mi < 2; mi++) {
        int row = bm + m0 + mi * 16 + gID;
        #pragma unroll
        for (int nt = 0; nt < 8; nt++) {
            int col = bn + n0 + nt * 8 + 2 * tig;
            float b0 = bias ? bias[col] : 0.f;
            float b1 = bias ? bias[col + 1] : 0.f;
            float2 w0; w0.x = acc[mi][nt][0] + b0; w0.y = acc[mi][nt][1] + b1;
            float2 w1; w1.x = acc[mi][nt][2] + b0; w1.y = acc[mi][nt][3] + b1;
            *(float2*)&C[(size_t)row * N + col] = w0;
            *(float2*)&C[(size_t)(row + 8) * N + col] = w1;
        }
    }
#undef GLOAD
}

// ---------------------------------------------------------------------------
// RoPE + split into per-head [B,H,N,d] fp16 Q/K/V. Scale folded into Q.
// ---------------------------------------------------------------------------
__global__ void rope_split(const float* __restrict__ qkv,
                           __half* __restrict__ Q, __half* __restrict__ Kt,
                           __half* __restrict__ Vt)
{
    int idx = blockIdx.x * blockDim.x + threadIdx.x;
    int i = idx & 31;
    int n = (idx >> 5) & (NN - 1);
    int h = (idx >> 16) & (Hh - 1);
    int b = idx >> 20;

    float inv_freq = powf(10000.f, -(float)i / 32.f);
    float fr = (float)n * inv_freq;
    float c = cosf(fr), s = sinf(fr);

    size_t base = ((size_t)b * NN + n) * (3 * CC) + h * DD;
    float q1 = qkv[base + i],          q2 = qkv[base + i + 32];
    float k1 = qkv[base + CC + i],     k2 = qkv[base + CC + i + 32];
    float v1 = qkv[base + 2 * CC + i], v2 = qkv[base + 2 * CC + i + 32];

    size_t ob = ((size_t)(b * Hh + h) * NN + n) * DD;
    Q[ob + i]       = __float2half_rn(0.125f * (q1 * c - q2 * s));
    Q[ob + i + 32]  = __float2half_rn(0.125f * (q1 * s + q2 * c));
    Kt[ob + i]      = __float2half_rn(k1 * c - k2 * s);
    Kt[ob + i + 32] = __float2half_rn(k1 * s + k2 * c);
    Vt[ob + i]      = __float2half_rn(v1);
    Vt[ob + i + 32] = __float2half_rn(v2);
}

// ---------------------------------------------------------------------------
// Flash attention, fp16 mma (m16n8k16), ldmatrix fragments, 2-stage KV pipe.
// 256 threads = 8 warps; Q tile 128 rows/CTA, KV tiles 64. Rows 128B, XOR swz.
// smem: K st0 [0,8K) K st1 [8K,16K) V st0 [16K,24K) V st1 [24K,32K)
// ---------------------------------------------------------------------------
#define FA_SMEM 32768

__global__ void __launch_bounds__(256, 2) flash_mma(
    const __half* __restrict__ Q, const __half* __restrict__ K,
    const __half* __restrict__ V, __half* __restrict__ O)
{
    extern __shared__ __align__(16) char sma[];
    const uint32_t sb = (uint32_t)__cvta_generic_to_shared(sma);

    const int bh = blockIdx.x;
    const int b = bh >> 4, h = bh & 15;
    const int tid = threadIdx.x;
    const int warp = tid >> 5, lane = tid & 31;
    const int gID = lane >> 2, tig = lane & 3;
    const int qbase = blockIdx.y * 128;

    // ---- stage Q tile (128 rows x 128B = 16KB) into [0,16K), extract frags ----
    {
        const __half* qg = Q + ((size_t)bh * NN + qbase) * DD;
        #pragma unroll
        for (int j = 0; j < 4; j++) {
            int id = tid + j * 256;          // 0..1023
            int r = id >> 3, g = id & 7;
            CP16(sb + (uint32_t)(r * 128 + ((g ^ (r & 7)) << 4)), qg + r * DD + g * 8);
        }
        asm volatile("cp.async.commit_group;");
        asm volatile("cp.async.wait_group 0;");
        __syncthreads();
    }

    uint32_t aQ[4][4];
    {
        int qr = warp * 16 + (lane & 15);
        #pragma unroll
        for (int s = 0; s < 4; s++) {
            int gran = 2 * s + (lane >> 4);
            LDM4(aQ[s], sb + (uint32_t)(qr * 128 + ((gran ^ (qr & 7)) << 4)));
        }
    }
    __syncthreads();

    // ---- KV loader ----
    const __half* kbase = K + (size_t)bh * NN * DD;
    const __half* vbase = V + (size_t)bh * NN * DD;
#define KVLOAD(st, row0)                                                       \
    do { _Pragma("unroll")                                                     \
         for (int j_ = 0; j_ < 2; j_++) {                                      \
             int id_ = tid + j_ * 256;          /* 0..511 */                   \
             int r_ = id_ >> 3, g_ = id_ & 7;                                  \
             uint32_t sw_ = (uint32_t)(r_ * 128 + (((g_ ^ (r_ & 7))) << 4));   \
             CP16(sb + (uint32_t)(st) * 8192 + sw_,                            \
                  kbase + (size_t)(row0 + r_) * DD + g_ * 8);                  \
             CP16(sb + 16384u + (uint32_t)(st) * 8192 + sw_,                   \
                  vbase + (size_t)(row0 + r_) * DD + g_ * 8);                  \
         } } while (0)

    const int kr0  = lane & 7;
    const int gsel = (lane >> 3) & 1;
    const int sel  = lane >> 4;

    float of[8][4];
    #pragma unroll
    for (int i = 0; i < 8; i++)
        #pragma unroll
        for (int c = 0; c < 4; c++) of[i][c] = 0.f;
    float m0 = -1e30f, m1 = -1e30f, l0 = 0.f, l1 = 0.f;

    KVLOAD(0, 0);
    asm volatile("cp.async.commit_group;");

    #pragma unroll 1
    for (int t = 0; t < 32; t++) {
        asm volatile("cp.async.wait_group 0;");
        __syncthreads();
        if (t + 1 < 32) KVLOAD((t + 1) & 1, (t + 1) * 64);
        asm volatile("cp.async.commit_group;");

        const uint32_t Kst = sb + (uint32_t)((t & 1) * 8192);
        const uint32_t Vst = sb + 16384u + (uint32_t)((t & 1) * 8192);

        // ---- S = Q . K^T  (m16 x n64, 4 k16 steps) ----
        float sf[8][4];
        #pragma unroll
        for (int nt = 0; nt < 8; nt++)
            #pragma unroll
            for (int c = 0; c < 4; c++) sf[nt][c] = 0.f;

        #pragma unroll
        for (int s = 0; s < 4; s++) {
            int physg = (2 * s + gsel) ^ kr0;
            #pragma unroll
            for (int ip = 0; ip < 4; ip++) {
                int row = (2 * ip + sel) * 8 + kr0;
                uint32_t bb[4];
                LDM4(bb, Kst + (uint32_t)(row * 128 + (physg << 4)));
                mma_f16(sf[2 * ip],     aQ[s][0], aQ[s][1], aQ[s][2], aQ[s][3], bb[0], bb[1]);
                mma_f16(sf[2 * ip + 1], aQ[s][0], aQ[s][1], aQ[s][2], aQ[s][3], bb[2], bb[3]);
            }
        }

        // ---- online softmax (scale pre-folded into Q) ----
        float tmax0 = -1e30f, tmax1 = -1e30f;
        #pragma unroll
        for (int nt = 0; nt < 8; nt++) {
            tmax0 = fmaxf(tmax0, fmaxf(sf[nt][0], sf[nt][1]));
            tmax1 = fmaxf(tmax1, fmaxf(sf[nt][2], sf[nt][3]));
        }
        tmax0 = fmaxf(tmax0, __shfl_xor_sync(0xffffffffu, tmax0, 1));
        tmax0 = fmaxf(tmax0, __shfl_xor_sync(0xffffffffu, tmax0, 2));
        tmax1 = fmaxf(tmax1, __shfl_xor_sync(0xffffffffu, tmax1, 1));
        tmax1 = fmaxf(tmax1, __shfl_xor_sync(0xffffffffu, tmax1, 2));

        float mn0 = fmaxf(m0, tmax0);
        float mn1 = fmaxf(m1, tmax1);
        float al0 = __expf(m0 - mn0);
        float al1 = __expf(m1 - mn1);
        m0 = mn0; m1 = mn1;
        l0 *= al0; l1 *= al1;
        #pragma unroll
        for (int i = 0; i < 8; i++) {
            of[i][0] *= al0; of[i][1] *= al0;
            of[i][2] *= al1; of[i][3] *= al1;
        }
        #pragma unroll
        for (int nt = 0; nt < 8; nt++) {
            sf[nt][0] = __expf(sf[nt][0] - mn0);
            sf[nt][1] = __expf(sf[nt][1] - mn0);
            sf[nt][2] = __expf(sf[nt][2] - mn1);
            sf[nt][3] = __expf(sf[nt][3] - mn1);
            l0 += sf[nt][0] + sf[nt][1];
            l1 += sf[nt][2] + sf[nt][3];
        }

        // ---- O += P . V  (4 k16 steps over keys; A-frags by register pack) ----
        #pragma unroll
        for (int kk = 0; kk < 4; kk++) {
            uint32_t a0 = packh2(sf[2 * kk][0],     sf[2 * kk][1]);
            uint32_t a1 = packh2(sf[2 * kk][2],     sf[2 * kk][3]);
            uint32_t a2 = packh2(sf[2 * kk + 1][0], sf[2 * kk + 1][1]);
            uint32_t a3 = packh2(sf[2 * kk + 1][2], sf[2 * kk + 1][3]);
            int row = 16 * kk + kr0 + 8 * gsel;
            #pragma unroll
            for (int jp = 0; jp < 4; jp++) {
                int physg = (2 * jp + sel) ^ kr0;
                uint32_t bb[4];
                LDM4T(bb, Vst + (uint32_t)(row * 128 + (physg << 4)));
                mma_f16(of[2 * jp],     a0, a1, a2, a3, bb[0], bb[1]);
                mma_f16(of[2 * jp + 1], a0, a1, a2, a3, bb[2], bb[3]);
            }
        }
    }

    l0 += __shfl_xor_sync(0xffffffffu, l0, 1);
    l0 += __shfl_xor_sync(0xffffffffu, l0, 2);
    l1 += __shfl_xor_sync(0xffffffffu, l1, 1);
    l1 += __shfl_xor_sync(0xffffffffu, l1, 2);
    float inv0 = 1.f / l0;
    float inv1 = 1.f / l1;

    int r0 = qbase + warp * 16 + gID;
    int r1 = r0 + 8;
    size_t base0 = ((size_t)b * NN + r0) * CC + h * DD;
    size_t base1 = ((size_t)b * NN + r1) * CC + h * DD;
    #pragma unroll
    for (int i = 0; i < 8; i++) {
        int col = i * 8 + 2 * tig;
        *(__half2*)&O[base0 + col] = __floats2half2_rn(of[i][0] * inv0, of[i][1] * inv0);
        *(__half2*)&O[base1 + col] = __floats2half2_rn(of[i][2] * inv1, of[i][3] * inv1);
    }
#undef KVLOAD
}

// ---------------------------------------------------------------------------
extern "C" void kernel_launch(void* const* d_in, const int* in_sizes, int n_in,
                              void* d_out, int out_size)
{
    const float* x      = (const float*)d_in[0];
    const float* w_qkv  = (const float*)d_in[1];
    const float* w_proj = (const float*)d_in[2];
    const float* b_proj = (const float*)d_in[3];
    float* out = (float*)d_out;

    float* qkv;
    __half *qh, *kh, *vh, *xa, *wqh, *wql, *wph, *wpl, *att;
    cudaGetSymbolAddress((void**)&qkv, g_qkv);
    cudaGetSymbolAddress((void**)&qh,  g_qh);
    cudaGetSymbolAddress((void**)&kh,  g_kh);
    cudaGetSymbolAddress((void**)&vh,  g_vh);
    cudaGetSymbolAddress((void**)&xa,  g_xa);
    cudaGetSymbolAddress((void**)&wqh, g_wqh);
    cudaGetSymbolAddress((void**)&wql, g_wql);
    cudaGetSymbolAddress((void**)&wph, g_wph);
    cudaGetSymbolAddress((void**)&wpl, g_wpl);
    cudaGetSymbolAddress((void**)&att, g_att);

    static int attr_done = 0;
    if (!attr_done) {
        cudaFuncSetAttribute(gemm_f16x2, cudaFuncAttributeMaxDynamicSharedMemorySize,
                             3 * GSTG);
        cudaFuncSetAttribute(flash_mma, cudaFuncAttributeMaxDynamicSharedMemorySize,
                             FA_SMEM);
        attr_done = 1;
    }

    // 0) one-time prep
    conv_h<<<(MM_ * CC / 4) / 256, 256>>>(x, xa);
    split_T_h<<<dim3(3 * CC / 32, CC / 32), 256>>>(w_qkv, wqh, wql, CC, 3 * CC);
    split_T_h<<<dim3(CC / 32, CC / 32), 256>>>(w_proj, wph, wpl, CC, CC);

    // 1) QKV GEMM: [4096, 3072] (fp16x2, 3-stage pipeline)
    gemm_f16x2<<<dim3(3 * CC / 128, MM_ / 128), 256, 3 * GSTG>>>(
        xa, wqh, wql, qkv, nullptr, MM_, 3 * CC, CC);

    // 2) RoPE + head split (fp16 outputs, scale folded into Q)
    rope_split<<<(Bb * Hh * NN * 32) / 256, 256>>>(qkv, qh, kh, vh);

    // 3) Attention (fp16 tensor cores, pipelined KV, 128-row Q tiles)
    flash_mma<<<dim3(Bb * Hh, NN / 128), 256, FA_SMEM>>>(qh, kh, vh, att);

    // 4) Projection GEMM + bias (fp16x2)
    gemm_f16x2<<<dim3(CC / 128, MM_ / 128), 256, 3 * GSTG>>>(
        att, wph, wpl, out, b_proj, MM_, CC, CC);
}

// round 10
// speedup vs baseline: 8.3448x; 1.2918x over previous
#include <cuda_runtime.h>
#include <cuda_bf16.h>
#include <cuda_fp16.h>
#include <math.h>
#include <stdint.h>

// Problem shape (fixed)
#define Bb 2
#define Hh 16
#define NN 2048
#define CC 1024
#define DD 64
#define MM_ (Bb * NN)        // 4096 rows

// Scratch (device globals — no allocation allowed)
__device__ float g_qkv[(size_t)Bb * NN * 3 * CC];   // [B*N, 3C]
__device__ __align__(16) __half g_qh[(size_t)Bb * Hh * NN * DD];  // fp16, scale-folded
__device__ __align__(16) __half g_kh[(size_t)Bb * Hh * NN * DD];
__device__ __align__(16) __half g_vh[(size_t)Bb * Hh * NN * DD];

// fp16 activation + transposed weights
__device__ __align__(16) __half g_xa[(size_t)MM_ * CC];            // fp16(x)
__device__ __align__(16) __half g_wq[(size_t)3 * CC * CC];         // [3072][1024] T
__device__ __align__(16) __half g_wp[(size_t)CC * CC];             // [1024][1024] T
__device__ __align__(16) __half g_att[(size_t)MM_ * CC];           // fp16(attention out)

// ---------------------------------------------------------------------------
// helpers
// ---------------------------------------------------------------------------
__device__ __forceinline__ void mma_f16(float* d,
                                        uint32_t a0, uint32_t a1, uint32_t a2, uint32_t a3,
                                        uint32_t b0, uint32_t b1)
{
    asm volatile(
        "mma.sync.aligned.m16n8k16.row.col.f32.f16.f16.f32 "
        "{%0,%1,%2,%3}, {%4,%5,%6,%7}, {%8,%9}, {%0,%1,%2,%3};"
        : "+f"(d[0]), "+f"(d[1]), "+f"(d[2]), "+f"(d[3])
        : "r"(a0), "r"(a1), "r"(a2), "r"(a3), "r"(b0), "r"(b1));
}

#define LDM4(r, addr)                                                        \
    asm volatile("ldmatrix.sync.aligned.m8n8.x4.shared.b16 {%0,%1,%2,%3}, [%4];" \
                 : "=r"((r)[0]), "=r"((r)[1]), "=r"((r)[2]), "=r"((r)[3])    \
                 : "r"(addr))

#define LDM4T(r, addr)                                                       \
    asm volatile("ldmatrix.sync.aligned.m8n8.x4.trans.shared.b16 {%0,%1,%2,%3}, [%4];" \
                 : "=r"((r)[0]), "=r"((r)[1]), "=r"((r)[2]), "=r"((r)[3])    \
                 : "r"(addr))

#define CP16(saddr, gptr)                                                    \
    asm volatile("cp.async.cg.shared.global [%0], [%1], 16;" :: "r"(saddr), "l"(gptr))

__device__ __forceinline__ uint32_t packh2(float lo, float hi) {
    __half2 h = __floats2half2_rn(lo, hi);
    return *(uint32_t*)&h;
}

// ---------------------------------------------------------------------------
// prep kernels
// ---------------------------------------------------------------------------
// x f32 -> fp16 (plain downconvert)
__global__ void conv_h(const float* __restrict__ src, __half* __restrict__ dst)
{
    int i = blockIdx.x * blockDim.x + threadIdx.x;   // over n/4
    float4 v = ((const float4*)src)[i];
    ((__half2*)dst)[2 * i]     = __floats2half2_rn(v.x, v.y);
    ((__half2*)dst)[2 * i + 1] = __floats2half2_rn(v.z, v.w);
}

// W [K,N] f32 -> T [N,K] fp16
__global__ __launch_bounds__(256) void conv_T_h(
    const float* __restrict__ W, __half* __restrict__ WT, int K, int N)
{
    __shared__ float t[32][33];
    int n0 = blockIdx.x * 32, k0 = blockIdx.y * 32;
    int c = threadIdx.x & 31, r0 = threadIdx.x >> 5;
    #pragma unroll
    for (int j = 0; j < 4; j++) {
        int r = r0 + j * 8;
        t[r][c] = W[(size_t)(k0 + r) * N + n0 + c];
    }
    __syncthreads();
    #pragma unroll
    for (int j = 0; j < 4; j++) {
        int r = r0 + j * 8;
        WT[(size_t)(n0 + r) * K + k0 + c] = __float2half_rn(t[c][r]);
    }
}

// ---------------------------------------------------------------------------
// fp16 3-stage pipelined GEMM: C[M,N] = A @ B^T (+bias)
// A [M][K] fp16; B [N][K] fp16 (pre-transposed). Block 128x128, k-tile 32,
// 3 stages; 64B rows, XOR swizzle, zero padding.
// ---------------------------------------------------------------------------
#define GPLANE 8192            // 128 rows * 64 B
#define GSTG   16384           // 2 planes
#define OFF_A  0
#define OFF_B  8192

__global__ void __launch_bounds__(256, 2) gemm_f16(
    const __half* __restrict__ A, const __half* __restrict__ B,
    float* __restrict__ C, const float* __restrict__ bias,
    int M, int N, int K)
{
    extern __shared__ __align__(16) char smg[];
    const uint32_t sbase = (uint32_t)__cvta_generic_to_shared(smg);

    const int tid  = threadIdx.x;
    const int warp = tid >> 5, lane = tid & 31;
    const int gID  = lane >> 2, tig = lane & 3;
    const int bm = blockIdx.y * 128;
    const int bn = blockIdx.x * 128;
    const int m0 = (warp >> 1) * 32;
    const int n0 = (warp & 1) * 64;

    // loader: 4 granules (16B) per thread: 1024 granules = 2 planes x 512
    const __half* gsrc[4];
    uint32_t      gdst[4];
    #pragma unroll
    for (int j = 0; j < 4; j++) {
        int id = tid + j * 256;
        int pl = id >> 9;                  // 0=A, 1=B
        int idx = id & 511;
        int r = idx >> 2, g = idx & 3;
        const __half* base = pl == 0 ? A + (size_t)(bm + r) * K
                                     : B + (size_t)(bn + r) * K;
        gsrc[j] = base + g * 8;
        gdst[j] = (uint32_t)(pl * GPLANE + r * 64 + ((g ^ ((r >> 1) & 3)) << 4));
    }
#define GLOAD(st, k0)                                                          \
    do { for (int j_ = 0; j_ < 4; j_++)                                        \
             CP16(sbase + (uint32_t)(st) * GSTG + gdst[j_], gsrc[j_] + (k0));  \
    } while (0)

    uint32_t aoff[2]; int aswz[2];
    #pragma unroll
    for (int mi = 0; mi < 2; mi++) {
        int r = m0 + mi * 16 + (lane & 15);
        aoff[mi] = (uint32_t)(r * 64);
        aswz[mi] = (r >> 1) & 3;
    }
    const int ghA = lane >> 4;
    uint32_t boff[4]; int bswz[4];
    const int permB = ((lane >> 4) << 3) + (lane & 7);
    const int gbB = (lane >> 3) & 1;
    #pragma unroll
    for (int ntp = 0; ntp < 4; ntp++) {
        int r = n0 + ntp * 16 + permB;
        boff[ntp] = (uint32_t)(r * 64);
        bswz[ntp] = (r >> 1) & 3;
    }

    float acc[2][8][4];
    #pragma unroll
    for (int mi = 0; mi < 2; mi++)
        #pragma unroll
        for (int nt = 0; nt < 8; nt++)
            #pragma unroll
            for (int c = 0; c < 4; c++) acc[mi][nt][c] = 0.f;

    const int NIT = K >> 5;

    GLOAD(0, 0);
    asm volatile("cp.async.commit_group;");
    GLOAD(1, 32);
    asm volatile("cp.async.commit_group;");

    int cur = 0;
    #pragma unroll 1
    for (int it = 0; it < NIT; it++) {
        asm volatile("cp.async.wait_group 1;");
        __syncthreads();
        int nxt = cur + 2; if (nxt >= 3) nxt -= 3;
        if (it + 2 < NIT) GLOAD(nxt, (it + 2) * 32);
        asm volatile("cp.async.commit_group;");

        const uint32_t stb = sbase + (uint32_t)cur * GSTG;
        #pragma unroll
        for (int s = 0; s < 2; s++) {
            uint32_t af[2][4];
            #pragma unroll
            for (int mi = 0; mi < 2; mi++) {
                uint32_t ra = stb + OFF_A + aoff[mi]
                              + (uint32_t)((((s << 1) + ghA) ^ aswz[mi]) << 4);
                LDM4(af[mi], ra);
            }
            #pragma unroll
            for (int ntp = 0; ntp < 4; ntp++) {
                uint32_t rb = stb + OFF_B + boff[ntp]
                              + (uint32_t)((((s << 1) + gbB) ^ bswz[ntp]) << 4);
                uint32_t b4[4];
                LDM4(b4, rb);
                #pragma unroll
                for (int mi = 0; mi < 2; mi++) {
                    mma_f16(acc[mi][2 * ntp],
                            af[mi][0], af[mi][1], af[mi][2], af[mi][3], b4[0], b4[1]);
                    mma_f16(acc[mi][2 * ntp + 1],
                            af[mi][0], af[mi][1], af[mi][2], af[mi][3], b4[2], b4[3]);
                }
            }
        }
        cur = cur + 1; if (cur == 3) cur = 0;
    }

    #pragma unroll
    for (int mi = 0; mi < 2; mi++) {
        int row = bm + m0 + mi * 16 + gID;
        #pragma unroll
        for (int nt = 0; nt < 8; nt++) {
            int col = bn + n0 + nt * 8 + 2 * tig;
            float b0 = bias ? bias[col] : 0.f;
            float b1 = bias ? bias[col + 1] : 0.f;
            float2 w0; w0.x = acc[mi][nt][0] + b0; w0.y = acc[mi][nt][1] + b1;
            float2 w1; w1.x = acc[mi][nt][2] + b0; w1.y = acc[mi][nt][3] + b1;
            *(float2*)&C[(size_t)row * N + col] = w0;
            *(float2*)&C[(size_t)(row + 8) * N + col] = w1;
        }
    }
#undef GLOAD
}

// ---------------------------------------------------------------------------
// RoPE + split into per-head [B,H,N,d] fp16 Q/K/V. Scale folded into Q.
// ---------------------------------------------------------------------------
__global__ void rope_split(const float* __restrict__ qkv,
                           __half* __restrict__ Q, __half* __restrict__ Kt,
                           __half* __restrict__ Vt)
{
    int idx = blockIdx.x * blockDim.x + threadIdx.x;
    int i = idx & 31;
    int n = (idx >> 5) & (NN - 1);
    int h = (idx >> 16) & (Hh - 1);
    int b = idx >> 20;

    float inv_freq = powf(10000.f, -(float)i / 32.f);
    float fr = (float)n * inv_freq;
    float c = cosf(fr), s = sinf(fr);

    size_t base = ((size_t)b * NN + n) * (3 * CC) + h * DD;
    float q1 = qkv[base + i],          q2 = qkv[base + i + 32];
    float k1 = qkv[base + CC + i],     k2 = qkv[base + CC + i + 32];
    float v1 = qkv[base + 2 * CC + i], v2 = qkv[base + 2 * CC + i + 32];

    size_t ob = ((size_t)(b * Hh + h) * NN + n) * DD;
    Q[ob + i]       = __float2half_rn(0.125f * (q1 * c - q2 * s));
    Q[ob + i + 32]  = __float2half_rn(0.125f * (q1 * s + q2 * c));
    Kt[ob + i]      = __float2half_rn(k1 * c - k2 * s);
    Kt[ob + i + 32] = __float2half_rn(k1 * s + k2 * c);
    Vt[ob + i]      = __float2half_rn(v1);
    Vt[ob + i + 32] = __float2half_rn(v2);
}

// ---------------------------------------------------------------------------
// Flash attention, fp16 mma (m16n8k16), ldmatrix fragments, 2-stage KV pipe.
// 256 threads = 8 warps; Q tile 128 rows/CTA, KV tiles 64. Rows 128B, XOR swz.
// ---------------------------------------------------------------------------
#define FA_SMEM 32768

__global__ void __launch_bounds__(256, 2) flash_mma(
    const __half* __restrict__ Q, const __half* __restrict__ K,
    const __half* __restrict__ V, __half* __restrict__ O)
{
    extern __shared__ __align__(16) char sma[];
    const uint32_t sb = (uint32_t)__cvta_generic_to_shared(sma);

    const int bh = blockIdx.x;
    const int b = bh >> 4, h = bh & 15;
    const int tid = threadIdx.x;
    const int warp = tid >> 5, lane = tid & 31;
    const int gID = lane >> 2, tig = lane & 3;
    const int qbase = blockIdx.y * 128;

    // ---- stage Q tile (128 rows x 128B = 16KB), extract frags ----
    {
        const __half* qg = Q + ((size_t)bh * NN + qbase) * DD;
        #pragma unroll
        for (int j = 0; j < 4; j++) {
            int id = tid + j * 256;          // 0..1023
            int r = id >> 3, g = id & 7;
            CP16(sb + (uint32_t)(r * 128 + ((g ^ (r & 7)) << 4)), qg + r * DD + g * 8);
        }
        asm volatile("cp.async.commit_group;");
        asm volatile("cp.async.wait_group 0;");
        __syncthreads();
    }

    uint32_t aQ[4][4];
    {
        int qr = warp * 16 + (lane & 15);
        #pragma unroll
        for (int s = 0; s < 4; s++) {
            int gran = 2 * s + (lane >> 4);
            LDM4(aQ[s], sb + (uint32_t)(qr * 128 + ((gran ^ (qr & 7)) << 4)));
        }
    }
    __syncthreads();

    // ---- KV loader ----
    const __half* kbase = K + (size_t)bh * NN * DD;
    const __half* vbase = V + (size_t)bh * NN * DD;
#define KVLOAD(st, row0)                                                       \
    do { _Pragma("unroll")                                                     \
         for (int j_ = 0; j_ < 2; j_++) {                                      \
             int id_ = tid + j_ * 256;          /* 0..511 */                   \
             int r_ = id_ >> 3, g_ = id_ & 7;                                  \
             uint32_t sw_ = (uint32_t)(r_ * 128 + (((g_ ^ (r_ & 7))) << 4));   \
             CP16(sb + (uint32_t)(st) * 8192 + sw_,                            \
                  kbase + (size_t)(row0 + r_) * DD + g_ * 8);                  \
             CP16(sb + 16384u + (uint32_t)(st) * 8192 + sw_,                   \
                  vbase + (size_t)(row0 + r_) * DD + g_ * 8);                  \
         } } while (0)

    const int kr0  = lane & 7;
    const int gsel = (lane >> 3) & 1;
    const int sel  = lane >> 4;

    float of[8][4];
    #pragma unroll
    for (int i = 0; i < 8; i++)
        #pragma unroll
        for (int c = 0; c < 4; c++) of[i][c] = 0.f;
    float m0 = -1e30f, m1 = -1e30f, l0 = 0.f, l1 = 0.f;

    KVLOAD(0, 0);
    asm volatile("cp.async.commit_group;");

    #pragma unroll 1
    for (int t = 0; t < 32; t++) {
        asm volatile("cp.async.wait_group 0;");
        __syncthreads();
        if (t + 1 < 32) KVLOAD((t + 1) & 1, (t + 1) * 64);
        asm volatile("cp.async.commit_group;");

        const uint32_t Kst = sb + (uint32_t)((t & 1) * 8192);
        const uint32_t Vst = sb + 16384u + (uint32_t)((t & 1) * 8192);

        // ---- S = Q . K^T ----
        float sf[8][4];
        #pragma unroll
        for (int nt = 0; nt < 8; nt++)
            #pragma unroll
            for (int c = 0; c < 4; c++) sf[nt][c] = 0.f;

        #pragma unroll
        for (int s = 0; s < 4; s++) {
            int physg = (2 * s + gsel) ^ kr0;
            #pragma unroll
            for (int ip = 0; ip < 4; ip++) {
                int row = (2 * ip + sel) * 8 + kr0;
                uint32_t bb[4];
                LDM4(bb, Kst + (uint32_t)(row * 128 + (physg << 4)));
                mma_f16(sf[2 * ip],     aQ[s][0], aQ[s][1], aQ[s][2], aQ[s][3], bb[0], bb[1]);
                mma_f16(sf[2 * ip + 1], aQ[s][0], aQ[s][1], aQ[s][2], aQ[s][3], bb[2], bb[3]);
            }
        }

        // ---- online softmax (scale pre-folded into Q) ----
        float tmax0 = -1e30f, tmax1 = -1e30f;
        #pragma unroll
        for (int nt = 0; nt < 8; nt++) {
            tmax0 = fmaxf(tmax0, fmaxf(sf[nt][0], sf[nt][1]));
            tmax1 = fmaxf(tmax1, fmaxf(sf[nt][2], sf[nt][3]));
        }
        tmax0 = fmaxf(tmax0, __shfl_xor_sync(0xffffffffu, tmax0, 1));
        tmax0 = fmaxf(tmax0, __shfl_xor_sync(0xffffffffu, tmax0, 2));
        tmax1 = fmaxf(tmax1, __shfl_xor_sync(0xffffffffu, tmax1, 1));
        tmax1 = fmaxf(tmax1, __shfl_xor_sync(0xffffffffu, tmax1, 2));

        float mn0 = fmaxf(m0, tmax0);
        float mn1 = fmaxf(m1, tmax1);
        float al0 = __expf(m0 - mn0);
        float al1 = __expf(m1 - mn1);
        m0 = mn0; m1 = mn1;
        l0 *= al0; l1 *= al1;
        #pragma unroll
        for (int i = 0; i < 8; i++) {
            of[i][0] *= al0; of[i][1] *= al0;
            of[i][2] *= al1; of[i][3] *= al1;
        }
        #pragma unroll
        for (int nt = 0; nt < 8; nt++) {
            sf[nt][0] = __expf(sf[nt][0] - mn0);
            sf[nt][1] = __expf(sf[nt][1] - mn0);
            sf[nt][2] = __expf(sf[nt][2] - mn1);
            sf[nt][3] = __expf(sf[nt][3] - mn1);
            l0 += sf[nt][0] + sf[nt][1];
            l1 += sf[nt][2] + sf[nt][3];
        }

        // ---- O += P . V ----
        #pragma unroll
        for (int kk = 0; kk < 4; kk++) {
            uint32_t a0 = packh2(sf[2 * kk][0],     sf[2 * kk][1]);
            uint32_t a1 = packh2(sf[2 * kk][2],     sf[2 * kk][3]);
            uint32_t a2 = packh2(sf[2 * kk + 1][0], sf[2 * kk + 1][1]);
            uint32_t a3 = packh2(sf[2 * kk + 1][2], sf[2 * kk + 1][3]);
            int row = 16 * kk + kr0 + 8 * gsel;
            #pragma unroll
            for (int jp = 0; jp < 4; jp++) {
                int physg = (2 * jp + sel) ^ kr0;
                uint32_t bb[4];
                LDM4T(bb, Vst + (uint32_t)(row * 128 + (physg << 4)));
                mma_f16(of[2 * jp],     a0, a1, a2, a3, bb[0], bb[1]);
                mma_f16(of[2 * jp + 1], a0, a1, a2, a3, bb[2], bb[3]);
            }
        }
    }

    l0 += __shfl_xor_sync(0xffffffffu, l0, 1);
    l0 += __shfl_xor_sync(0xffffffffu, l0, 2);
    l1 += __shfl_xor_sync(0xffffffffu, l1, 1);
    l1 += __shfl_xor_sync(0xffffffffu, l1, 2);
    float inv0 = 1.f / l0;
    float inv1 = 1.f / l1;

    int r0 = qbase + warp * 16 + gID;
    int r1 = r0 + 8;
    size_t base0 = ((size_t)b * NN + r0) * CC + h * DD;
    size_t base1 = ((size_t)b * NN + r1) * CC + h * DD;
    #pragma unroll
    for (int i = 0; i < 8; i++) {
        int col = i * 8 + 2 * tig;
        *(__half2*)&O[base0 + col] = __floats2half2_rn(of[i][0] * inv0, of[i][1] * inv0);
        *(__half2*)&O[base1 + col] = __floats2half2_rn(of[i][2] * inv1, of[i][3] * inv1);
    }
#undef KVLOAD
}

// ---------------------------------------------------------------------------
extern "C" void kernel_launch(void* const* d_in, const int* in_sizes, int n_in,
                              void* d_out, int out_size)
{
    const float* x      = (const float*)d_in[0];
    const float* w_qkv  = (const float*)d_in[1];
    const float* w_proj = (const float*)d_in[2];
    const float* b_proj = (const float*)d_in[3];
    float* out = (float*)d_out;

    float* qkv;
    __half *qh, *kh, *vh, *xa, *wq, *wp, *att;
    cudaGetSymbolAddress((void**)&qkv, g_qkv);
    cudaGetSymbolAddress((void**)&qh,  g_qh);
    cudaGetSymbolAddress((void**)&kh,  g_kh);
    cudaGetSymbolAddress((void**)&vh,  g_vh);
    cudaGetSymbolAddress((void**)&xa,  g_xa);
    cudaGetSymbolAddress((void**)&wq,  g_wq);
    cudaGetSymbolAddress((void**)&wp,  g_wp);
    cudaGetSymbolAddress((void**)&att, g_att);

    static int attr_done = 0;
    if (!attr_done) {
        cudaFuncSetAttribute(gemm_f16, cudaFuncAttributeMaxDynamicSharedMemorySize,
                             3 * GSTG);
        cudaFuncSetAttribute(flash_mma, cudaFuncAttributeMaxDynamicSharedMemorySize,
                             FA_SMEM);
        attr_done = 1;
    }

    // 0) one-time prep
    conv_h<<<(MM_ * CC / 4) / 256, 256>>>(x, xa);
    conv_T_h<<<dim3(3 * CC / 32, CC / 32), 256>>>(w_qkv, wq, CC, 3 * CC);
    conv_T_h<<<dim3(CC / 32, CC / 32), 256>>>(w_proj, wp, CC, CC);

    // 1) QKV GEMM: [4096, 3072] (fp16, 3-stage pipeline)
    gemm_f16<<<dim3(3 * CC / 128, MM_ / 128), 256, 3 * GSTG>>>(
        xa, wq, qkv, nullptr, MM_, 3 * CC, CC);

    // 2) RoPE + head split (fp16 outputs, scale folded into Q)
    rope_split<<<(Bb * Hh * NN * 32) / 256, 256>>>(qkv, qh, kh, vh);

    // 3) Attention (fp16 tensor cores, pipelined KV, 128-row Q tiles)
    flash_mma<<<dim3(Bb * Hh, NN / 128), 256, FA_SMEM>>>(qh, kh, vh, att);

    // 4) Projection GEMM + bias (fp16)
    gemm_f16<<<dim3(CC / 128, MM_ / 128), 256, 3 * GSTG>>>(
        att, wp, out, b_proj, MM_, CC, CC);
}

// round 11
// speedup vs baseline: 8.7018x; 1.0428x over previous
#include <cuda_runtime.h>
#include <cuda_bf16.h>
#include <cuda_fp16.h>
#include <math.h>
#include <stdint.h>

// Problem shape (fixed)
#define Bb 2
#define Hh 16
#define NN 2048
#define CC 1024
#define DD 64
#define MM_ (Bb * NN)        // 4096 rows

// Scratch (device globals — no allocation allowed)
__device__ __align__(16) __half g_qh[(size_t)Bb * Hh * NN * DD];  // fp16, scale-folded
__device__ __align__(16) __half g_kh[(size_t)Bb * Hh * NN * DD];
__device__ __align__(16) __half g_vh[(size_t)Bb * Hh * NN * DD];

__device__ __align__(16) __half g_xa[(size_t)MM_ * CC];            // fp16(x)
__device__ __align__(16) __half g_wq[(size_t)3 * CC * CC];         // [3072][1024] T
__device__ __align__(16) __half g_wp[(size_t)CC * CC];             // [1024][1024] T
__device__ __align__(16) __half g_att[(size_t)MM_ * CC];           // fp16(attention out)
__device__ __align__(16) float2 g_rope[(size_t)NN * 32];           // (cos,sin)[n][d]

// ---------------------------------------------------------------------------
// helpers
// ---------------------------------------------------------------------------
__device__ __forceinline__ void mma_f16(float* d,
                                        uint32_t a0, uint32_t a1, uint32_t a2, uint32_t a3,
                                        uint32_t b0, uint32_t b1)
{
    asm volatile(
        "mma.sync.aligned.m16n8k16.row.col.f32.f16.f16.f32 "
        "{%0,%1,%2,%3}, {%4,%5,%6,%7}, {%8,%9}, {%0,%1,%2,%3};"
        : "+f"(d[0]), "+f"(d[1]), "+f"(d[2]), "+f"(d[3])
        : "r"(a0), "r"(a1), "r"(a2), "r"(a3), "r"(b0), "r"(b1));
}

#define LDM4(r, addr)                                                        \
    asm volatile("ldmatrix.sync.aligned.m8n8.x4.shared.b16 {%0,%1,%2,%3}, [%4];" \
                 : "=r"((r)[0]), "=r"((r)[1]), "=r"((r)[2]), "=r"((r)[3])    \
                 : "r"(addr))

#define LDM4T(r, addr)                                                       \
    asm volatile("ldmatrix.sync.aligned.m8n8.x4.trans.shared.b16 {%0,%1,%2,%3}, [%4];" \
                 : "=r"((r)[0]), "=r"((r)[1]), "=r"((r)[2]), "=r"((r)[3])    \
                 : "r"(addr))

#define CP16(saddr, gptr)                                                    \
    asm volatile("cp.async.cg.shared.global [%0], [%1], 16;" :: "r"(saddr), "l"(gptr))

__device__ __forceinline__ uint32_t packh2(float lo, float hi) {
    __half2 h = __floats2half2_rn(lo, hi);
    return *(uint32_t*)&h;
}

// ---------------------------------------------------------------------------
// prep kernels
// ---------------------------------------------------------------------------
__global__ void rope_tab(float2* __restrict__ tab)
{
    int idx = blockIdx.x * blockDim.x + threadIdx.x;    // over NN*32
    int n = idx >> 5, d = idx & 31;
    float inv_freq = powf(10000.f, -(float)d / 32.f);
    float a = (float)n * inv_freq;
    tab[idx] = make_float2(cosf(a), sinf(a));
}

__global__ void conv_h(const float* __restrict__ src, __half* __restrict__ dst)
{
    int i = blockIdx.x * blockDim.x + threadIdx.x;   // over n/4
    float4 v = ((const float4*)src)[i];
    ((__half2*)dst)[2 * i]     = __floats2half2_rn(v.x, v.y);
    ((__half2*)dst)[2 * i + 1] = __floats2half2_rn(v.z, v.w);
}

// W [K,N] f32 -> T [N,K] fp16
__global__ __launch_bounds__(256) void conv_T_h(
    const float* __restrict__ W, __half* __restrict__ WT, int K, int N)
{
    __shared__ float t[32][33];
    int n0 = blockIdx.x * 32, k0 = blockIdx.y * 32;
    int c = threadIdx.x & 31, r0 = threadIdx.x >> 5;
    #pragma unroll
    for (int j = 0; j < 4; j++) {
        int r = r0 + j * 8;
        t[r][c] = W[(size_t)(k0 + r) * N + n0 + c];
    }
    __syncthreads();
    #pragma unroll
    for (int j = 0; j < 4; j++) {
        int r = r0 + j * 8;
        WT[(size_t)(n0 + r) * K + k0 + c] = __float2half_rn(t[c][r]);
    }
}

// ---------------------------------------------------------------------------
// Shared GEMM mainloop skeleton (fp16, 3-stage, 128x128 tile, k-tile 32).
// Two kernels below share it via macro; they differ only in the epilogue.
// ---------------------------------------------------------------------------
#define GPLANE 8192            // 128 rows * 64 B
#define GSTG   16384           // 2 planes
#define OFF_A  0
#define OFF_B  8192

#define GEMM_MAINLOOP(Aptr, Bptr)                                              \
    extern __shared__ __align__(16) char smg[];                                \
    const uint32_t sbase = (uint32_t)__cvta_generic_to_shared(smg);            \
    const int tid  = threadIdx.x;                                              \
    const int warp = tid >> 5, lane = tid & 31;                                \
    const int gID  = lane >> 2, tig = lane & 3;                                \
    const int bm = blockIdx.y * 128;                                           \
    const int bn = blockIdx.x * 128;                                           \
    const int m0 = (warp >> 1) * 32;                                           \
    const int n0 = (warp & 1) * 64;                                            \
    const __half* gsrc[4];                                                     \
    uint32_t      gdst[4];                                                     \
    _Pragma("unroll")                                                          \
    for (int j = 0; j < 4; j++) {                                              \
        int id = tid + j * 256;                                                \
        int pl = id >> 9;                                                      \
        int idx = id & 511;                                                    \
        int r = idx >> 2, g = idx & 3;                                         \
        const __half* base = pl == 0 ? (Aptr) + (size_t)(bm + r) * K           \
                                     : (Bptr) + (size_t)(bn + r) * K;          \
        gsrc[j] = base + g * 8;                                                \
        gdst[j] = (uint32_t)(pl * GPLANE + r * 64 + ((g ^ ((r >> 1) & 3)) << 4)); \
    }                                                                          \
    uint32_t aoff[2]; int aswz[2];                                             \
    _Pragma("unroll")                                                          \
    for (int mi = 0; mi < 2; mi++) {                                           \
        int r = m0 + mi * 16 + (lane & 15);                                    \
        aoff[mi] = (uint32_t)(r * 64);                                         \
        aswz[mi] = (r >> 1) & 3;                                               \
    }                                                                          \
    const int ghA = lane >> 4;                                                 \
    uint32_t boff[4]; int bswz[4];                                             \
    const int permB = ((lane >> 4) << 3) + (lane & 7);                         \
    const int gbB = (lane >> 3) & 1;                                           \
    _Pragma("unroll")                                                          \
    for (int ntp = 0; ntp < 4; ntp++) {                                        \
        int r = n0 + ntp * 16 + permB;                                         \
        boff[ntp] = (uint32_t)(r * 64);                                        \
        bswz[ntp] = (r >> 1) & 3;                                              \
    }                                                                          \
    float acc[2][8][4];                                                        \
    _Pragma("unroll")                                                          \
    for (int mi = 0; mi < 2; mi++)                                             \
        _Pragma("unroll")                                                      \
        for (int nt = 0; nt < 8; nt++)                                         \
            _Pragma("unroll")                                                  \
            for (int c = 0; c < 4; c++) acc[mi][nt][c] = 0.f;                  \
    const int NIT = K >> 5;                                                    \
    { for (int j_ = 0; j_ < 4; j_++) CP16(sbase + gdst[j_], gsrc[j_]); }       \
    asm volatile("cp.async.commit_group;");                                    \
    { for (int j_ = 0; j_ < 4; j_++)                                           \
          CP16(sbase + GSTG + gdst[j_], gsrc[j_] + 32); }                      \
    asm volatile("cp.async.commit_group;");                                    \
    int cur = 0;                                                               \
    _Pragma("unroll 1")                                                        \
    for (int it = 0; it < NIT; it++) {                                         \
        asm volatile("cp.async.wait_group 1;");                                \
        __syncthreads();                                                       \
        int nxt = cur + 2; if (nxt >= 3) nxt -= 3;                             \
        if (it + 2 < NIT) {                                                    \
            for (int j_ = 0; j_ < 4; j_++)                                     \
                CP16(sbase + (uint32_t)nxt * GSTG + gdst[j_],                  \
                     gsrc[j_] + (it + 2) * 32);                                \
        }                                                                      \
        asm volatile("cp.async.commit_group;");                                \
        const uint32_t stb = sbase + (uint32_t)cur * GSTG;                     \
        _Pragma("unroll")                                                      \
        for (int s = 0; s < 2; s++) {                                          \
            uint32_t af[2][4];                                                 \
            _Pragma("unroll")                                                  \
            for (int mi = 0; mi < 2; mi++) {                                   \
                uint32_t ra = stb + OFF_A + aoff[mi]                           \
                              + (uint32_t)((((s << 1) + ghA) ^ aswz[mi]) << 4);\
                LDM4(af[mi], ra);                                              \
            }                                                                  \
            _Pragma("unroll")                                                  \
            for (int ntp = 0; ntp < 4; ntp++) {                                \
                uint32_t rb = stb + OFF_B + boff[ntp]                          \
                              + (uint32_t)((((s << 1) + gbB) ^ bswz[ntp]) << 4);\
                uint32_t b4[4];                                                \
                LDM4(b4, rb);                                                  \
                _Pragma("unroll")                                              \
                for (int mi = 0; mi < 2; mi++) {                               \
                    mma_f16(acc[mi][2 * ntp],                                  \
                            af[mi][0], af[mi][1], af[mi][2], af[mi][3],        \
                            b4[0], b4[1]);                                     \
                    mma_f16(acc[mi][2 * ntp + 1],                              \
                            af[mi][0], af[mi][1], af[mi][2], af[mi][3],        \
                            b4[2], b4[3]);                                     \
                }                                                              \
            }                                                                  \
        }                                                                      \
        cur = cur + 1; if (cur == 3) cur = 0;                                  \
    }

// ---------------------------------------------------------------------------
// QKV GEMM with fused RoPE + head-split epilogue -> fp16 Q/K/V [B,H,N,d]
// ---------------------------------------------------------------------------
__global__ void __launch_bounds__(256, 2) gemm_qkv(
    const __half* __restrict__ A, const __half* __restrict__ B,
    const float2* __restrict__ rope,
    __half* __restrict__ Qo, __half* __restrict__ Ko, __half* __restrict__ Vo,
    int M, int N, int K)
{
    GEMM_MAINLOOP(A, B)

    // epilogue: bn selects q/k/v (tiles of 1024 cols); warp n-tile = one head
    const int t  = bn >> 10;
    const int h  = ((bn & 1023) + n0) >> 6;
    __half* outb = (t == 0) ? Qo : (t == 1) ? Ko : Vo;
    const float sc = (t == 0) ? 0.125f : 1.f;

    #pragma unroll
    for (int mi = 0; mi < 2; mi++) {
        int row0 = bm + m0 + mi * 16 + gID;
        #pragma unroll
        for (int rr = 0; rr < 2; rr++) {
            int r = row0 + rr * 8;
            int n = r & (NN - 1), bi = r >> 11;
            __half* dst = outb + ((size_t)(bi * Hh + h) * NN + n) * DD;
            if (t == 2) {
                #pragma unroll
                for (int nt = 0; nt < 8; nt++) {
                    int d0 = nt * 8 + 2 * tig;
                    *(__half2*)&dst[d0] =
                        __floats2half2_rn(acc[mi][nt][2 * rr], acc[mi][nt][2 * rr + 1]);
                }
            } else {
                #pragma unroll
                for (int nt = 0; nt < 4; nt++) {
                    int d0 = nt * 8 + 2 * tig;
                    float2 cs0 = rope[n * 32 + d0];
                    float2 cs1 = rope[n * 32 + d0 + 1];
                    float x10 = acc[mi][nt][2 * rr],     x11 = acc[mi][nt][2 * rr + 1];
                    float x20 = acc[mi][nt + 4][2 * rr], x21 = acc[mi][nt + 4][2 * rr + 1];
                    float lo0 = (x10 * cs0.x - x20 * cs0.y) * sc;
                    float lo1 = (x11 * cs1.x - x21 * cs1.y) * sc;
                    float hi0 = (x10 * cs0.y + x20 * cs0.x) * sc;
                    float hi1 = (x11 * cs1.y + x21 * cs1.x) * sc;
                    *(__half2*)&dst[d0]      = __floats2half2_rn(lo0, lo1);
                    *(__half2*)&dst[d0 + 32] = __floats2half2_rn(hi0, hi1);
                }
            }
        }
    }
}

// ---------------------------------------------------------------------------
// Projection GEMM: f32 out + bias
// ---------------------------------------------------------------------------
__global__ void __launch_bounds__(256, 2) gemm_f16(
    const __half* __restrict__ A, const __half* __restrict__ B,
    float* __restrict__ C, const float* __restrict__ bias,
    int M, int N, int K)
{
    GEMM_MAINLOOP(A, B)

    #pragma unroll
    for (int mi = 0; mi < 2; mi++) {
        int row = bm + m0 + mi * 16 + gID;
        #pragma unroll
        for (int nt = 0; nt < 8; nt++) {
            int col = bn + n0 + nt * 8 + 2 * tig;
            float b0 = bias[col];
            float b1 = bias[col + 1];
            float2 w0; w0.x = acc[mi][nt][0] + b0; w0.y = acc[mi][nt][1] + b1;
            float2 w1; w1.x = acc[mi][nt][2] + b0; w1.y = acc[mi][nt][3] + b1;
            *(float2*)&C[(size_t)row * N + col] = w0;
            *(float2*)&C[(size_t)(row + 8) * N + col] = w1;
        }
    }
}

// ---------------------------------------------------------------------------
// Flash attention, fp16 mma (m16n8k16), ldmatrix fragments, 2-stage KV pipe.
// ---------------------------------------------------------------------------
#define FA_SMEM 32768

__global__ void __launch_bounds__(256, 2) flash_mma(
    const __half* __restrict__ Q, const __half* __restrict__ K,
    const __half* __restrict__ V, __half* __restrict__ O)
{
    extern __shared__ __align__(16) char sma[];
    const uint32_t sb = (uint32_t)__cvta_generic_to_shared(sma);

    const int bh = blockIdx.x;
    const int b = bh >> 4, h = bh & 15;
    const int tid = threadIdx.x;
    const int warp = tid >> 5, lane = tid & 31;
    const int gID = lane >> 2, tig = lane & 3;
    const int qbase = blockIdx.y * 128;

    {
        const __half* qg = Q + ((size_t)bh * NN + qbase) * DD;
        #pragma unroll
        for (int j = 0; j < 4; j++) {
            int id = tid + j * 256;
            int r = id >> 3, g = id & 7;
            CP16(sb + (uint32_t)(r * 128 + ((g ^ (r & 7)) << 4)), qg + r * DD + g * 8);
        }
        asm volatile("cp.async.commit_group;");
        asm volatile("cp.async.wait_group 0;");
        __syncthreads();
    }

    uint32_t aQ[4][4];
    {
        int qr = warp * 16 + (lane & 15);
        #pragma unroll
        for (int s = 0; s < 4; s++) {
            int gran = 2 * s + (lane >> 4);
            LDM4(aQ[s], sb + (uint32_t)(qr * 128 + ((gran ^ (qr & 7)) << 4)));
        }
    }
    __syncthreads();

    const __half* kbase = K + (size_t)bh * NN * DD;
    const __half* vbase = V + (size_t)bh * NN * DD;
#define KVLOAD(st, row0)                                                       \
    do { _Pragma("unroll")                                                     \
         for (int j_ = 0; j_ < 2; j_++) {                                      \
             int id_ = tid + j_ * 256;                                         \
             int r_ = id_ >> 3, g_ = id_ & 7;                                  \
             uint32_t sw_ = (uint32_t)(r_ * 128 + (((g_ ^ (r_ & 7))) << 4));   \
             CP16(sb + (uint32_t)(st) * 8192 + sw_,                            \
                  kbase + (size_t)(row0 + r_) * DD + g_ * 8);                  \
             CP16(sb + 16384u + (uint32_t)(st) * 8192 + sw_,                   \
                  vbase + (size_t)(row0 + r_) * DD + g_ * 8);                  \
         } } while (0)

    const int kr0  = lane & 7;
    const int gsel = (lane >> 3) & 1;
    const int sel  = lane >> 4;

    float of[8][4];
    #pragma unroll
    for (int i = 0; i < 8; i++)
        #pragma unroll
        for (int c = 0; c < 4; c++) of[i][c] = 0.f;
    float m0 = -1e30f, m1 = -1e30f, l0 = 0.f, l1 = 0.f;

    KVLOAD(0, 0);
    asm volatile("cp.async.commit_group;");

    #pragma unroll 1
    for (int t = 0; t < 32; t++) {
        asm volatile("cp.async.wait_group 0;");
        __syncthreads();
        if (t + 1 < 32) KVLOAD((t + 1) & 1, (t + 1) * 64);
        asm volatile("cp.async.commit_group;");

        const uint32_t Kst = sb + (uint32_t)((t & 1) * 8192);
        const uint32_t Vst = sb + 16384u + (uint32_t)((t & 1) * 8192);

        float sf[8][4];
        #pragma unroll
        for (int nt = 0; nt < 8; nt++)
            #pragma unroll
            for (int c = 0; c < 4; c++) sf[nt][c] = 0.f;

        #pragma unroll
        for (int s = 0; s < 4; s++) {
            int physg = (2 * s + gsel) ^ kr0;
            #pragma unroll
            for (int ip = 0; ip < 4; ip++) {
                int row = (2 * ip + sel) * 8 + kr0;
                uint32_t bb[4];
                LDM4(bb, Kst + (uint32_t)(row * 128 + (physg << 4)));
                mma_f16(sf[2 * ip],     aQ[s][0], aQ[s][1], aQ[s][2], aQ[s][3], bb[0], bb[1]);
                mma_f16(sf[2 * ip + 1], aQ[s][0], aQ[s][1], aQ[s][2], aQ[s][3], bb[2], bb[3]);
            }
        }

        float tmax0 = -1e30f, tmax1 = -1e30f;
        #pragma unroll
        for (int nt = 0; nt < 8; nt++) {
            tmax0 = fmaxf(tmax0, fmaxf(sf[nt][0], sf[nt][1]));
            tmax1 = fmaxf(tmax1, fmaxf(sf[nt][2], sf[nt][3]));
        }
        tmax0 = fmaxf(tmax0, __shfl_xor_sync(0xffffffffu, tmax0, 1));
        tmax0 = fmaxf(tmax0, __shfl_xor_sync(0xffffffffu, tmax0, 2));
        tmax1 = fmaxf(tmax1, __shfl_xor_sync(0xffffffffu, tmax1, 1));
        tmax1 = fmaxf(tmax1, __shfl_xor_sync(0xffffffffu, tmax1, 2));

        float mn0 = fmaxf(m0, tmax0);
        float mn1 = fmaxf(m1, tmax1);
        float al0 = __expf(m0 - mn0);
        float al1 = __expf(m1 - mn1);
        m0 = mn0; m1 = mn1;
        l0 *= al0; l1 *= al1;
        #pragma unroll
        for (int i = 0; i < 8; i++) {
            of[i][0] *= al0; of[i][1] *= al0;
            of[i][2] *= al1; of[i][3] *= al1;
        }
        #pragma unroll
        for (int nt = 0; nt < 8; nt++) {
            sf[nt][0] = __expf(sf[nt][0] - mn0);
            sf[nt][1] = __expf(sf[nt][1] - mn0);
            sf[nt][2] = __expf(sf[nt][2] - mn1);
            sf[nt][3] = __expf(sf[nt][3] - mn1);
            l0 += sf[nt][0] + sf[nt][1];
            l1 += sf[nt][2] + sf[nt][3];
        }

        #pragma unroll
        for (int kk = 0; kk < 4; kk++) {
            uint32_t a0 = packh2(sf[2 * kk][0],     sf[2 * kk][1]);
            uint32_t a1 = packh2(sf[2 * kk][2],     sf[2 * kk][3]);
            uint32_t a2 = packh2(sf[2 * kk + 1][0], sf[2 * kk + 1][1]);
            uint32_t a3 = packh2(sf[2 * kk + 1][2], sf[2 * kk + 1][3]);
            int row = 16 * kk + kr0 + 8 * gsel;
            #pragma unroll
            for (int jp = 0; jp < 4; jp++) {
                int physg = (2 * jp + sel) ^ kr0;
                uint32_t bb[4];
                LDM4T(bb, Vst + (uint32_t)(row * 128 + (physg << 4)));
                mma_f16(of[2 * jp],     a0, a1, a2, a3, bb[0], bb[1]);
                mma_f16(of[2 * jp + 1], a0, a1, a2, a3, bb[2], bb[3]);
            }
        }
    }

    l0 += __shfl_xor_sync(0xffffffffu, l0, 1);
    l0 += __shfl_xor_sync(0xffffffffu, l0, 2);
    l1 += __shfl_xor_sync(0xffffffffu, l1, 1);
    l1 += __shfl_xor_sync(0xffffffffu, l1, 2);
    float inv0 = 1.f / l0;
    float inv1 = 1.f / l1;

    int r0 = qbase + warp * 16 + gID;
    int r1 = r0 + 8;
    size_t base0 = ((size_t)b * NN + r0) * CC + h * DD;
    size_t base1 = ((size_t)b * NN + r1) * CC + h * DD;
    #pragma unroll
    for (int i = 0; i < 8; i++) {
        int col = i * 8 + 2 * tig;
        *(__half2*)&O[base0 + col] = __floats2half2_rn(of[i][0] * inv0, of[i][1] * inv0);
        *(__half2*)&O[base1 + col] = __floats2half2_rn(of[i][2] * inv1, of[i][3] * inv1);
    }
#undef KVLOAD
}

// ---------------------------------------------------------------------------
extern "C" void kernel_launch(void* const* d_in, const int* in_sizes, int n_in,
                              void* d_out, int out_size)
{
    const float* x      = (const float*)d_in[0];
    const float* w_qkv  = (const float*)d_in[1];
    const float* w_proj = (const float*)d_in[2];
    const float* b_proj = (const float*)d_in[3];
    float* out = (float*)d_out;

    __half *qh, *kh, *vh, *xa, *wq, *wp, *att;
    float2* rope;
    cudaGetSymbolAddress((void**)&qh,   g_qh);
    cudaGetSymbolAddress((void**)&kh,   g_kh);
    cudaGetSymbolAddress((void**)&vh,   g_vh);
    cudaGetSymbolAddress((void**)&xa,   g_xa);
    cudaGetSymbolAddress((void**)&wq,   g_wq);
    cudaGetSymbolAddress((void**)&wp,   g_wp);
    cudaGetSymbolAddress((void**)&att,  g_att);
    cudaGetSymbolAddress((void**)&rope, g_rope);

    static int attr_done = 0;
    if (!attr_done) {
        cudaFuncSetAttribute(gemm_qkv, cudaFuncAttributeMaxDynamicSharedMemorySize,
                             3 * GSTG);
        cudaFuncSetAttribute(gemm_f16, cudaFuncAttributeMaxDynamicSharedMemorySize,
                             3 * GSTG);
        cudaFuncSetAttribute(flash_mma, cudaFuncAttributeMaxDynamicSharedMemorySize,
                             FA_SMEM);
        attr_done = 1;
    }

    // 0) one-time prep
    rope_tab<<<(NN * 32) / 256, 256>>>(rope);
    conv_h<<<(MM_ * CC / 4) / 256, 256>>>(x, xa);
    conv_T_h<<<dim3(3 * CC / 32, CC / 32), 256>>>(w_qkv, wq, CC, 3 * CC);
    conv_T_h<<<dim3(CC / 32, CC / 32), 256>>>(w_proj, wp, CC, CC);

    // 1) QKV GEMM with fused RoPE + head split -> fp16 Q/K/V
    gemm_qkv<<<dim3(3 * CC / 128, MM_ / 128), 256, 3 * GSTG>>>(
        xa, wq, rope, qh, kh, vh, MM_, 3 * CC, CC);

    // 2) Attention (fp16 tensor cores, pipelined KV, 128-row Q tiles)
    flash_mma<<<dim3(Bb * Hh, NN / 128), 256, FA_SMEM>>>(qh, kh, vh, att);

    // 3) Projection GEMM + bias (fp16 -> f32)
    gemm_f16<<<dim3(CC / 128, MM_ / 128), 256, 3 * GSTG>>>(
        att, wp, out, b_proj, MM_, CC, CC);
}

// round 12
// speedup vs baseline: 9.0724x; 1.0426x over previous
#include <cuda_runtime.h>
#include <cuda_bf16.h>
#include <cuda_fp16.h>
#include <math.h>
#include <stdint.h>

// Problem shape (fixed)
#define Bb 2
#define Hh 16
#define NN 2048
#define CC 1024
#define DD 64
#define MM_ (Bb * NN)        // 4096 rows

// Scratch (device globals — no allocation allowed)
__device__ __align__(16) __half g_qh[(size_t)Bb * Hh * NN * DD];  // fp16, scale-folded
__device__ __align__(16) __half g_kh[(size_t)Bb * Hh * NN * DD];
__device__ __align__(16) __half g_vh[(size_t)Bb * Hh * NN * DD];

__device__ __align__(16) __half g_xa[(size_t)MM_ * CC];            // fp16(x)
__device__ __align__(16) __half g_wq[(size_t)3 * CC * CC];         // [3072][1024] T
__device__ __align__(16) __half g_wp[(size_t)CC * CC];             // [1024][1024] T
__device__ __align__(16) __half g_att[(size_t)MM_ * CC];           // fp16(attention out)
__device__ __align__(16) float2 g_rope[(size_t)NN * 32];           // (cos,sin)[n][d]

// ---------------------------------------------------------------------------
// helpers
// ---------------------------------------------------------------------------
__device__ __forceinline__ void mma_f16(float* d,
                                        uint32_t a0, uint32_t a1, uint32_t a2, uint32_t a3,
                                        uint32_t b0, uint32_t b1)
{
    asm volatile(
        "mma.sync.aligned.m16n8k16.row.col.f32.f16.f16.f32 "
        "{%0,%1,%2,%3}, {%4,%5,%6,%7}, {%8,%9}, {%0,%1,%2,%3};"
        : "+f"(d[0]), "+f"(d[1]), "+f"(d[2]), "+f"(d[3])
        : "r"(a0), "r"(a1), "r"(a2), "r"(a3), "r"(b0), "r"(b1));
}

#define LDM4(r, addr)                                                        \
    asm volatile("ldmatrix.sync.aligned.m8n8.x4.shared.b16 {%0,%1,%2,%3}, [%4];" \
                 : "=r"((r)[0]), "=r"((r)[1]), "=r"((r)[2]), "=r"((r)[3])    \
                 : "r"(addr))

#define LDM4T(r, addr)                                                       \
    asm volatile("ldmatrix.sync.aligned.m8n8.x4.trans.shared.b16 {%0,%1,%2,%3}, [%4];" \
                 : "=r"((r)[0]), "=r"((r)[1]), "=r"((r)[2]), "=r"((r)[3])    \
                 : "r"(addr))

#define CP16(saddr, gptr)                                                    \
    asm volatile("cp.async.cg.shared.global [%0], [%1], 16;" :: "r"(saddr), "l"(gptr))

__device__ __forceinline__ uint32_t packh2(float lo, float hi) {
    __half2 h = __floats2half2_rn(lo, hi);
    return *(uint32_t*)&h;
}

// ---------------------------------------------------------------------------
// prep kernels
// ---------------------------------------------------------------------------
__global__ void rope_tab(float2* __restrict__ tab)
{
    int idx = blockIdx.x * blockDim.x + threadIdx.x;    // over NN*32
    int n = idx >> 5, d = idx & 31;
    float inv_freq = powf(10000.f, -(float)d / 32.f);
    float a = (float)n * inv_freq;
    tab[idx] = make_float2(cosf(a), sinf(a));
}

__global__ void conv_h(const float* __restrict__ src, __half* __restrict__ dst)
{
    int i = blockIdx.x * blockDim.x + threadIdx.x;   // over n/4
    float4 v = ((const float4*)src)[i];
    ((__half2*)dst)[2 * i]     = __floats2half2_rn(v.x, v.y);
    ((__half2*)dst)[2 * i + 1] = __floats2half2_rn(v.z, v.w);
}

// W [K,N] f32 -> T [N,K] fp16
__global__ __launch_bounds__(256) void conv_T_h(
    const float* __restrict__ W, __half* __restrict__ WT, int K, int N)
{
    __shared__ float t[32][33];
    int n0 = blockIdx.x * 32, k0 = blockIdx.y * 32;
    int c = threadIdx.x & 31, r0 = threadIdx.x >> 5;
    #pragma unroll
    for (int j = 0; j < 4; j++) {
        int r = r0 + j * 8;
        t[r][c] = W[(size_t)(k0 + r) * N + n0 + c];
    }
    __syncthreads();
    #pragma unroll
    for (int j = 0; j < 4; j++) {
        int r = r0 + j * 8;
        WT[(size_t)(n0 + r) * K + k0 + c] = __float2half_rn(t[c][r]);
    }
}

// ---------------------------------------------------------------------------
// Shared GEMM mainloop skeleton (fp16, 3-stage, 128x128 tile, k-tile 32).
// ---------------------------------------------------------------------------
#define GPLANE 8192            // 128 rows * 64 B
#define GSTG   16384           // 2 planes
#define OFF_A  0
#define OFF_B  8192

#define GEMM_MAINLOOP(Aptr, Bptr)                                              \
    extern __shared__ __align__(16) char smg[];                                \
    const uint32_t sbase = (uint32_t)__cvta_generic_to_shared(smg);            \
    const int tid  = threadIdx.x;                                              \
    const int warp = tid >> 5, lane = tid & 31;                                \
    const int gID  = lane >> 2, tig = lane & 3;                                \
    const int bm = blockIdx.y * 128;                                           \
    const int bn = blockIdx.x * 128;                                           \
    const int m0 = (warp >> 1) * 32;                                           \
    const int n0 = (warp & 1) * 64;                                            \
    const __half* gsrc[4];                                                     \
    uint32_t      gdst[4];                                                     \
    _Pragma("unroll")                                                          \
    for (int j = 0; j < 4; j++) {                                              \
        int id = tid + j * 256;                                                \
        int pl = id >> 9;                                                      \
        int idx = id & 511;                                                    \
        int r = idx >> 2, g = idx & 3;                                         \
        const __half* base = pl == 0 ? (Aptr) + (size_t)(bm + r) * K           \
                                     : (Bptr) + (size_t)(bn + r) * K;          \
        gsrc[j] = base + g * 8;                                                \
        gdst[j] = (uint32_t)(pl * GPLANE + r * 64 + ((g ^ ((r >> 1) & 3)) << 4)); \
    }                                                                          \
    uint32_t aoff[2]; int aswz[2];                                             \
    _Pragma("unroll")                                                          \
    for (int mi = 0; mi < 2; mi++) {                                           \
        int r = m0 + mi * 16 + (lane & 15);                                    \
        aoff[mi] = (uint32_t)(r * 64);                                         \
        aswz[mi] = (r >> 1) & 3;                                               \
    }                                                                          \
    const int ghA = lane >> 4;                                                 \
    uint32_t boff[4]; int bswz[4];                                             \
    const int permB = ((lane >> 4) << 3) + (lane & 7);                         \
    const int gbB = (lane >> 3) & 1;                                           \
    _Pragma("unroll")                                                          \
    for (int ntp = 0; ntp < 4; ntp++) {                                        \
        int r = n0 + ntp * 16 + permB;                                         \
        boff[ntp] = (uint32_t)(r * 64);                                        \
        bswz[ntp] = (r >> 1) & 3;                                              \
    }                                                                          \
    float acc[2][8][4];                                                        \
    _Pragma("unroll")                                                          \
    for (int mi = 0; mi < 2; mi++)                                             \
        _Pragma("unroll")                                                      \
        for (int nt = 0; nt < 8; nt++)                                         \
            _Pragma("unroll")                                                  \
            for (int c = 0; c < 4; c++) acc[mi][nt][c] = 0.f;                  \
    const int NIT = K >> 5;                                                    \
    { for (int j_ = 0; j_ < 4; j_++) CP16(sbase + gdst[j_], gsrc[j_]); }       \
    asm volatile("cp.async.commit_group;");                                    \
    { for (int j_ = 0; j_ < 4; j_++)                                           \
          CP16(sbase + GSTG + gdst[j_], gsrc[j_] + 32); }                      \
    asm volatile("cp.async.commit_group;");                                    \
    int cur = 0;                                                               \
    _Pragma("unroll 1")                                                        \
    for (int it = 0; it < NIT; it++) {                                         \
        asm volatile("cp.async.wait_group 1;");                                \
        __syncthreads();                                                       \
        int nxt = cur + 2; if (nxt >= 3) nxt -= 3;                             \
        if (it + 2 < NIT) {                                                    \
            for (int j_ = 0; j_ < 4; j_++)                                     \
                CP16(sbase + (uint32_t)nxt * GSTG + gdst[j_],                  \
                     gsrc[j_] + (it + 2) * 32);                                \
        }                                                                      \
        asm volatile("cp.async.commit_group;");                                \
        const uint32_t stb = sbase + (uint32_t)cur * GSTG;                     \
        _Pragma("unroll")                                                      \
        for (int s = 0; s < 2; s++) {                                          \
            uint32_t af[2][4];                                                 \
            _Pragma("unroll")                                                  \
            for (int mi = 0; mi < 2; mi++) {                                   \
                uint32_t ra = stb + OFF_A + aoff[mi]                           \
                              + (uint32_t)((((s << 1) + ghA) ^ aswz[mi]) << 4);\
                LDM4(af[mi], ra);                                              \
            }                                                                  \
            _Pragma("unroll")                                                  \
            for (int ntp = 0; ntp < 4; ntp++) {                                \
                uint32_t rb = stb + OFF_B + boff[ntp]                          \
                              + (uint32_t)((((s << 1) + gbB) ^ bswz[ntp]) << 4);\
                uint32_t b4[4];                                                \
                LDM4(b4, rb);                                                  \
                _Pragma("unroll")                                              \
                for (int mi = 0; mi < 2; mi++) {                               \
                    mma_f16(acc[mi][2 * ntp],                                  \
                            af[mi][0], af[mi][1], af[mi][2], af[mi][3],        \
                            b4[0], b4[1]);                                     \
                    mma_f16(acc[mi][2 * ntp + 1],                              \
                            af[mi][0], af[mi][1], af[mi][2], af[mi][3],        \
                            b4[2], b4[3]);                                     \
                }                                                              \
            }                                                                  \
        }                                                                      \
        cur = cur + 1; if (cur == 3) cur = 0;                                  \
    }

// ---------------------------------------------------------------------------
// QKV GEMM with fused RoPE + head-split epilogue -> fp16 Q/K/V [B,H,N,d]
// ---------------------------------------------------------------------------
__global__ void __launch_bounds__(256, 2) gemm_qkv(
    const __half* __restrict__ A, const __half* __restrict__ B,
    const float2* __restrict__ rope,
    __half* __restrict__ Qo, __half* __restrict__ Ko, __half* __restrict__ Vo,
    int M, int N, int K)
{
    GEMM_MAINLOOP(A, B)

    const int t  = bn >> 10;
    const int h  = ((bn & 1023) + n0) >> 6;
    __half* outb = (t == 0) ? Qo : (t == 1) ? Ko : Vo;
    const float sc = (t == 0) ? 0.125f : 1.f;

    #pragma unroll
    for (int mi = 0; mi < 2; mi++) {
        int row0 = bm + m0 + mi * 16 + gID;
        #pragma unroll
        for (int rr = 0; rr < 2; rr++) {
            int r = row0 + rr * 8;
            int n = r & (NN - 1), bi = r >> 11;
            __half* dst = outb + ((size_t)(bi * Hh + h) * NN + n) * DD;
            if (t == 2) {
                #pragma unroll
                for (int nt = 0; nt < 8; nt++) {
                    int d0 = nt * 8 + 2 * tig;
                    *(__half2*)&dst[d0] =
                        __floats2half2_rn(acc[mi][nt][2 * rr], acc[mi][nt][2 * rr + 1]);
                }
            } else {
                #pragma unroll
                for (int nt = 0; nt < 4; nt++) {
                    int d0 = nt * 8 + 2 * tig;
                    float2 cs0 = rope[n * 32 + d0];
                    float2 cs1 = rope[n * 32 + d0 + 1];
                    float x10 = acc[mi][nt][2 * rr],     x11 = acc[mi][nt][2 * rr + 1];
                    float x20 = acc[mi][nt + 4][2 * rr], x21 = acc[mi][nt + 4][2 * rr + 1];
                    float lo0 = (x10 * cs0.x - x20 * cs0.y) * sc;
                    float lo1 = (x11 * cs1.x - x21 * cs1.y) * sc;
                    float hi0 = (x10 * cs0.y + x20 * cs0.x) * sc;
                    float hi1 = (x11 * cs1.y + x21 * cs1.x) * sc;
                    *(__half2*)&dst[d0]      = __floats2half2_rn(lo0, lo1);
                    *(__half2*)&dst[d0 + 32] = __floats2half2_rn(hi0, hi1);
                }
            }
        }
    }
}

// ---------------------------------------------------------------------------
// Projection GEMM: f32 out + bias
// ---------------------------------------------------------------------------
__global__ void __launch_bounds__(256, 2) gemm_f16(
    const __half* __restrict__ A, const __half* __restrict__ B,
    float* __restrict__ C, const float* __restrict__ bias,
    int M, int N, int K)
{
    GEMM_MAINLOOP(A, B)

    #pragma unroll
    for (int mi = 0; mi < 2; mi++) {
        int row = bm + m0 + mi * 16 + gID;
        #pragma unroll
        for (int nt = 0; nt < 8; nt++) {
            int col = bn + n0 + nt * 8 + 2 * tig;
            float b0 = bias[col];
            float b1 = bias[col + 1];
            float2 w0; w0.x = acc[mi][nt][0] + b0; w0.y = acc[mi][nt][1] + b1;
            float2 w1; w1.x = acc[mi][nt][2] + b0; w1.y = acc[mi][nt][3] + b1;
            *(float2*)&C[(size_t)row * N + col] = w0;
            *(float2*)&C[(size_t)(row + 8) * N + col] = w1;
        }
    }
}

// ---------------------------------------------------------------------------
// Flash attention, fp16 mma, warp M-tile 32 (2 m-frags): 4:1 mma:LDM ratio.
// 256 threads = 8 warps; CTA Q tile 256 rows; KV tiles 64, 2-stage cp.async.
// Q staged transiently in the KV smem region (32 KB total).
// ---------------------------------------------------------------------------
#define FA_SMEM 32768

__global__ void __launch_bounds__(256, 1) flash_mma(
    const __half* __restrict__ Q, const __half* __restrict__ K,
    const __half* __restrict__ V, __half* __restrict__ O)
{
    extern __shared__ __align__(16) char sma[];
    const uint32_t sb = (uint32_t)__cvta_generic_to_shared(sma);

    const int bh = blockIdx.x;
    const int b = bh >> 4, h = bh & 15;
    const int tid = threadIdx.x;
    const int warp = tid >> 5, lane = tid & 31;
    const int gID = lane >> 2, tig = lane & 3;
    const int qbase = blockIdx.y * 256;

    // ---- stage Q tile (256 rows x 128B = 32KB) into [0,32K), extract frags ----
    {
        const __half* qg = Q + ((size_t)bh * NN + qbase) * DD;
        #pragma unroll
        for (int j = 0; j < 8; j++) {
            int id = tid + j * 256;          // 0..2047
            int r = id >> 3, g = id & 7;
            CP16(sb + (uint32_t)(r * 128 + ((g ^ (r & 7)) << 4)), qg + r * DD + g * 8);
        }
        asm volatile("cp.async.commit_group;");
        asm volatile("cp.async.wait_group 0;");
        __syncthreads();
    }

    uint32_t aQ[2][4][4];
    #pragma unroll
    for (int mi = 0; mi < 2; mi++) {
        int qr = warp * 32 + mi * 16 + (lane & 15);
        #pragma unroll
        for (int s = 0; s < 4; s++) {
            int gran = 2 * s + (lane >> 4);
            LDM4(aQ[mi][s], sb + (uint32_t)(qr * 128 + ((gran ^ (qr & 7)) << 4)));
        }
    }
    __syncthreads();

    // ---- KV loader (K st0 [0,8K) st1 [8,16K); V st0 [16,24K) st1 [24,32K)) ----
    const __half* kbase = K + (size_t)bh * NN * DD;
    const __half* vbase = V + (size_t)bh * NN * DD;
#define KVLOAD(st, row0)                                                       \
    do { _Pragma("unroll")                                                     \
         for (int j_ = 0; j_ < 2; j_++) {                                      \
             int id_ = tid + j_ * 256;          /* 0..511 */                   \
             int r_ = id_ >> 3, g_ = id_ & 7;                                  \
             uint32_t sw_ = (uint32_t)(r_ * 128 + (((g_ ^ (r_ & 7))) << 4));   \
             CP16(sb + (uint32_t)(st) * 8192 + sw_,                            \
                  kbase + (size_t)(row0 + r_) * DD + g_ * 8);                  \
             CP16(sb + 16384u + (uint32_t)(st) * 8192 + sw_,                   \
                  vbase + (size_t)(row0 + r_) * DD + g_ * 8);                  \
         } } while (0)

    const int kr0  = lane & 7;
    const int gsel = (lane >> 3) & 1;
    const int sel  = lane >> 4;

    float of[2][8][4];
    #pragma unroll
    for (int mi = 0; mi < 2; mi++)
        #pragma unroll
        for (int i = 0; i < 8; i++)
            #pragma unroll
            for (int c = 0; c < 4; c++) of[mi][i][c] = 0.f;
    float mm[2][2], ll[2][2];
    #pragma unroll
    for (int mi = 0; mi < 2; mi++) {
        mm[mi][0] = -1e30f; mm[mi][1] = -1e30f;
        ll[mi][0] = 0.f;    ll[mi][1] = 0.f;
    }

    KVLOAD(0, 0);
    asm volatile("cp.async.commit_group;");

    #pragma unroll 1
    for (int t = 0; t < 32; t++) {
        asm volatile("cp.async.wait_group 0;");
        __syncthreads();
        if (t + 1 < 32) KVLOAD((t + 1) & 1, (t + 1) * 64);
        asm volatile("cp.async.commit_group;");

        const uint32_t Kst = sb + (uint32_t)((t & 1) * 8192);
        const uint32_t Vst = sb + 16384u + (uint32_t)((t & 1) * 8192);

        // ---- S = Q . K^T  (m32 x n64; 1 B-frag feeds 4 mma) ----
        float sf[2][8][4];
        #pragma unroll
        for (int mi = 0; mi < 2; mi++)
            #pragma unroll
            for (int nt = 0; nt < 8; nt++)
                #pragma unroll
                for (int c = 0; c < 4; c++) sf[mi][nt][c] = 0.f;

        #pragma unroll
        for (int s = 0; s < 4; s++) {
            int physg = (2 * s + gsel) ^ kr0;
            #pragma unroll
            for (int ip = 0; ip < 4; ip++) {
                int row = (2 * ip + sel) * 8 + kr0;
                uint32_t bb[4];
                LDM4(bb, Kst + (uint32_t)(row * 128 + (physg << 4)));
                #pragma unroll
                for (int mi = 0; mi < 2; mi++) {
                    mma_f16(sf[mi][2 * ip],
                            aQ[mi][s][0], aQ[mi][s][1], aQ[mi][s][2], aQ[mi][s][3],
                            bb[0], bb[1]);
                    mma_f16(sf[mi][2 * ip + 1],
                            aQ[mi][s][0], aQ[mi][s][1], aQ[mi][s][2], aQ[mi][s][3],
                            bb[2], bb[3]);
                }
            }
        }

        // ---- online softmax (2 m-frags x 2 rows each) ----
        #pragma unroll
        for (int mi = 0; mi < 2; mi++) {
            float tmax0 = -1e30f, tmax1 = -1e30f;
            #pragma unroll
            for (int nt = 0; nt < 8; nt++) {
                tmax0 = fmaxf(tmax0, fmaxf(sf[mi][nt][0], sf[mi][nt][1]));
                tmax1 = fmaxf(tmax1, fmaxf(sf[mi][nt][2], sf[mi][nt][3]));
            }
            tmax0 = fmaxf(tmax0, __shfl_xor_sync(0xffffffffu, tmax0, 1));
            tmax0 = fmaxf(tmax0, __shfl_xor_sync(0xffffffffu, tmax0, 2));
            tmax1 = fmaxf(tmax1, __shfl_xor_sync(0xffffffffu, tmax1, 1));
            tmax1 = fmaxf(tmax1, __shfl_xor_sync(0xffffffffu, tmax1, 2));

            float mn0 = fmaxf(mm[mi][0], tmax0);
            float mn1 = fmaxf(mm[mi][1], tmax1);
            float al0 = __expf(mm[mi][0] - mn0);
            float al1 = __expf(mm[mi][1] - mn1);
            mm[mi][0] = mn0; mm[mi][1] = mn1;
            ll[mi][0] *= al0; ll[mi][1] *= al1;
            #pragma unroll
            for (int i = 0; i < 8; i++) {
                of[mi][i][0] *= al0; of[mi][i][1] *= al0;
                of[mi][i][2] *= al1; of[mi][i][3] *= al1;
            }
            #pragma unroll
            for (int nt = 0; nt < 8; nt++) {
                sf[mi][nt][0] = __expf(sf[mi][nt][0] - mn0);
                sf[mi][nt][1] = __expf(sf[mi][nt][1] - mn0);
                sf[mi][nt][2] = __expf(sf[mi][nt][2] - mn1);
                sf[mi][nt][3] = __expf(sf[mi][nt][3] - mn1);
                ll[mi][0] += sf[mi][nt][0] + sf[mi][nt][1];
                ll[mi][1] += sf[mi][nt][2] + sf[mi][nt][3];
            }
        }

        // ---- O += P . V  (1 V-frag feeds 4 mma) ----
        #pragma unroll
        for (int kk = 0; kk < 4; kk++) {
            uint32_t Af[2][4];
            #pragma unroll
            for (int mi = 0; mi < 2; mi++) {
                Af[mi][0] = packh2(sf[mi][2 * kk][0],     sf[mi][2 * kk][1]);
                Af[mi][1] = packh2(sf[mi][2 * kk][2],     sf[mi][2 * kk][3]);
                Af[mi][2] = packh2(sf[mi][2 * kk + 1][0], sf[mi][2 * kk + 1][1]);
                Af[mi][3] = packh2(sf[mi][2 * kk + 1][2], sf[mi][2 * kk + 1][3]);
            }
            int row = 16 * kk + kr0 + 8 * gsel;
            #pragma unroll
            for (int jp = 0; jp < 4; jp++) {
                int physg = (2 * jp + sel) ^ kr0;
                uint32_t bb[4];
                LDM4T(bb, Vst + (uint32_t)(row * 128 + (physg << 4)));
                #pragma unroll
                for (int mi = 0; mi < 2; mi++) {
                    mma_f16(of[mi][2 * jp],
                            Af[mi][0], Af[mi][1], Af[mi][2], Af[mi][3], bb[0], bb[1]);
                    mma_f16(of[mi][2 * jp + 1],
                            Af[mi][0], Af[mi][1], Af[mi][2], Af[mi][3], bb[2], bb[3]);
                }
            }
        }
    }

    // ---- normalize + write ----
    #pragma unroll
    for (int mi = 0; mi < 2; mi++) {
        float l0 = ll[mi][0], l1 = ll[mi][1];
        l0 += __shfl_xor_sync(0xffffffffu, l0, 1);
        l0 += __shfl_xor_sync(0xffffffffu, l0, 2);
        l1 += __shfl_xor_sync(0xffffffffu, l1, 1);
        l1 += __shfl_xor_sync(0xffffffffu, l1, 2);
        float inv0 = 1.f / l0;
        float inv1 = 1.f / l1;

        int r0 = qbase + warp * 32 + mi * 16 + gID;
        int r1 = r0 + 8;
        size_t base0 = ((size_t)b * NN + r0) * CC + h * DD;
        size_t base1 = ((size_t)b * NN + r1) * CC + h * DD;
        #pragma unroll
        for (int i = 0; i < 8; i++) {
            int col = i * 8 + 2 * tig;
            *(__half2*)&O[base0 + col] =
                __floats2half2_rn(of[mi][i][0] * inv0, of[mi][i][1] * inv0);
            *(__half2*)&O[base1 + col] =
                __floats2half2_rn(of[mi][i][2] * inv1, of[mi][i][3] * inv1);
        }
    }
#undef KVLOAD
}

// ---------------------------------------------------------------------------
extern "C" void kernel_launch(void* const* d_in, const int* in_sizes, int n_in,
                              void* d_out, int out_size)
{
    const float* x      = (const float*)d_in[0];
    const float* w_qkv  = (const float*)d_in[1];
    const float* w_proj = (const float*)d_in[2];
    const float* b_proj = (const float*)d_in[3];
    float* out = (float*)d_out;

    __half *qh, *kh, *vh, *xa, *wq, *wp, *att;
    float2* rope;
    cudaGetSymbolAddress((void**)&qh,   g_qh);
    cudaGetSymbolAddress((void**)&kh,   g_kh);
    cudaGetSymbolAddress((void**)&vh,   g_vh);
    cudaGetSymbolAddress((void**)&xa,   g_xa);
    cudaGetSymbolAddress((void**)&wq,   g_wq);
    cudaGetSymbolAddress((void**)&wp,   g_wp);
    cudaGetSymbolAddress((void**)&att,  g_att);
    cudaGetSymbolAddress((void**)&rope, g_rope);

    static int attr_done = 0;
    if (!attr_done) {
        cudaFuncSetAttribute(gemm_qkv, cudaFuncAttributeMaxDynamicSharedMemorySize,
                             3 * GSTG);
        cudaFuncSetAttribute(gemm_f16, cudaFuncAttributeMaxDynamicSharedMemorySize,
                             3 * GSTG);
        cudaFuncSetAttribute(flash_mma, cudaFuncAttributeMaxDynamicSharedMemorySize,
                             FA_SMEM);
        attr_done = 1;
    }

    // 0) one-time prep
    rope_tab<<<(NN * 32) / 256, 256>>>(rope);
    conv_h<<<(MM_ * CC / 4) / 256, 256>>>(x, xa);
    conv_T_h<<<dim3(3 * CC / 32, CC / 32), 256>>>(w_qkv, wq, CC, 3 * CC);
    conv_T_h<<<dim3(CC / 32, CC / 32), 256>>>(w_proj, wp, CC, CC);

    // 1) QKV GEMM with fused RoPE + head split -> fp16 Q/K/V
    gemm_qkv<<<dim3(3 * CC / 128, MM_ / 128), 256, 3 * GSTG>>>(
        xa, wq, rope, qh, kh, vh, MM_, 3 * CC, CC);

    // 2) Attention (fp16 mma, m32 warp tiles, 256-row Q tiles)
    flash_mma<<<dim3(Bb * Hh, NN / 256), 256, FA_SMEM>>>(qh, kh, vh, att);

    // 3) Projection GEMM + bias (fp16 -> f32)
    gemm_f16<<<dim3(CC / 128, MM_ / 128), 256, 3 * GSTG>>>(
        att, wp, out, b_proj, MM_, CC, CC);
}